// round 1
// baseline (speedup 1.0000x reference)
#include <cuda_runtime.h>
#include <math.h>
#include <stdint.h>

#define HWSZ 16384
#define ATT_SMEM ((3*16384 + 128*68) * 4)

// ---------------- scratch (static device arrays; no runtime alloc) ----------------
__device__ float g_q [4ull*512*16384];
__device__ float g_k [4ull*512*16384];
__device__ float g_v [4ull*256*16384];
__device__ float g_qT[4ull*512*16384];
__device__ float g_kT[4ull*512*16384];
__device__ float g_vT[4ull*256*16384];
__device__ float g_outW [4ull*256*16384];
__device__ float g_outHT[4ull*256*16384];
__device__ float g_outH [4ull*256*16384];
__device__ float g_scH[256];   // [0..127]=scale, [128..255]=shift
__device__ float g_scW[256];

// ---------------- grouped 1x1 conv as tiled GEMM ----------------
// Y[b][o][p] = sum_k W[o][k] * X[b][gbase+k][p] + bias[o]
// 128x128 tile, BK=16, 256 threads, 8x8 per thread, warp 8x4 lane map.
__global__ __launch_bounds__(256, 2)
void proj_kernel(const float* __restrict__ X, const float* __restrict__ Wt,
                 const float* __restrict__ bias, float* __restrict__ Y,
                 int O, int group_out) {
    __shared__ float As[16*132];
    __shared__ float Bs[16*128];
    int b = blockIdx.z;
    int m_base = blockIdx.y * 128;
    int p_base = blockIdx.x * 128;
    int gbase = (m_base / group_out) * 256;
    const float* Xb = X + (size_t)b * 512 * HWSZ + (size_t)gbase * HWSZ + p_base;

    int tid = threadIdx.x;
    int warp = tid >> 5, lane = tid & 31;
    int wm = warp >> 2, wn = warp & 3;
    int lm = lane >> 2, ln = lane & 3;
    int m0 = wm*64 + lm*8;
    int n0 = wn*32 + ln*8;

    float acc[8][8];
    #pragma unroll
    for (int i = 0; i < 8; i++)
        #pragma unroll
        for (int j = 0; j < 8; j++) acc[i][j] = 0.f;

    for (int k0 = 0; k0 < 256; k0 += 16) {
        // As: W tile transposed -> [k][m]
        {
            int o  = tid >> 1;
            int kc = (tid & 1) * 8;
            const float* wp = Wt + (size_t)(m_base + o) * 256 + k0 + kc;
            float4 w0 = *(const float4*)wp;
            float4 w1 = *(const float4*)(wp + 4);
            As[(kc+0)*132 + o] = w0.x; As[(kc+1)*132 + o] = w0.y;
            As[(kc+2)*132 + o] = w0.z; As[(kc+3)*132 + o] = w0.w;
            As[(kc+4)*132 + o] = w1.x; As[(kc+5)*132 + o] = w1.y;
            As[(kc+6)*132 + o] = w1.z; As[(kc+7)*132 + o] = w1.w;
        }
        // Bs: X tile [k][p] (already k-major)
        #pragma unroll
        for (int u = 0; u < 2; u++) {
            int idx = tid + u*256;
            int kk = idx >> 5, j4 = (idx & 31) << 2;
            *(float4*)(Bs + kk*128 + j4) =
                *(const float4*)(Xb + (size_t)(k0+kk)*HWSZ + j4);
        }
        __syncthreads();
        #pragma unroll
        for (int kk = 0; kk < 16; kk++) {
            float a[8], bb[8];
            *(float4*)(a)    = *(const float4*)(As + kk*132 + m0);
            *(float4*)(a+4)  = *(const float4*)(As + kk*132 + m0 + 4);
            *(float4*)(bb)   = *(const float4*)(Bs + kk*128 + n0);
            *(float4*)(bb+4) = *(const float4*)(Bs + kk*128 + n0 + 4);
            #pragma unroll
            for (int i = 0; i < 8; i++)
                #pragma unroll
                for (int j = 0; j < 8; j++)
                    acc[i][j] += a[i]*bb[j];
        }
        __syncthreads();
    }
    #pragma unroll
    for (int i = 0; i < 8; i++) {
        float bv = bias[m_base + m0 + i];
        float* yp = Y + ((size_t)b*O + m_base + m0 + i) * HWSZ + p_base + n0;
        float4 r0, r1;
        r0.x = acc[i][0]+bv; r0.y = acc[i][1]+bv; r0.z = acc[i][2]+bv; r0.w = acc[i][3]+bv;
        r1.x = acc[i][4]+bv; r1.y = acc[i][5]+bv; r1.z = acc[i][6]+bv; r1.w = acc[i][7]+bv;
        *(float4*)yp = r0; *(float4*)(yp+4) = r1;
    }
}

// ---------------- 128x128 transpose per slice ----------------
__global__ void transpose_kernel(const float* __restrict__ in, float* __restrict__ out) {
    __shared__ float t[32][33];
    int tile = blockIdx.x;              // 0..15
    int bx = (tile & 3) * 32, by = (tile >> 2) * 32;
    const float* ip = in  + (size_t)blockIdx.y * HWSZ;
    float*       op = out + (size_t)blockIdx.y * HWSZ;
    int x = threadIdx.x, y = threadIdx.y;
    #pragma unroll
    for (int r = 0; r < 32; r += 8)
        t[y+r][x] = ip[(size_t)(by + y + r)*128 + bx + x];
    __syncthreads();
    #pragma unroll
    for (int r = 0; r < 32; r += 8)
        op[(size_t)(bx + y + r)*128 + by + x] = t[x][y+r];
}

// ---------------- per-slice axial attention ----------------
// slice (b, head n, row r): Q,K [128c x 128], V [64c x 128], all row-contiguous.
// S = scale * Q^T K ; A = softmax_rows(S) ; O[c][i] = sum_j A[i][j] V[c][j]
__global__ __launch_bounds__(256, 1)
void attn_kernel(const float* __restrict__ q, const float* __restrict__ k,
                 const float* __restrict__ v, float* __restrict__ out) {
    extern __shared__ float sm[];
    float* Ks = sm;                 // 128*128
    float* Qs = sm + 16384;         // 128*128 (reused for reductions)
    float* At = sm + 32768;         // 128*128  A transposed [j][i]
    float* Vt = sm + 49152;         // 128*68   V transposed [j][c]
    const float SCALE = 0.08838834764831845f;   // 128^-0.5

    int r = blockIdx.x, n = blockIdx.y, b = blockIdx.z;
    size_t qoff = ((size_t)(b*4 + n) * 128) * HWSZ + (size_t)r * 128;
    size_t voff = ((size_t)(b*4 + n) *  64) * HWSZ + (size_t)r * 128;
    int tid = threadIdx.x;

    // stage Q, K, Vt
    #pragma unroll
    for (int u = 0; u < 16; u++) {
        int idx = tid + u*256;          // 0..4095
        int c = idx >> 5, j4 = (idx & 31) << 2;
        *(float4*)(Qs + c*128 + j4) = *(const float4*)(q + qoff + (size_t)c*HWSZ + j4);
        *(float4*)(Ks + c*128 + j4) = *(const float4*)(k + qoff + (size_t)c*HWSZ + j4);
    }
    #pragma unroll
    for (int u = 0; u < 8; u++) {
        int idx = tid + u*256;          // 0..2047
        int c = idx >> 5, j4 = (idx & 31) << 2;
        float4 vv = *(const float4*)(v + voff + (size_t)c*HWSZ + j4);
        Vt[(j4+0)*68 + c] = vv.x;
        Vt[(j4+1)*68 + c] = vv.y;
        Vt[(j4+2)*68 + c] = vv.z;
        Vt[(j4+3)*68 + c] = vv.w;
    }
    __syncthreads();

    int warp = tid >> 5, lane = tid & 31;
    int wm = warp >> 2, wn = warp & 3;
    int lm = lane >> 2, ln = lane & 3;
    int m0 = wm*64 + lm*8, n0 = wn*32 + ln*8;

    float acc[8][8];
    #pragma unroll
    for (int i = 0; i < 8; i++)
        #pragma unroll
        for (int j = 0; j < 8; j++) acc[i][j] = 0.f;

    #pragma unroll 2
    for (int c = 0; c < 128; c++) {
        float a[8], bb[8];
        *(float4*)(a)    = *(const float4*)(Qs + c*128 + m0);
        *(float4*)(a+4)  = *(const float4*)(Qs + c*128 + m0 + 4);
        *(float4*)(bb)   = *(const float4*)(Ks + c*128 + n0);
        *(float4*)(bb+4) = *(const float4*)(Ks + c*128 + n0 + 4);
        #pragma unroll
        for (int i = 0; i < 8; i++)
            #pragma unroll
            for (int j = 0; j < 8; j++)
                acc[i][j] += a[i]*bb[j];
    }
    #pragma unroll
    for (int i = 0; i < 8; i++)
        #pragma unroll
        for (int j = 0; j < 8; j++) acc[i][j] *= SCALE;

    __syncthreads();                 // everyone done reading Qs
    float* P = Qs;                   // partials [128][16]
    float* rstat = Qs + 4096;        // per-row stats [128]
    int g = wn*4 + ln;

    // row max
    #pragma unroll
    for (int i = 0; i < 8; i++) {
        float pm = acc[i][0];
        #pragma unroll
        for (int j = 1; j < 8; j++) pm = fmaxf(pm, acc[i][j]);
        P[(m0+i)*16 + g] = pm;
    }
    __syncthreads();
    if (tid < 128) {
        float mx = P[tid*16];
        #pragma unroll
        for (int gg = 1; gg < 16; gg++) mx = fmaxf(mx, P[tid*16+gg]);
        rstat[tid] = mx;
    }
    __syncthreads();
    // exp + row sum
    #pragma unroll
    for (int i = 0; i < 8; i++) {
        float mx = rstat[m0+i], ps = 0.f;
        #pragma unroll
        for (int j = 0; j < 8; j++) {
            float e = __expf(acc[i][j] - mx);
            acc[i][j] = e; ps += e;
        }
        P[(m0+i)*16 + g] = ps;
    }
    __syncthreads();
    if (tid < 128) {
        float s = 0.f;
        #pragma unroll
        for (int gg = 0; gg < 16; gg++) s += P[tid*16+gg];
        rstat[tid] = 1.0f / s;
    }
    __syncthreads();
    // write normalized A transposed: At[j][i]
    #pragma unroll
    for (int i = 0; i < 8; i++) {
        float inv = rstat[m0+i];
        #pragma unroll
        for (int j = 0; j < 8; j++)
            At[(n0+j)*128 + (m0+i)] = acc[i][j] * inv;
    }
    __syncthreads();

    // phase 2: O[c][i] = sum_j Vt[j][c] * At[j][i]   (64 x 128)
    int c0 = wm*32 + lm*4;
    int i0 = n0;
    float oacc[4][8];
    #pragma unroll
    for (int cc = 0; cc < 4; cc++)
        #pragma unroll
        for (int j = 0; j < 8; j++) oacc[cc][j] = 0.f;

    #pragma unroll 2
    for (int j = 0; j < 128; j++) {
        float vv[4], aa[8];
        *(float4*)(vv)   = *(const float4*)(Vt + j*68 + c0);
        *(float4*)(aa)   = *(const float4*)(At + j*128 + i0);
        *(float4*)(aa+4) = *(const float4*)(At + j*128 + i0 + 4);
        #pragma unroll
        for (int cc = 0; cc < 4; cc++)
            #pragma unroll
            for (int jj = 0; jj < 8; jj++)
                oacc[cc][jj] += vv[cc]*aa[jj];
    }
    #pragma unroll
    for (int cc = 0; cc < 4; cc++) {
        float* op = out + voff + (size_t)(c0+cc)*HWSZ + i0;
        float4 r0, r1;
        r0.x = oacc[cc][0]; r0.y = oacc[cc][1]; r0.z = oacc[cc][2]; r0.w = oacc[cc][3];
        r1.x = oacc[cc][4]; r1.y = oacc[cc][5]; r1.z = oacc[cc][6]; r1.w = oacc[cc][7];
        *(float4*)op = r0; *(float4*)(op+4) = r1;
    }
}

// ---------------- BN (train-mode) stats, fold into scale/shift ----------------
// only first 128 channels are needed by p0/p1
__global__ void bn_stats_kernel(const float* __restrict__ x, const float* __restrict__ w,
                                const float* __restrict__ bb, float* __restrict__ sc) {
    int c = blockIdx.x;     // 0..127
    int tid = threadIdx.x;
    float s = 0.f, sq = 0.f;
    for (int b = 0; b < 4; b++) {
        const float* p = x + ((size_t)b*256 + c) * HWSZ;
        for (int i = tid; i < HWSZ; i += 256) { float vv = p[i]; s += vv; sq += vv*vv; }
    }
    __shared__ float ss[256], ssq[256];
    ss[tid] = s; ssq[tid] = sq; __syncthreads();
    for (int st = 128; st > 0; st >>= 1) {
        if (tid < st) { ss[tid] += ss[tid+st]; ssq[tid] += ssq[tid+st]; }
        __syncthreads();
    }
    if (tid == 0) {
        const float N = 65536.0f;
        float mean = ss[0] / N;
        float var  = ssq[0] / N - mean*mean;
        float scale = w[c] * rsqrtf(var + 1e-5f);
        sc[c]       = scale;
        sc[128 + c] = bb[c] - mean*scale;
    }
}

__global__ void bn_apply_kernel(const float* __restrict__ x, const float* __restrict__ sc,
                                float* __restrict__ outp) {
    int idx = blockIdx.x * 256 + threadIdx.x;     // float4 idx, 2,097,152 total
    int b  = idx >> 19;
    int c  = (idx >> 12) & 127;
    int i4 = (idx & 4095) << 2;
    float4 vv = *(const float4*)(x + ((size_t)b*256 + c)*HWSZ + i4);
    float s = sc[c], sh = sc[128+c];
    vv.x = vv.x*s + sh; vv.y = vv.y*s + sh; vv.z = vv.z*s + sh; vv.w = vv.w*s + sh;
    *(float4*)(outp + ((size_t)b*128 + c)*HWSZ + i4) = vv;
}

// ---------------- residual epilogue ----------------
__global__ void final_kernel(const float* __restrict__ x, const float* __restrict__ oh,
                             const float* __restrict__ ow, const float* __restrict__ gamma,
                             float* __restrict__ out) {
    size_t idx = (size_t)blockIdx.x * 256 + threadIdx.x;   // float4 idx, 8,388,608 total
    int b  = (int)(idx >> 21);
    int ch = (int)((idx >> 12) & 511);
    int i4 = (int)((idx & 4095) << 2);
    float gm = gamma[0];
    const float* tp = (ch < 256)
        ? oh + ((size_t)b*256 + ch)      *HWSZ + i4
        : ow + ((size_t)b*256 + (ch-256))*HWSZ + i4;
    float4 t  = *(const float4*)tp;
    float4 xv = *(const float4*)(x + ((size_t)b*512 + ch)*HWSZ + i4);
    float4 o;
    o.x = gm*fmaxf(t.x, 0.f) + xv.x;
    o.y = gm*fmaxf(t.y, 0.f) + xv.y;
    o.z = gm*fmaxf(t.z, 0.f) + xv.z;
    o.w = gm*fmaxf(t.w, 0.f) + xv.w;
    *(float4*)(out + idx*4) = o;
}

// ---------------- launch ----------------
extern "C" void kernel_launch(void* const* d_in, const int* in_sizes, int n_in,
                              void* d_out, int out_size) {
    const float* x     = (const float*)d_in[0];
    const float* wq    = (const float*)d_in[1];
    const float* bq    = (const float*)d_in[2];
    const float* wk    = (const float*)d_in[3];
    const float* bk    = (const float*)d_in[4];
    const float* wv    = (const float*)d_in[5];
    const float* bv    = (const float*)d_in[6];
    const float* bnh_w = (const float*)d_in[7];
    const float* bnh_b = (const float*)d_in[8];
    const float* bnw_w = (const float*)d_in[9];
    const float* bnw_b = (const float*)d_in[10];
    const float* gamma = (const float*)d_in[11];
    float* out = (float*)d_out;

    float *q, *k, *v, *qT, *kT, *vT, *oW, *oHT, *oH, *scH, *scW;
    cudaGetSymbolAddress((void**)&q,   g_q);
    cudaGetSymbolAddress((void**)&k,   g_k);
    cudaGetSymbolAddress((void**)&v,   g_v);
    cudaGetSymbolAddress((void**)&qT,  g_qT);
    cudaGetSymbolAddress((void**)&kT,  g_kT);
    cudaGetSymbolAddress((void**)&vT,  g_vT);
    cudaGetSymbolAddress((void**)&oW,  g_outW);
    cudaGetSymbolAddress((void**)&oHT, g_outHT);
    cudaGetSymbolAddress((void**)&oH,  g_outH);
    cudaGetSymbolAddress((void**)&scH, g_scH);
    cudaGetSymbolAddress((void**)&scW, g_scW);

    cudaFuncSetAttribute(attn_kernel, cudaFuncAttributeMaxDynamicSharedMemorySize, ATT_SMEM);

    // QKV projections (grouped GEMM)
    proj_kernel<<<dim3(128,4,4), 256>>>(x, wq, bq, q, 512, 256);
    proj_kernel<<<dim3(128,4,4), 256>>>(x, wk, bk, k, 512, 256);
    proj_kernel<<<dim3(128,2,4), 256>>>(x, wv, bv, v, 256, 128);

    // transposed copies for H-direction attention
    transpose_kernel<<<dim3(16, 2048), dim3(32,8)>>>(q, qT);
    transpose_kernel<<<dim3(16, 2048), dim3(32,8)>>>(k, kT);
    transpose_kernel<<<dim3(16, 1024), dim3(32,8)>>>(v, vT);

    // axial attention: W direction on natural layout, H direction on transposed
    attn_kernel<<<dim3(128,4,4), 256, ATT_SMEM>>>(q,  k,  v,  oW);
    attn_kernel<<<dim3(128,4,4), 256, ATT_SMEM>>>(qT, kT, vT, oHT);
    transpose_kernel<<<dim3(16, 1024), dim3(32,8)>>>(oHT, oH);

    // BN (train-mode) stats for the 128 channels each side output needs
    bn_stats_kernel<<<128, 256>>>(oH, bnh_w, bnh_b, scH);
    bn_stats_kernel<<<128, 256>>>(oW, bnw_w, bnw_b, scW);
    bn_apply_kernel<<<8192, 256>>>(oH, scH, out + 33554432ull);
    bn_apply_kernel<<<8192, 256>>>(oW, scW, out + 41943040ull);

    // residual epilogue
    final_kernel<<<32768, 256>>>(x, oH, oW, gamma, out);
}

// round 3
// speedup vs baseline: 1.3023x; 1.3023x over previous
#include <cuda_runtime.h>
#include <cuda_bf16.h>
#include <math.h>
#include <stdint.h>

#define HWSZ 16384
#define ATT_SMEM ((3*16384 + 128*68) * 4)
#define GEMM_SMEM (1024 + 3*65536)

#if defined(__CUDA_ARCH__) && defined(__CUDA_ARCH_FEAT_SM103_ALL)
#define USE_TCGEN05 1
#else
#define USE_TCGEN05 0
#endif

// ---------------- scratch (static device arrays; no runtime alloc) ----------------
__device__ float g_q [4ull*512*16384];
__device__ float g_k [4ull*512*16384];
__device__ float g_v [4ull*256*16384];
__device__ float g_qT[4ull*512*16384];
__device__ float g_kT[4ull*512*16384];
__device__ float g_vT[4ull*256*16384];
__device__ float g_outW [4ull*256*16384];
__device__ float g_outHT[4ull*256*16384];
__device__ float g_outH [4ull*256*16384];
__device__ float g_scH[256];
__device__ float g_scW[256];
__device__ __nv_bfloat16 g_xThi[8ull*16384*256];   // [b*2+g][pix][k]
__device__ __nv_bfloat16 g_xTlo[8ull*16384*256];
__device__ __nv_bfloat16 g_wph[2*640*256];          // [g][m][k]
__device__ __nv_bfloat16 g_wpl[2*640*256];
__device__ float g_bp[2*640];

// ---------------- helpers ----------------
__device__ __forceinline__ uint32_t smem_u32(const void* p) {
    uint32_t a;
    asm("{ .reg .u64 t; cvta.to.shared.u64 t, %1; cvt.u32.u64 %0, t; }" : "=r"(a) : "l"(p));
    return a;
}

#if USE_TCGEN05
__device__ __forceinline__ uint32_t elect_one_pred() {
    uint32_t pred;
    asm volatile(
        "{\n\t.reg .pred p;\n\t"
        "elect.sync _|p, 0xFFFFFFFF;\n\t"
        "selp.b32 %0, 1, 0, p;\n\t}"
        : "=r"(pred));
    return pred;
}
#define TCGEN05_ALLOC(smem_addr, nCols) \
    asm volatile("tcgen05.alloc.cta_group::1.sync.aligned.shared::cta.b32 [%0], %1;" \
        :: "r"((uint32_t)(smem_addr)), "r"((uint32_t)(nCols)) : "memory")
#define TCGEN05_DEALLOC(tmem_addr, nCols) \
    asm volatile("tcgen05.dealloc.cta_group::1.sync.aligned.b32 %0, %1;" \
        :: "r"(tmem_addr), "r"((uint32_t)(nCols)))
#define TCGEN05_COMMIT(mbar) \
    asm volatile("tcgen05.commit.cta_group::1.mbarrier::arrive::one.shared::cluster.b64 [%0];" \
        :: "r"((uint32_t)(mbar)) : "memory")
#define TCGEN05_WAIT_LD() asm volatile("tcgen05.wait::ld.sync.aligned;" ::: "memory")
#define TCGEN05_FENCE_AFTER() asm volatile("tcgen05.fence::after_thread_sync;" ::: "memory")
#define TCGEN05_FENCE_BEFORE() asm volatile("tcgen05.fence::before_thread_sync;" ::: "memory")
#define MBARRIER_INIT(mbar, count) \
    asm volatile("mbarrier.init.shared.b64 [%0], %1;" \
        :: "r"((uint32_t)(mbar)), "r"((uint32_t)(count)) : "memory")
#define MBARRIER_WAIT_PARITY(mbar_smem_addr, phase_parity) do { \
    uint32_t _mbar = (uint32_t)(mbar_smem_addr); \
    uint32_t _parity = (uint32_t)(phase_parity); \
    uint32_t _done; \
    asm volatile( \
        "{\n\t.reg .pred p;\n\t" \
        "mbarrier.try_wait.parity.acquire.cta.shared::cta.b64 p, [%1], %2;\n\t" \
        "selp.b32 %0, 1, 0, p;\n\t}" \
        : "=r"(_done) : "r"(_mbar), "r"(_parity) : "memory"); \
    if (!_done) { \
        asm volatile( \
            "{\n\t.reg .pred P1;\n\t" \
            "WAIT_LOOP_%=:\n\t" \
            "mbarrier.try_wait.parity.acquire.cta.shared::cta.b64 P1, [%0], %1, 0x989680;\n\t" \
            "@P1 bra.uni WAIT_DONE_%=;\n\t" \
            "bra.uni WAIT_LOOP_%=;\n\t" \
            "WAIT_DONE_%=:\n\t}" \
            :: "r"(_mbar), "r"(_parity) : "memory"); \
    } \
} while(0)
#define TCGEN05_LD_32X32B_X32(r, tmem_addr) \
    asm volatile( \
        "tcgen05.ld.sync.aligned.32x32b.x32.b32 " \
        "{%0, %1, %2, %3, %4, %5, %6, %7, " \
        " %8, %9, %10, %11, %12, %13, %14, %15, " \
        " %16, %17, %18, %19, %20, %21, %22, %23, " \
        " %24, %25, %26, %27, %28, %29, %30, %31}, [%32];" \
        : "=r"((r)[0]),  "=r"((r)[1]),  "=r"((r)[2]),  "=r"((r)[3]), \
          "=r"((r)[4]),  "=r"((r)[5]),  "=r"((r)[6]),  "=r"((r)[7]), \
          "=r"((r)[8]),  "=r"((r)[9]),  "=r"((r)[10]), "=r"((r)[11]), \
          "=r"((r)[12]), "=r"((r)[13]), "=r"((r)[14]), "=r"((r)[15]), \
          "=r"((r)[16]), "=r"((r)[17]), "=r"((r)[18]), "=r"((r)[19]), \
          "=r"((r)[20]), "=r"((r)[21]), "=r"((r)[22]), "=r"((r)[23]), \
          "=r"((r)[24]), "=r"((r)[25]), "=r"((r)[26]), "=r"((r)[27]), \
          "=r"((r)[28]), "=r"((r)[29]), "=r"((r)[30]), "=r"((r)[31]) \
        : "r"(tmem_addr))

__device__ __forceinline__ void mma_f16_ss_cg1(uint32_t d_tmem, uint64_t a_desc,
                                               uint64_t b_desc, uint32_t idesc,
                                               uint32_t enable) {
    asm volatile(
        "{\n\t.reg .pred p;\n\t"
        "setp.ne.u32 p, %5, 0;\n\t"
        "tcgen05.mma.cta_group::1.kind::f16 [%0], %1, %2, %3, {%4, %4, %4, %4}, p;\n\t}"
        :: "r"(d_tmem), "l"(a_desc), "l"(b_desc), "r"(idesc), "r"(0u), "r"(enable)
        : "memory");
}
__device__ __forceinline__ uint64_t make_desc(uint32_t addr) {
    return (2ull << 61) | (1ull << 46) | (64ull << 32) | (1ull << 16)
         | ((uint64_t)(addr >> 4) & 0x3FFF);
}
#endif  // USE_TCGEN05

// legacy mma.sync / ldmatrix (plain PTX, works on any sm_80+ target incl sm_103)
#define LDSM_X4(r0, r1, r2, r3, addr) \
    asm volatile("ldmatrix.sync.aligned.m8n8.x4.shared.b16 {%0,%1,%2,%3}, [%4];" \
        : "=r"(r0), "=r"(r1), "=r"(r2), "=r"(r3) : "r"(addr))

__device__ __forceinline__ void mma16816(float* d, const uint32_t* a,
                                         uint32_t b0, uint32_t b1) {
    asm volatile(
        "mma.sync.aligned.m16n8k16.row.col.f32.bf16.bf16.f32 "
        "{%0,%1,%2,%3}, {%4,%5,%6,%7}, {%8,%9}, {%0,%1,%2,%3};"
        : "+f"(d[0]), "+f"(d[1]), "+f"(d[2]), "+f"(d[3])
        : "r"(a[0]), "r"(a[1]), "r"(a[2]), "r"(a[3]), "r"(b0), "r"(b1));
}

// address of 16B row segment (row, bf16-col kc) in blocked SW128 atom tile layout
__device__ __forceinline__ uint32_t tile_addr(uint32_t tbase, int row, int kc) {
    uint32_t byte = (uint32_t)(((row >> 3) + ((kc >> 6) << 4)) * 1024
                  + ((row & 7) << 7)
                  + ((((kc & 63) << 1)) ^ ((row & 7) << 4)));
    return tbase + byte;
}

// ---------------- weight pack + bf16 split ----------------
__global__ void prepw_kernel(const float* __restrict__ wq, const float* __restrict__ bq,
                             const float* __restrict__ wk, const float* __restrict__ bk,
                             const float* __restrict__ wv, const float* __restrict__ bv,
                             __nv_bfloat16* __restrict__ wph, __nv_bfloat16* __restrict__ wpl,
                             float* __restrict__ bp) {
    int idx = blockIdx.x * 256 + threadIdx.x;    // 0..327679
    int g = idx / 163840;
    int r = idx - g * 163840;
    int m = r >> 8, k = r & 255;
    const float* src; float bias;
    if (m < 256)       { src = wq + (size_t)(g*256 + m)       * 256; bias = bq[g*256 + m]; }
    else if (m < 512)  { src = wk + (size_t)(g*256 + (m-256)) * 256; bias = bk[g*256 + m-256]; }
    else               { src = wv + (size_t)(g*128 + (m-512)) * 256; bias = bv[g*128 + m-512]; }
    float w = src[k];
    __nv_bfloat16 h = __float2bfloat16(w);
    wph[idx] = h;
    wpl[idx] = __float2bfloat16(w - __bfloat162float(h));
    if (k == 0) bp[g*640 + m] = bias;
}

// ---------------- x: transpose [k][pix] -> [pix][k] + bf16 hi/lo split ----------------
__global__ void convx_kernel(const float* __restrict__ x,
                             __nv_bfloat16* __restrict__ hi, __nv_bfloat16* __restrict__ lo) {
    __shared__ float t[32][33];
    int px = blockIdx.x * 32;
    int kx = blockIdx.y * 32;
    int z = blockIdx.z;
    int b = z >> 1, gg = z & 1;
    const float* ip = x + ((size_t)b*512 + gg*256 + kx) * HWSZ + px;
    int xx = threadIdx.x, yy = threadIdx.y;
    #pragma unroll
    for (int r = 0; r < 32; r += 8)
        t[yy+r][xx] = ip[(size_t)(yy+r)*HWSZ + xx];
    __syncthreads();
    size_t obase = ((size_t)z * 16384 + px) * 256 + kx;
    #pragma unroll
    for (int r = 0; r < 32; r += 8) {
        float v = t[xx][yy+r];
        __nv_bfloat16 h = __float2bfloat16(v);
        __nv_bfloat16 l = __float2bfloat16(v - __bfloat162float(h));
        hi[obase + (size_t)(yy+r)*256 + xx] = h;
        lo[obase + (size_t)(yy+r)*256 + xx] = l;
    }
}

// ---------------- stage [128 x 256] bf16 tile into blocked SW128 layout (256 thr) ----
__device__ __forceinline__ void stage_tile(char* smp, const __nv_bfloat16* __restrict__ src,
                                           int tid) {
    #pragma unroll 4
    for (int it = 0; it < 16; it++) {
        int idx = it * 256 + tid;           // 0..4095 vec8
        int row = idx >> 5;
        int k8 = (idx & 31) << 3;
        uint4 vdata = *(const uint4*)(src + (size_t)row * 256 + k8);
        uint32_t byte = (uint32_t)(((row >> 3) + ((k8 >> 6) << 4)) * 1024
                      + ((row & 7) << 7)
                      + (((k8 & 63) << 1) ^ ((row & 7) << 4)));
        *(uint4*)(smp + byte) = vdata;
    }
}

// ---------------- fused qkv projection GEMM (dual path) ----------------
// per CTA: D[128 ch x 128 pix] = Wg[m_base..+128, :256] * XgT[pix_base..+128, :256]^T
__global__ __launch_bounds__(256, 1)
void gemm_kernel(const __nv_bfloat16* __restrict__ xThi, const __nv_bfloat16* __restrict__ xTlo,
                 const __nv_bfloat16* __restrict__ wph, const __nv_bfloat16* __restrict__ wpl,
                 const float* __restrict__ bp,
                 float* __restrict__ qb, float* __restrict__ kb, float* __restrict__ vb) {
    extern __shared__ char sm[];
    uint32_t sbase = smem_u32(sm);
    const uint32_t A0 = 1024, B0 = 1024 + 65536, B1 = 1024 + 131072;
    int tid = threadIdx.x;
    int lane = tid & 31, wid = tid >> 5;
    int my = blockIdx.x;                 // 0..4: M tile (0,1=q  2,3=k  4=v)
    int pbase = blockIdx.y * 128;
    int z = blockIdx.z;                  // b*2+g
    int b = z >> 1, g = z & 1;
    int m_base = my * 128;

    const __nv_bfloat16* asrcH = wph + ((size_t)g*640 + m_base) * 256;
    const __nv_bfloat16* asrcL = wpl + ((size_t)g*640 + m_base) * 256;
    const __nv_bfloat16* bsrcH = xThi + ((size_t)z*16384 + pbase) * 256;
    const __nv_bfloat16* bsrcL = xTlo + ((size_t)z*16384 + pbase) * 256;

    // destination base (shared by both paths)
    float* dst; size_t ch0;
    if (my < 2)      { dst = qb; ch0 = (size_t)b*512 + g*256 + m_base; }
    else if (my < 4) { dst = kb; ch0 = (size_t)b*512 + g*256 + (m_base - 256); }
    else             { dst = vb; ch0 = (size_t)b*256 + g*128 + (m_base - 512); }

#if USE_TCGEN05
    const uint32_t IDESC = 0x8200490u;   // bf16 in, f32 acc, M=128, N=128
    if (wid == 0) TCGEN05_ALLOC(sbase, 128);
    if (tid == 0) MBARRIER_INIT(sbase + 16, 1);
    __syncthreads();
    uint32_t tmem;
    asm volatile("ld.shared.b32 %0, [%1];" : "=r"(tmem) : "r"(sbase));

    stage_tile(sm + A0, asrcH, tid);
    stage_tile(sm + B0, bsrcH, tid);
    stage_tile(sm + B1, bsrcL, tid);
    asm volatile("fence.proxy.async.shared::cta;" ::: "memory");
    __syncthreads();

    uint64_t adesc  = make_desc(sbase + A0);
    uint64_t bdescH = make_desc(sbase + B0);
    uint64_t bdescL = make_desc(sbase + B1);

    if (wid == 0 && elect_one_pred()) {
        #pragma unroll
        for (int s = 0; s < 16; s++) {
            uint64_t off = (uint64_t)((s >> 2) * 1024 + (s & 3) * 2);
            mma_f16_ss_cg1(tmem, adesc + off, bdescH + off, IDESC, s > 0);
        }
        #pragma unroll
        for (int s = 0; s < 16; s++) {
            uint64_t off = (uint64_t)((s >> 2) * 1024 + (s & 3) * 2);
            mma_f16_ss_cg1(tmem, adesc + off, bdescL + off, IDESC, 1);
        }
        TCGEN05_COMMIT(sbase + 16);
    }
    MBARRIER_WAIT_PARITY(sbase + 16, 0);
    __syncthreads();

    stage_tile(sm + A0, asrcL, tid);
    asm volatile("fence.proxy.async.shared::cta;" ::: "memory");
    __syncthreads();
    if (wid == 0 && elect_one_pred()) {
        #pragma unroll
        for (int s = 0; s < 16; s++) {
            uint64_t off = (uint64_t)((s >> 2) * 1024 + (s & 3) * 2);
            mma_f16_ss_cg1(tmem, adesc + off, bdescH + off, IDESC, 1);
        }
        TCGEN05_COMMIT(sbase + 16);
    }
    MBARRIER_WAIT_PARITY(sbase + 16, 1);
    TCGEN05_FENCE_AFTER();

    if (wid < 4) {
        int row = wid * 32 + lane;        // TMEM lane = D row = channel
        float bias = bp[g*640 + m_base + row];
        float* op = dst + (ch0 + row) * HWSZ + pbase;
        #pragma unroll
        for (int cb = 0; cb < 128; cb += 32) {
            uint32_t r[32];
            TCGEN05_LD_32X32B_X32(r, tmem + cb);
            TCGEN05_WAIT_LD();
            #pragma unroll
            for (int j = 0; j < 8; j++) {
                float4 o;
                o.x = __uint_as_float(r[4*j+0]) + bias;
                o.y = __uint_as_float(r[4*j+1]) + bias;
                o.z = __uint_as_float(r[4*j+2]) + bias;
                o.w = __uint_as_float(r[4*j+3]) + bias;
                *(float4*)(op + cb + 4*j) = o;
            }
        }
        TCGEN05_FENCE_BEFORE();
    }
    __syncthreads();
    if (wid == 0) TCGEN05_DEALLOC(tmem, 128);

#else  // ---------------- legacy mma.sync fallback (tensor cores via HMMA) ----------
    stage_tile(sm + A0, asrcH, tid);
    stage_tile(sm + B0, bsrcH, tid);
    stage_tile(sm + B1, bsrcL, tid);
    __syncthreads();

    int mb = (wid & 3) * 32;             // warp M offset (within 128)
    int nb = (wid >> 2) * 64;            // warp N offset
    uint32_t Ab  = sbase + A0;
    uint32_t BHb = sbase + B0;
    uint32_t BLb = sbase + B1;
    // A frag lane map: matrices {r0-7,k0-7},{r8-15,k0-7},{r0-7,k8-15},{r8-15,k8-15}
    int laneA_row = ((lane >> 3) & 1) * 8 + (lane & 7);
    int laneA_k8  = (lane >> 4) * 8;
    // B frag lane map: matrices {n0-7,k0-7},{n0-7,k8-15},{n8-15,k0-7},{n8-15,k8-15}
    int laneB_row = ((lane >> 4) & 1) * 8 + (lane & 7);
    int laneB_k8  = ((lane >> 3) & 1) * 8;

    float d[2][8][4];
    #pragma unroll
    for (int mi = 0; mi < 2; mi++)
        #pragma unroll
        for (int nj = 0; nj < 8; nj++)
            #pragma unroll
            for (int c = 0; c < 4; c++) d[mi][nj][c] = 0.f;

    // pass 1: Wh*Xh + Wh*Xl
    #pragma unroll 1
    for (int ks = 0; ks < 16; ks++) {
        int kk = ks * 16;
        uint32_t a[2][4];
        #pragma unroll
        for (int mi = 0; mi < 2; mi++)
            LDSM_X4(a[mi][0], a[mi][1], a[mi][2], a[mi][3],
                    tile_addr(Ab, mb + mi*16 + laneA_row, kk + laneA_k8));
        uint32_t bf[4][4];
        #pragma unroll
        for (int oj = 0; oj < 4; oj++)
            LDSM_X4(bf[oj][0], bf[oj][1], bf[oj][2], bf[oj][3],
                    tile_addr(BHb, nb + oj*16 + laneB_row, kk + laneB_k8));
        #pragma unroll
        for (int mi = 0; mi < 2; mi++)
            #pragma unroll
            for (int nj = 0; nj < 8; nj++)
                mma16816(d[mi][nj], a[mi], bf[nj>>1][(nj&1)*2], bf[nj>>1][(nj&1)*2+1]);
        #pragma unroll
        for (int oj = 0; oj < 4; oj++)
            LDSM_X4(bf[oj][0], bf[oj][1], bf[oj][2], bf[oj][3],
                    tile_addr(BLb, nb + oj*16 + laneB_row, kk + laneB_k8));
        #pragma unroll
        for (int mi = 0; mi < 2; mi++)
            #pragma unroll
            for (int nj = 0; nj < 8; nj++)
                mma16816(d[mi][nj], a[mi], bf[nj>>1][(nj&1)*2], bf[nj>>1][(nj&1)*2+1]);
    }
    __syncthreads();
    stage_tile(sm + A0, asrcL, tid);      // A slot now holds Wl
    __syncthreads();

    // pass 2: Wl*Xh
    #pragma unroll 1
    for (int ks = 0; ks < 16; ks++) {
        int kk = ks * 16;
        uint32_t a[2][4];
        #pragma unroll
        for (int mi = 0; mi < 2; mi++)
            LDSM_X4(a[mi][0], a[mi][1], a[mi][2], a[mi][3],
                    tile_addr(Ab, mb + mi*16 + laneA_row, kk + laneA_k8));
        uint32_t bf[4][4];
        #pragma unroll
        for (int oj = 0; oj < 4; oj++)
            LDSM_X4(bf[oj][0], bf[oj][1], bf[oj][2], bf[oj][3],
                    tile_addr(BHb, nb + oj*16 + laneB_row, kk + laneB_k8));
        #pragma unroll
        for (int mi = 0; mi < 2; mi++)
            #pragma unroll
            for (int nj = 0; nj < 8; nj++)
                mma16816(d[mi][nj], a[mi], bf[nj>>1][(nj&1)*2], bf[nj>>1][(nj&1)*2+1]);
    }

    // epilogue: c0/c1 at (r, col..col+1), c2/c3 at (r+8)
    #pragma unroll
    for (int mi = 0; mi < 2; mi++) {
        int r0 = mb + mi*16 + (lane >> 2);
        float bias0 = bp[g*640 + m_base + r0];
        float bias1 = bp[g*640 + m_base + r0 + 8];
        float* row0 = dst + (ch0 + r0)     * HWSZ + pbase;
        float* row1 = dst + (ch0 + r0 + 8) * HWSZ + pbase;
        #pragma unroll
        for (int nj = 0; nj < 8; nj++) {
            int col = nb + nj*8 + (lane & 3)*2;
            float2 o0 = { d[mi][nj][0] + bias0, d[mi][nj][1] + bias0 };
            float2 o1 = { d[mi][nj][2] + bias1, d[mi][nj][3] + bias1 };
            *(float2*)(row0 + col) = o0;
            *(float2*)(row1 + col) = o1;
        }
    }
#endif
}

// ---------------- 128x128 transpose per slice ----------------
__global__ void transpose_kernel(const float* __restrict__ in, float* __restrict__ out) {
    __shared__ float t[32][33];
    int tile = blockIdx.x;
    int bx = (tile & 3) * 32, by = (tile >> 2) * 32;
    const float* ip = in  + (size_t)blockIdx.y * HWSZ;
    float*       op = out + (size_t)blockIdx.y * HWSZ;
    int x = threadIdx.x, y = threadIdx.y;
    #pragma unroll
    for (int r = 0; r < 32; r += 8)
        t[y+r][x] = ip[(size_t)(by + y + r)*128 + bx + x];
    __syncthreads();
    #pragma unroll
    for (int r = 0; r < 32; r += 8)
        op[(size_t)(bx + y + r)*128 + by + x] = t[x][y+r];
}

// ---------------- per-slice axial attention (fp32) ----------------
__global__ __launch_bounds__(256, 1)
void attn_kernel(const float* __restrict__ q, const float* __restrict__ k,
                 const float* __restrict__ v, float* __restrict__ out) {
    extern __shared__ float smf[];
    float* Ks = smf;
    float* Qs = smf + 16384;
    float* At = smf + 32768;
    float* Vt = smf + 49152;
    const float SCALE = 0.08838834764831845f;

    int r = blockIdx.x, n = blockIdx.y, b = blockIdx.z;
    size_t qoff = ((size_t)(b*4 + n) * 128) * HWSZ + (size_t)r * 128;
    size_t voff = ((size_t)(b*4 + n) *  64) * HWSZ + (size_t)r * 128;
    int tid = threadIdx.x;

    #pragma unroll
    for (int u = 0; u < 16; u++) {
        int idx = tid + u*256;
        int c = idx >> 5, j4 = (idx & 31) << 2;
        *(float4*)(Qs + c*128 + j4) = *(const float4*)(q + qoff + (size_t)c*HWSZ + j4);
        *(float4*)(Ks + c*128 + j4) = *(const float4*)(k + qoff + (size_t)c*HWSZ + j4);
    }
    #pragma unroll
    for (int u = 0; u < 8; u++) {
        int idx = tid + u*256;
        int c = idx >> 5, j4 = (idx & 31) << 2;
        float4 vv = *(const float4*)(v + voff + (size_t)c*HWSZ + j4);
        Vt[(j4+0)*68 + c] = vv.x;
        Vt[(j4+1)*68 + c] = vv.y;
        Vt[(j4+2)*68 + c] = vv.z;
        Vt[(j4+3)*68 + c] = vv.w;
    }
    __syncthreads();

    int warp = tid >> 5, lane = tid & 31;
    int wm = warp >> 2, wn = warp & 3;
    int lm = lane >> 2, ln = lane & 3;
    int m0 = wm*64 + lm*8, n0 = wn*32 + ln*8;

    float acc[8][8];
    #pragma unroll
    for (int i = 0; i < 8; i++)
        #pragma unroll
        for (int j = 0; j < 8; j++) acc[i][j] = 0.f;

    #pragma unroll 2
    for (int c = 0; c < 128; c++) {
        float a[8], bb[8];
        *(float4*)(a)    = *(const float4*)(Qs + c*128 + m0);
        *(float4*)(a+4)  = *(const float4*)(Qs + c*128 + m0 + 4);
        *(float4*)(bb)   = *(const float4*)(Ks + c*128 + n0);
        *(float4*)(bb+4) = *(const float4*)(Ks + c*128 + n0 + 4);
        #pragma unroll
        for (int i = 0; i < 8; i++)
            #pragma unroll
            for (int j = 0; j < 8; j++)
                acc[i][j] += a[i]*bb[j];
    }
    #pragma unroll
    for (int i = 0; i < 8; i++)
        #pragma unroll
        for (int j = 0; j < 8; j++) acc[i][j] *= SCALE;

    __syncthreads();
    float* P = Qs;
    float* rstat = Qs + 4096;
    int gp = wn*4 + ln;

    #pragma unroll
    for (int i = 0; i < 8; i++) {
        float pm = acc[i][0];
        #pragma unroll
        for (int j = 1; j < 8; j++) pm = fmaxf(pm, acc[i][j]);
        P[(m0+i)*16 + gp] = pm;
    }
    __syncthreads();
    if (tid < 128) {
        float mx = P[tid*16];
        #pragma unroll
        for (int gg = 1; gg < 16; gg++) mx = fmaxf(mx, P[tid*16+gg]);
        rstat[tid] = mx;
    }
    __syncthreads();
    #pragma unroll
    for (int i = 0; i < 8; i++) {
        float mx = rstat[m0+i], ps = 0.f;
        #pragma unroll
        for (int j = 0; j < 8; j++) {
            float e = __expf(acc[i][j] - mx);
            acc[i][j] = e; ps += e;
        }
        P[(m0+i)*16 + gp] = ps;
    }
    __syncthreads();
    if (tid < 128) {
        float s = 0.f;
        #pragma unroll
        for (int gg = 0; gg < 16; gg++) s += P[tid*16+gg];
        rstat[tid] = 1.0f / s;
    }
    __syncthreads();
    #pragma unroll
    for (int i = 0; i < 8; i++) {
        float inv = rstat[m0+i];
        #pragma unroll
        for (int j = 0; j < 8; j++)
            At[(n0+j)*128 + (m0+i)] = acc[i][j] * inv;
    }
    __syncthreads();

    int c0 = wm*32 + lm*4;
    int i0 = n0;
    float oacc[4][8];
    #pragma unroll
    for (int cc = 0; cc < 4; cc++)
        #pragma unroll
        for (int j = 0; j < 8; j++) oacc[cc][j] = 0.f;

    #pragma unroll 2
    for (int j = 0; j < 128; j++) {
        float vv[4], aa[8];
        *(float4*)(vv)   = *(const float4*)(Vt + j*68 + c0);
        *(float4*)(aa)   = *(const float4*)(At + j*128 + i0);
        *(float4*)(aa+4) = *(const float4*)(At + j*128 + i0 + 4);
        #pragma unroll
        for (int cc = 0; cc < 4; cc++)
            #pragma unroll
            for (int jj = 0; jj < 8; jj++)
                oacc[cc][jj] += vv[cc]*aa[jj];
    }
    #pragma unroll
    for (int cc = 0; cc < 4; cc++) {
        float* op = out + voff + (size_t)(c0+cc)*HWSZ + i0;
        float4 r0, r1;
        r0.x = oacc[cc][0]; r0.y = oacc[cc][1]; r0.z = oacc[cc][2]; r0.w = oacc[cc][3];
        r1.x = oacc[cc][4]; r1.y = oacc[cc][5]; r1.z = oacc[cc][6]; r1.w = oacc[cc][7];
        *(float4*)op = r0; *(float4*)(op+4) = r1;
    }
}

// ---------------- BN stats + apply ----------------
__global__ void bn_stats_kernel(const float* __restrict__ x, const float* __restrict__ w,
                                const float* __restrict__ bb, float* __restrict__ sc) {
    int c = blockIdx.x;
    int tid = threadIdx.x;
    float s = 0.f, sq = 0.f;
    for (int b = 0; b < 4; b++) {
        const float* p = x + ((size_t)b*256 + c) * HWSZ;
        for (int i = tid; i < HWSZ; i += 256) { float vv = p[i]; s += vv; sq += vv*vv; }
    }
    __shared__ float ss[256], ssq[256];
    ss[tid] = s; ssq[tid] = sq; __syncthreads();
    for (int st = 128; st > 0; st >>= 1) {
        if (tid < st) { ss[tid] += ss[tid+st]; ssq[tid] += ssq[tid+st]; }
        __syncthreads();
    }
    if (tid == 0) {
        const float N = 65536.0f;
        float mean = ss[0] / N;
        float var  = ssq[0] / N - mean*mean;
        float scale = w[c] * rsqrtf(var + 1e-5f);
        sc[c]       = scale;
        sc[128 + c] = bb[c] - mean*scale;
    }
}

__global__ void bn_apply_kernel(const float* __restrict__ x, const float* __restrict__ sc,
                                float* __restrict__ outp) {
    int idx = blockIdx.x * 256 + threadIdx.x;
    int b  = idx >> 19;
    int c  = (idx >> 12) & 127;
    int i4 = (idx & 4095) << 2;
    float4 vv = *(const float4*)(x + ((size_t)b*256 + c)*HWSZ + i4);
    float s = sc[c], sh = sc[128+c];
    vv.x = vv.x*s + sh; vv.y = vv.y*s + sh; vv.z = vv.z*s + sh; vv.w = vv.w*s + sh;
    *(float4*)(outp + ((size_t)b*128 + c)*HWSZ + i4) = vv;
}

// ---------------- residual epilogue ----------------
__global__ void final_kernel(const float* __restrict__ x, const float* __restrict__ oh,
                             const float* __restrict__ ow, const float* __restrict__ gamma,
                             float* __restrict__ out) {
    size_t idx = (size_t)blockIdx.x * 256 + threadIdx.x;
    int b  = (int)(idx >> 21);
    int ch = (int)((idx >> 12) & 511);
    int i4 = (int)((idx & 4095) << 2);
    float gm = gamma[0];
    const float* tp = (ch < 256)
        ? oh + ((size_t)b*256 + ch)      *HWSZ + i4
        : ow + ((size_t)b*256 + (ch-256))*HWSZ + i4;
    float4 t  = *(const float4*)tp;
    float4 xv = *(const float4*)(x + ((size_t)b*512 + ch)*HWSZ + i4);
    float4 o;
    o.x = gm*fmaxf(t.x, 0.f) + xv.x;
    o.y = gm*fmaxf(t.y, 0.f) + xv.y;
    o.z = gm*fmaxf(t.z, 0.f) + xv.z;
    o.w = gm*fmaxf(t.w, 0.f) + xv.w;
    *(float4*)(out + idx*4) = o;
}

// ---------------- launch ----------------
extern "C" void kernel_launch(void* const* d_in, const int* in_sizes, int n_in,
                              void* d_out, int out_size) {
    const float* x     = (const float*)d_in[0];
    const float* wq    = (const float*)d_in[1];
    const float* bq    = (const float*)d_in[2];
    const float* wk    = (const float*)d_in[3];
    const float* bk    = (const float*)d_in[4];
    const float* wv    = (const float*)d_in[5];
    const float* bv    = (const float*)d_in[6];
    const float* bnh_w = (const float*)d_in[7];
    const float* bnh_b = (const float*)d_in[8];
    const float* bnw_w = (const float*)d_in[9];
    const float* bnw_b = (const float*)d_in[10];
    const float* gamma = (const float*)d_in[11];
    float* out = (float*)d_out;

    float *q, *k, *v, *qT, *kT, *vT, *oW, *oHT, *oH, *scH, *scW, *bp;
    __nv_bfloat16 *xThi, *xTlo, *wph, *wpl;
    cudaGetSymbolAddress((void**)&q,    g_q);
    cudaGetSymbolAddress((void**)&k,    g_k);
    cudaGetSymbolAddress((void**)&v,    g_v);
    cudaGetSymbolAddress((void**)&qT,   g_qT);
    cudaGetSymbolAddress((void**)&kT,   g_kT);
    cudaGetSymbolAddress((void**)&vT,   g_vT);
    cudaGetSymbolAddress((void**)&oW,   g_outW);
    cudaGetSymbolAddress((void**)&oHT,  g_outHT);
    cudaGetSymbolAddress((void**)&oH,   g_outH);
    cudaGetSymbolAddress((void**)&scH,  g_scH);
    cudaGetSymbolAddress((void**)&scW,  g_scW);
    cudaGetSymbolAddress((void**)&xThi, g_xThi);
    cudaGetSymbolAddress((void**)&xTlo, g_xTlo);
    cudaGetSymbolAddress((void**)&wph,  g_wph);
    cudaGetSymbolAddress((void**)&wpl,  g_wpl);
    cudaGetSymbolAddress((void**)&bp,   g_bp);

    cudaFuncSetAttribute(attn_kernel, cudaFuncAttributeMaxDynamicSharedMemorySize, ATT_SMEM);
    cudaFuncSetAttribute(gemm_kernel, cudaFuncAttributeMaxDynamicSharedMemorySize, GEMM_SMEM);

    // pack weights + split, transpose+split x
    prepw_kernel<<<1280, 256>>>(wq, bq, wk, bk, wv, bv, wph, wpl, bp);
    convx_kernel<<<dim3(512, 8, 8), dim3(32, 8)>>>(x, xThi, xTlo);

    // fused qkv projection (tensor cores, dual path)
    gemm_kernel<<<dim3(5, 128, 8), 256, GEMM_SMEM>>>(xThi, xTlo, wph, wpl, bp, q, k, v);

    // transposed copies for H-direction attention
    transpose_kernel<<<dim3(16, 2048), dim3(32,8)>>>(q, qT);
    transpose_kernel<<<dim3(16, 2048), dim3(32,8)>>>(k, kT);
    transpose_kernel<<<dim3(16, 1024), dim3(32,8)>>>(v, vT);

    // axial attention
    attn_kernel<<<dim3(128,4,4), 256, ATT_SMEM>>>(q,  k,  v,  oW);
    attn_kernel<<<dim3(128,4,4), 256, ATT_SMEM>>>(qT, kT, vT, oHT);
    transpose_kernel<<<dim3(16, 1024), dim3(32,8)>>>(oHT, oH);

    // BN side outputs
    bn_stats_kernel<<<128, 256>>>(oH, bnh_w, bnh_b, scH);
    bn_stats_kernel<<<128, 256>>>(oW, bnw_w, bnw_b, scW);
    bn_apply_kernel<<<8192, 256>>>(oH, scH, out + 33554432ull);
    bn_apply_kernel<<<8192, 256>>>(oW, scW, out + 41943040ull);

    // residual epilogue
    final_kernel<<<32768, 256>>>(x, oH, oW, gamma, out);
}

// round 4
// speedup vs baseline: 1.6110x; 1.2371x over previous
#include <cuda_runtime.h>
#include <cuda_bf16.h>
#include <math.h>
#include <stdint.h>

#define HWSZ 16384
#define GEMM_SMEM (1024 + 3*65536)
#define ATT2_SMEM 176128

// ---------------- scratch (static device arrays; no runtime alloc) ----------------
__device__ uint32_t g_qp [4ull*512*16384];   // packed bf16: hi | lo<<16
__device__ uint32_t g_kp [4ull*512*16384];
__device__ uint32_t g_vp [4ull*256*16384];
__device__ uint32_t g_qpT[4ull*512*16384];
__device__ uint32_t g_kpT[4ull*512*16384];
__device__ uint32_t g_vpT[4ull*256*16384];
__device__ float g_outW [4ull*256*16384];
__device__ float g_outHT[4ull*256*16384];
__device__ float g_outH [4ull*256*16384];
__device__ float g_scH[256];
__device__ float g_scW[256];
__device__ __nv_bfloat16 g_xThi[8ull*16384*256];   // [b*2+g][pix][k]
__device__ __nv_bfloat16 g_xTlo[8ull*16384*256];
__device__ __nv_bfloat16 g_wph[2*640*256];          // [g][m][k]
__device__ __nv_bfloat16 g_wpl[2*640*256];
__device__ float g_bp[2*640];

// ---------------- helpers ----------------
__device__ __forceinline__ uint32_t smem_u32(const void* p) {
    uint32_t a;
    asm("{ .reg .u64 t; cvta.to.shared.u64 t, %1; cvt.u32.u64 %0, t; }" : "=r"(a) : "l"(p));
    return a;
}

#define LDSM_X4(r0, r1, r2, r3, addr) \
    asm volatile("ldmatrix.sync.aligned.m8n8.x4.shared.b16 {%0,%1,%2,%3}, [%4];" \
        : "=r"(r0), "=r"(r1), "=r"(r2), "=r"(r3) : "r"(addr))
#define LDSM_X4_T(r0, r1, r2, r3, addr) \
    asm volatile("ldmatrix.sync.aligned.m8n8.x4.trans.shared.b16 {%0,%1,%2,%3}, [%4];" \
        : "=r"(r0), "=r"(r1), "=r"(r2), "=r"(r3) : "r"(addr))

__device__ __forceinline__ void mma16816(float* d, const uint32_t* a,
                                         uint32_t b0, uint32_t b1) {
    asm volatile(
        "mma.sync.aligned.m16n8k16.row.col.f32.bf16.bf16.f32 "
        "{%0,%1,%2,%3}, {%4,%5,%6,%7}, {%8,%9}, {%0,%1,%2,%3};"
        : "+f"(d[0]), "+f"(d[1]), "+f"(d[2]), "+f"(d[3])
        : "r"(a[0]), "r"(a[1]), "r"(a[2]), "r"(a[3]), "r"(b0), "r"(b1));
}

// pack f32 -> (bf16 hi) | (bf16 lo)<<16
__device__ __forceinline__ uint32_t pack_bf(float f) {
    __nv_bfloat16 h = __float2bfloat16(f);
    __nv_bfloat16 l = __float2bfloat16(f - __bfloat162float(h));
    return (uint32_t)__bfloat16_as_ushort(h) | ((uint32_t)__bfloat16_as_ushort(l) << 16);
}
// split two probs into (hi0,hi1) and (lo0,lo1) packed words
__device__ __forceinline__ void split2(float a, float b, uint32_t& h, uint32_t& l) {
    __nv_bfloat16 ha = __float2bfloat16(a);
    __nv_bfloat16 hb = __float2bfloat16(b);
    __nv_bfloat16 la = __float2bfloat16(a - __bfloat162float(ha));
    __nv_bfloat16 lb = __float2bfloat16(b - __bfloat162float(hb));
    h = (uint32_t)__bfloat16_as_ushort(ha) | ((uint32_t)__bfloat16_as_ushort(hb) << 16);
    l = (uint32_t)__bfloat16_as_ushort(la) | ((uint32_t)__bfloat16_as_ushort(lb) << 16);
}

// address of 16B row segment (row, bf16-col kc) in blocked SW128 atom tile layout
__device__ __forceinline__ uint32_t tile_addr(uint32_t tbase, int row, int kc) {
    uint32_t byte = (uint32_t)(((row >> 3) + ((kc >> 6) << 4)) * 1024
                  + ((row & 7) << 7)
                  + ((((kc & 63) << 1)) ^ ((row & 7) << 4)));
    return tbase + byte;
}

// ---------------- weight pack + bf16 split ----------------
__global__ void prepw_kernel(const float* __restrict__ wq, const float* __restrict__ bq,
                             const float* __restrict__ wk, const float* __restrict__ bk,
                             const float* __restrict__ wv, const float* __restrict__ bv,
                             __nv_bfloat16* __restrict__ wph, __nv_bfloat16* __restrict__ wpl,
                             float* __restrict__ bp) {
    int idx = blockIdx.x * 256 + threadIdx.x;
    int g = idx / 163840;
    int r = idx - g * 163840;
    int m = r >> 8, k = r & 255;
    const float* src; float bias;
    if (m < 256)       { src = wq + (size_t)(g*256 + m)       * 256; bias = bq[g*256 + m]; }
    else if (m < 512)  { src = wk + (size_t)(g*256 + (m-256)) * 256; bias = bk[g*256 + m-256]; }
    else               { src = wv + (size_t)(g*128 + (m-512)) * 256; bias = bv[g*128 + m-512]; }
    float w = src[k];
    __nv_bfloat16 h = __float2bfloat16(w);
    wph[idx] = h;
    wpl[idx] = __float2bfloat16(w - __bfloat162float(h));
    if (k == 0) bp[g*640 + m] = bias;
}

// ---------------- x: transpose [k][pix] -> [pix][k] + bf16 hi/lo split ----------------
__global__ void convx_kernel(const float* __restrict__ x,
                             __nv_bfloat16* __restrict__ hi, __nv_bfloat16* __restrict__ lo) {
    __shared__ float t[32][33];
    int px = blockIdx.x * 32;
    int kx = blockIdx.y * 32;
    int z = blockIdx.z;
    int b = z >> 1, gg = z & 1;
    const float* ip = x + ((size_t)b*512 + gg*256 + kx) * HWSZ + px;
    int xx = threadIdx.x, yy = threadIdx.y;
    #pragma unroll
    for (int r = 0; r < 32; r += 8)
        t[yy+r][xx] = ip[(size_t)(yy+r)*HWSZ + xx];
    __syncthreads();
    size_t obase = ((size_t)z * 16384 + px) * 256 + kx;
    #pragma unroll
    for (int r = 0; r < 32; r += 8) {
        float v = t[xx][yy+r];
        __nv_bfloat16 h = __float2bfloat16(v);
        __nv_bfloat16 l = __float2bfloat16(v - __bfloat162float(h));
        hi[obase + (size_t)(yy+r)*256 + xx] = h;
        lo[obase + (size_t)(yy+r)*256 + xx] = l;
    }
}

// ---------------- stage [128 x 256] bf16 tile into blocked SW128 layout (256 thr) ----
__device__ __forceinline__ void stage_tile(char* smp, const __nv_bfloat16* __restrict__ src,
                                           int tid) {
    #pragma unroll 4
    for (int it = 0; it < 16; it++) {
        int idx = it * 256 + tid;
        int row = idx >> 5;
        int k8 = (idx & 31) << 3;
        uint4 vdata = *(const uint4*)(src + (size_t)row * 256 + k8);
        uint32_t byte = (uint32_t)(((row >> 3) + ((k8 >> 6) << 4)) * 1024
                      + ((row & 7) << 7)
                      + (((k8 & 63) << 1) ^ ((row & 7) << 4)));
        *(uint4*)(smp + byte) = vdata;
    }
}

// ---------------- fused qkv projection GEMM (legacy mma.sync, bf16 3-term) ----------
// per CTA: D[128 ch x 128 pix]; output packed bf16 hi/lo uint32
__global__ __launch_bounds__(256, 1)
void gemm_kernel(const __nv_bfloat16* __restrict__ xThi, const __nv_bfloat16* __restrict__ xTlo,
                 const __nv_bfloat16* __restrict__ wph, const __nv_bfloat16* __restrict__ wpl,
                 const float* __restrict__ bp,
                 uint32_t* __restrict__ qb, uint32_t* __restrict__ kb2, uint32_t* __restrict__ vb) {
    extern __shared__ char sm[];
    uint32_t sbase = smem_u32(sm);
    const uint32_t A0 = 1024, B0 = 1024 + 65536, B1 = 1024 + 131072;
    int tid = threadIdx.x;
    int lane = tid & 31, wid = tid >> 5;
    int my = blockIdx.x;
    int pbase = blockIdx.y * 128;
    int z = blockIdx.z;
    int b = z >> 1, g = z & 1;
    int m_base = my * 128;

    const __nv_bfloat16* asrcH = wph + ((size_t)g*640 + m_base) * 256;
    const __nv_bfloat16* asrcL = wpl + ((size_t)g*640 + m_base) * 256;
    const __nv_bfloat16* bsrcH = xThi + ((size_t)z*16384 + pbase) * 256;
    const __nv_bfloat16* bsrcL = xTlo + ((size_t)z*16384 + pbase) * 256;

    uint32_t* dst; size_t ch0;
    if (my < 2)      { dst = qb;  ch0 = (size_t)b*512 + g*256 + m_base; }
    else if (my < 4) { dst = kb2; ch0 = (size_t)b*512 + g*256 + (m_base - 256); }
    else             { dst = vb;  ch0 = (size_t)b*256 + g*128 + (m_base - 512); }

    stage_tile(sm + A0, asrcH, tid);
    stage_tile(sm + B0, bsrcH, tid);
    stage_tile(sm + B1, bsrcL, tid);
    __syncthreads();

    int mb = (wid & 3) * 32;
    int nb = (wid >> 2) * 64;
    uint32_t Ab  = sbase + A0;
    uint32_t BHb = sbase + B0;
    uint32_t BLb = sbase + B1;
    int laneA_row = ((lane >> 3) & 1) * 8 + (lane & 7);
    int laneA_k8  = (lane >> 4) * 8;
    int laneB_row = ((lane >> 4) & 1) * 8 + (lane & 7);
    int laneB_k8  = ((lane >> 3) & 1) * 8;

    float d[2][8][4];
    #pragma unroll
    for (int mi = 0; mi < 2; mi++)
        #pragma unroll
        for (int nj = 0; nj < 8; nj++)
            #pragma unroll
            for (int c = 0; c < 4; c++) d[mi][nj][c] = 0.f;

    // pass 1: Wh*Xh + Wh*Xl
    #pragma unroll 1
    for (int ks = 0; ks < 16; ks++) {
        int kk = ks * 16;
        uint32_t a[2][4];
        #pragma unroll
        for (int mi = 0; mi < 2; mi++)
            LDSM_X4(a[mi][0], a[mi][1], a[mi][2], a[mi][3],
                    tile_addr(Ab, mb + mi*16 + laneA_row, kk + laneA_k8));
        uint32_t bf[4][4];
        #pragma unroll
        for (int oj = 0; oj < 4; oj++)
            LDSM_X4(bf[oj][0], bf[oj][1], bf[oj][2], bf[oj][3],
                    tile_addr(BHb, nb + oj*16 + laneB_row, kk + laneB_k8));
        #pragma unroll
        for (int mi = 0; mi < 2; mi++)
            #pragma unroll
            for (int nj = 0; nj < 8; nj++)
                mma16816(d[mi][nj], a[mi], bf[nj>>1][(nj&1)*2], bf[nj>>1][(nj&1)*2+1]);
        #pragma unroll
        for (int oj = 0; oj < 4; oj++)
            LDSM_X4(bf[oj][0], bf[oj][1], bf[oj][2], bf[oj][3],
                    tile_addr(BLb, nb + oj*16 + laneB_row, kk + laneB_k8));
        #pragma unroll
        for (int mi = 0; mi < 2; mi++)
            #pragma unroll
            for (int nj = 0; nj < 8; nj++)
                mma16816(d[mi][nj], a[mi], bf[nj>>1][(nj&1)*2], bf[nj>>1][(nj&1)*2+1]);
    }
    __syncthreads();
    stage_tile(sm + A0, asrcL, tid);      // A slot now holds Wl
    __syncthreads();

    // pass 2: Wl*Xh
    #pragma unroll 1
    for (int ks = 0; ks < 16; ks++) {
        int kk = ks * 16;
        uint32_t a[2][4];
        #pragma unroll
        for (int mi = 0; mi < 2; mi++)
            LDSM_X4(a[mi][0], a[mi][1], a[mi][2], a[mi][3],
                    tile_addr(Ab, mb + mi*16 + laneA_row, kk + laneA_k8));
        uint32_t bf[4][4];
        #pragma unroll
        for (int oj = 0; oj < 4; oj++)
            LDSM_X4(bf[oj][0], bf[oj][1], bf[oj][2], bf[oj][3],
                    tile_addr(BHb, nb + oj*16 + laneB_row, kk + laneB_k8));
        #pragma unroll
        for (int mi = 0; mi < 2; mi++)
            #pragma unroll
            for (int nj = 0; nj < 8; nj++)
                mma16816(d[mi][nj], a[mi], bf[nj>>1][(nj&1)*2], bf[nj>>1][(nj&1)*2+1]);
    }

    // epilogue: pack to bf16 hi/lo uint32
    #pragma unroll
    for (int mi = 0; mi < 2; mi++) {
        int r0 = mb + mi*16 + (lane >> 2);
        float bias0 = bp[g*640 + m_base + r0];
        float bias1 = bp[g*640 + m_base + r0 + 8];
        uint32_t* row0 = dst + (ch0 + r0)     * HWSZ + pbase;
        uint32_t* row1 = dst + (ch0 + r0 + 8) * HWSZ + pbase;
        #pragma unroll
        for (int nj = 0; nj < 8; nj++) {
            int col = nb + nj*8 + (lane & 3)*2;
            uint2 o0 = { pack_bf(d[mi][nj][0] + bias0), pack_bf(d[mi][nj][1] + bias0) };
            uint2 o1 = { pack_bf(d[mi][nj][2] + bias1), pack_bf(d[mi][nj][3] + bias1) };
            *(uint2*)(row0 + col) = o0;
            *(uint2*)(row1 + col) = o1;
        }
    }
}

// ---------------- 128x128 transpose per slice (4-byte elements) ----------------
__global__ void transpose_kernel(const float* __restrict__ in, float* __restrict__ out) {
    __shared__ float t[32][33];
    int tile = blockIdx.x;
    int bx = (tile & 3) * 32, by = (tile >> 2) * 32;
    const float* ip = in  + (size_t)blockIdx.y * HWSZ;
    float*       op = out + (size_t)blockIdx.y * HWSZ;
    int x = threadIdx.x, y = threadIdx.y;
    #pragma unroll
    for (int r = 0; r < 32; r += 8)
        t[y+r][x] = ip[(size_t)(by + y + r)*128 + bx + x];
    __syncthreads();
    #pragma unroll
    for (int r = 0; r < 32; r += 8)
        op[(size_t)(bx + y + r)*128 + by + x] = t[x][y+r];
}

// ---------------- per-slice axial attention (tensor cores, bf16 hi/lo) ----------------
// inputs: packed uint32 (bf16 hi | lo<<16). Q,K [128c][128pos], V [64c][128pos]
// S = scale*Q^T K (3-term) ; softmax fp32 ; O = V * A^T (3-term) -> f32 out
__global__ __launch_bounds__(256, 1)
void attn_mma_kernel(const uint32_t* __restrict__ qp, const uint32_t* __restrict__ kp,
                     const uint32_t* __restrict__ vp, float* __restrict__ out) {
    extern __shared__ char smc[];
    uint32_t sb = smem_u32(smc);
    const uint32_t SQh = 0, SQl = 34816, SKh = 69632, SKl = 104448,
                   SVh = 139264, SVl = 156672;
    float* redM = (float*)(smc + 174080);
    float* redS = (float*)(smc + 175104);
    const float SCALE = 0.08838834764831845f;   // 128^-0.5

    int r = blockIdx.x, n = blockIdx.y, b = blockIdx.z;
    size_t qoff = ((size_t)(b*4 + n) * 128) * HWSZ + (size_t)r * 128;
    size_t voff = ((size_t)(b*4 + n) *  64) * HWSZ + (size_t)r * 128;
    int tid = threadIdx.x;
    int lane = tid & 31, wid = tid >> 5;
    int g = lane >> 2, t = lane & 3;

    // ---- stage Q,K,V (unpack hi/lo) ----
    {
        const uint32_t* qs = qp + qoff;
        const uint32_t* ks = kp + qoff;
        #pragma unroll
        for (int u = 0; u < 16; u++) {
            int idx = u*256 + tid;
            int row = idx >> 5;
            int p4  = (idx & 31) << 2;
            uint32_t off = row*272 + p4*2;
            uint4 dq = *(const uint4*)(qs + (size_t)row*HWSZ + p4);
            uint2 qh = { (dq.x & 0xffffu) | (dq.y << 16), (dq.z & 0xffffu) | (dq.w << 16) };
            uint2 ql = { (dq.x >> 16) | (dq.y & 0xffff0000u), (dq.z >> 16) | (dq.w & 0xffff0000u) };
            *(uint2*)(smc + SQh + off) = qh;
            *(uint2*)(smc + SQl + off) = ql;
            uint4 dk = *(const uint4*)(ks + (size_t)row*HWSZ + p4);
            uint2 kh = { (dk.x & 0xffffu) | (dk.y << 16), (dk.z & 0xffffu) | (dk.w << 16) };
            uint2 kl = { (dk.x >> 16) | (dk.y & 0xffff0000u), (dk.z >> 16) | (dk.w & 0xffff0000u) };
            *(uint2*)(smc + SKh + off) = kh;
            *(uint2*)(smc + SKl + off) = kl;
        }
        const uint32_t* vs = vp + voff;
        #pragma unroll
        for (int u = 0; u < 8; u++) {
            int idx = u*256 + tid;
            int row = idx >> 5;
            int p4  = (idx & 31) << 2;
            uint32_t off = row*272 + p4*2;
            uint4 dv = *(const uint4*)(vs + (size_t)row*HWSZ + p4);
            uint2 vh = { (dv.x & 0xffffu) | (dv.y << 16), (dv.z & 0xffffu) | (dv.w << 16) };
            uint2 vl = { (dv.x >> 16) | (dv.y & 0xffff0000u), (dv.z >> 16) | (dv.w & 0xffff0000u) };
            *(uint2*)(smc + SVh + off) = vh;
            *(uint2*)(smc + SVl + off) = vl;
        }
    }
    __syncthreads();

    // ---- phase 1: S = Q^T K ----
    int wm = wid >> 1, wn = wid & 1;
    int m0 = wm * 32, n0 = wn * 64;
    float acc[2][8][4];
    #pragma unroll
    for (int mi = 0; mi < 2; mi++)
        #pragma unroll
        for (int nj = 0; nj < 8; nj++)
            #pragma unroll
            for (int c = 0; c < 4; c++) acc[mi][nj][c] = 0.f;

    int a_r = ((lane >> 4) << 3) + (lane & 7);
    int a_c = ((lane >> 3) & 1) << 3;
    int b_r = (((lane >> 3) & 1) << 3) + (lane & 7);
    int b_c = (lane >> 4) << 3;
    uint32_t aoff0 = (uint32_t)(a_r*272 + (m0 + a_c)*2);
    uint32_t boff0 = (uint32_t)(b_r*272 + (n0 + b_c)*2);

    #pragma unroll
    for (int ks = 0; ks < 8; ks++) {
        uint32_t kb = (uint32_t)(ks * 16 * 272);
        uint32_t aqh[2][4], aql[2][4];
        #pragma unroll
        for (int mi = 0; mi < 2; mi++) {
            uint32_t ad = sb + kb + aoff0 + mi*32;
            LDSM_X4_T(aqh[mi][0], aqh[mi][1], aqh[mi][2], aqh[mi][3], ad + SQh);
            LDSM_X4_T(aql[mi][0], aql[mi][1], aql[mi][2], aql[mi][3], ad + SQl);
        }
        uint32_t bkh[4][4], bkl[4][4];
        #pragma unroll
        for (int p = 0; p < 4; p++) {
            uint32_t bd = sb + kb + boff0 + p*32;
            LDSM_X4_T(bkh[p][0], bkh[p][1], bkh[p][2], bkh[p][3], bd + SKh);
            LDSM_X4_T(bkl[p][0], bkl[p][1], bkl[p][2], bkl[p][3], bd + SKl);
        }
        #pragma unroll
        for (int mi = 0; mi < 2; mi++)
            #pragma unroll
            for (int nj = 0; nj < 8; nj++) {
                int p = nj >> 1, q2 = (nj & 1) * 2;
                mma16816(acc[mi][nj], aqh[mi], bkh[p][q2], bkh[p][q2+1]);
                mma16816(acc[mi][nj], aqh[mi], bkl[p][q2], bkl[p][q2+1]);
                mma16816(acc[mi][nj], aql[mi], bkh[p][q2], bkh[p][q2+1]);
            }
    }
    #pragma unroll
    for (int mi = 0; mi < 2; mi++)
        #pragma unroll
        for (int nj = 0; nj < 8; nj++)
            #pragma unroll
            for (int c = 0; c < 4; c++) acc[mi][nj][c] *= SCALE;

    // ---- softmax (rows i) ----
    #pragma unroll
    for (int mi = 0; mi < 2; mi++) {
        int rA = m0 + mi*16 + g, rB = rA + 8;
        float mA = -1e30f, mB = -1e30f;
        #pragma unroll
        for (int nj = 0; nj < 8; nj++) {
            mA = fmaxf(mA, fmaxf(acc[mi][nj][0], acc[mi][nj][1]));
            mB = fmaxf(mB, fmaxf(acc[mi][nj][2], acc[mi][nj][3]));
        }
        mA = fmaxf(mA, __shfl_xor_sync(0xffffffffu, mA, 1));
        mA = fmaxf(mA, __shfl_xor_sync(0xffffffffu, mA, 2));
        mB = fmaxf(mB, __shfl_xor_sync(0xffffffffu, mB, 1));
        mB = fmaxf(mB, __shfl_xor_sync(0xffffffffu, mB, 2));
        if (t == 0) { redM[rA*2 + wn] = mA; redM[rB*2 + wn] = mB; }
    }
    __syncthreads();
    #pragma unroll
    for (int mi = 0; mi < 2; mi++) {
        int rA = m0 + mi*16 + g, rB = rA + 8;
        float mxA = fmaxf(redM[rA*2], redM[rA*2+1]);
        float mxB = fmaxf(redM[rB*2], redM[rB*2+1]);
        float sA = 0.f, sB = 0.f;
        #pragma unroll
        for (int nj = 0; nj < 8; nj++) {
            float e0 = __expf(acc[mi][nj][0] - mxA);
            float e1 = __expf(acc[mi][nj][1] - mxA);
            float e2 = __expf(acc[mi][nj][2] - mxB);
            float e3 = __expf(acc[mi][nj][3] - mxB);
            acc[mi][nj][0] = e0; acc[mi][nj][1] = e1;
            acc[mi][nj][2] = e2; acc[mi][nj][3] = e3;
            sA += e0 + e1; sB += e2 + e3;
        }
        sA += __shfl_xor_sync(0xffffffffu, sA, 1);
        sA += __shfl_xor_sync(0xffffffffu, sA, 2);
        sB += __shfl_xor_sync(0xffffffffu, sB, 1);
        sB += __shfl_xor_sync(0xffffffffu, sB, 2);
        if (t == 0) { redS[rA*2 + wn] = sA; redS[rB*2 + wn] = sB; }
    }
    __syncthreads();

    // ---- write A (normalized) hi/lo into Q smem slots, layout [i][j] ----
    #pragma unroll
    for (int mi = 0; mi < 2; mi++) {
        int rA = m0 + mi*16 + g, rB = rA + 8;
        float iA = 1.0f / (redS[rA*2] + redS[rA*2+1]);
        float iB = 1.0f / (redS[rB*2] + redS[rB*2+1]);
        #pragma unroll
        for (int nj = 0; nj < 8; nj++) {
            int j0 = n0 + nj*8 + t*2;
            uint32_t h, l;
            split2(acc[mi][nj][0]*iA, acc[mi][nj][1]*iA, h, l);
            *(uint32_t*)(smc + SQh + rA*272 + j0*2) = h;
            *(uint32_t*)(smc + SQl + rA*272 + j0*2) = l;
            split2(acc[mi][nj][2]*iB, acc[mi][nj][3]*iB, h, l);
            *(uint32_t*)(smc + SQh + rB*272 + j0*2) = h;
            *(uint32_t*)(smc + SQl + rB*272 + j0*2) = l;
        }
    }
    __syncthreads();

    // ---- phase 2: O[c][i] = sum_j V[c][j] A[i][j] ----
    int wm2 = wid >> 2, wn2 = wid & 3;
    int c0 = wm2 * 32, i0 = wn2 * 32;
    float oacc[2][4][4];
    #pragma unroll
    for (int mi = 0; mi < 2; mi++)
        #pragma unroll
        for (int nj = 0; nj < 4; nj++)
            #pragma unroll
            for (int c = 0; c < 4; c++) oacc[mi][nj][c] = 0.f;

    int ar2 = (((lane >> 3) & 1) << 3) + (lane & 7);
    int ac2 = (lane >> 4) << 3;
    int br2 = ((lane >> 4) << 3) + (lane & 7);
    int bc2 = ((lane >> 3) & 1) << 3;

    #pragma unroll
    for (int ks = 0; ks < 8; ks++) {
        int kb = ks * 16;
        uint32_t avh[2][4], avl[2][4];
        #pragma unroll
        for (int mi = 0; mi < 2; mi++) {
            uint32_t ad = sb + (uint32_t)((c0 + mi*16 + ar2)*272 + (kb + ac2)*2);
            LDSM_X4(avh[mi][0], avh[mi][1], avh[mi][2], avh[mi][3], ad + SVh);
            LDSM_X4(avl[mi][0], avl[mi][1], avl[mi][2], avl[mi][3], ad + SVl);
        }
        uint32_t bah[2][4], bal[2][4];
        #pragma unroll
        for (int ib2 = 0; ib2 < 2; ib2++) {
            uint32_t bd = sb + (uint32_t)((i0 + ib2*16 + br2)*272 + (kb + bc2)*2);
            LDSM_X4(bah[ib2][0], bah[ib2][1], bah[ib2][2], bah[ib2][3], bd + SQh);
            LDSM_X4(bal[ib2][0], bal[ib2][1], bal[ib2][2], bal[ib2][3], bd + SQl);
        }
        #pragma unroll
        for (int mi = 0; mi < 2; mi++)
            #pragma unroll
            for (int nj = 0; nj < 4; nj++) {
                int ib2 = nj >> 1, q2 = (nj & 1) * 2;
                mma16816(oacc[mi][nj], avh[mi], bah[ib2][q2], bah[ib2][q2+1]);
                mma16816(oacc[mi][nj], avh[mi], bal[ib2][q2], bal[ib2][q2+1]);
                mma16816(oacc[mi][nj], avl[mi], bah[ib2][q2], bah[ib2][q2+1]);
            }
    }

    // ---- write O (f32, direct; 32B sectors per row) ----
    #pragma unroll
    for (int mi = 0; mi < 2; mi++) {
        int cA = c0 + mi*16 + g, cB = cA + 8;
        float* oA = out + voff + (size_t)cA * HWSZ;
        float* oB = out + voff + (size_t)cB * HWSZ;
        #pragma unroll
        for (int nj = 0; nj < 4; nj++) {
            int i = i0 + nj*8 + t*2;
            float2 vA = { oacc[mi][nj][0], oacc[mi][nj][1] };
            float2 vB = { oacc[mi][nj][2], oacc[mi][nj][3] };
            *(float2*)(oA + i) = vA;
            *(float2*)(oB + i) = vB;
        }
    }
}

// ---------------- BN stats + apply ----------------
__global__ void bn_stats_kernel(const float* __restrict__ x, const float* __restrict__ w,
                                const float* __restrict__ bb, float* __restrict__ sc) {
    int c = blockIdx.x;
    int tid = threadIdx.x;
    float s = 0.f, sq = 0.f;
    for (int b = 0; b < 4; b++) {
        const float* p = x + ((size_t)b*256 + c) * HWSZ;
        for (int i = tid; i < HWSZ; i += 256) { float vv = p[i]; s += vv; sq += vv*vv; }
    }
    __shared__ float ss[256], ssq[256];
    ss[tid] = s; ssq[tid] = sq; __syncthreads();
    for (int st = 128; st > 0; st >>= 1) {
        if (tid < st) { ss[tid] += ss[tid+st]; ssq[tid] += ssq[tid+st]; }
        __syncthreads();
    }
    if (tid == 0) {
        const float N = 65536.0f;
        float mean = ss[0] / N;
        float var  = ssq[0] / N - mean*mean;
        float scale = w[c] * rsqrtf(var + 1e-5f);
        sc[c]       = scale;
        sc[128 + c] = bb[c] - mean*scale;
    }
}

__global__ void bn_apply_kernel(const float* __restrict__ x, const float* __restrict__ sc,
                                float* __restrict__ outp) {
    int idx = blockIdx.x * 256 + threadIdx.x;
    int b  = idx >> 19;
    int c  = (idx >> 12) & 127;
    int i4 = (idx & 4095) << 2;
    float4 vv = *(const float4*)(x + ((size_t)b*256 + c)*HWSZ + i4);
    float s = sc[c], sh = sc[128+c];
    vv.x = vv.x*s + sh; vv.y = vv.y*s + sh; vv.z = vv.z*s + sh; vv.w = vv.w*s + sh;
    *(float4*)(outp + ((size_t)b*128 + c)*HWSZ + i4) = vv;
}

// ---------------- residual epilogue ----------------
__global__ void final_kernel(const float* __restrict__ x, const float* __restrict__ oh,
                             const float* __restrict__ ow, const float* __restrict__ gamma,
                             float* __restrict__ out) {
    size_t idx = (size_t)blockIdx.x * 256 + threadIdx.x;
    int b  = (int)(idx >> 21);
    int ch = (int)((idx >> 12) & 511);
    int i4 = (int)((idx & 4095) << 2);
    float gm = gamma[0];
    const float* tp = (ch < 256)
        ? oh + ((size_t)b*256 + ch)      *HWSZ + i4
        : ow + ((size_t)b*256 + (ch-256))*HWSZ + i4;
    float4 t  = *(const float4*)tp;
    float4 xv = *(const float4*)(x + ((size_t)b*512 + ch)*HWSZ + i4);
    float4 o;
    o.x = gm*fmaxf(t.x, 0.f) + xv.x;
    o.y = gm*fmaxf(t.y, 0.f) + xv.y;
    o.z = gm*fmaxf(t.z, 0.f) + xv.z;
    o.w = gm*fmaxf(t.w, 0.f) + xv.w;
    *(float4*)(out + idx*4) = o;
}

// ---------------- launch ----------------
extern "C" void kernel_launch(void* const* d_in, const int* in_sizes, int n_in,
                              void* d_out, int out_size) {
    const float* x     = (const float*)d_in[0];
    const float* wq    = (const float*)d_in[1];
    const float* bq    = (const float*)d_in[2];
    const float* wk    = (const float*)d_in[3];
    const float* bk    = (const float*)d_in[4];
    const float* wv    = (const float*)d_in[5];
    const float* bv    = (const float*)d_in[6];
    const float* bnh_w = (const float*)d_in[7];
    const float* bnh_b = (const float*)d_in[8];
    const float* bnw_w = (const float*)d_in[9];
    const float* bnw_b = (const float*)d_in[10];
    const float* gamma = (const float*)d_in[11];
    float* out = (float*)d_out;

    uint32_t *qp, *kp, *vp, *qpT, *kpT, *vpT;
    float *oW, *oHT, *oH, *scH, *scW, *bp;
    __nv_bfloat16 *xThi, *xTlo, *wph, *wpl;
    cudaGetSymbolAddress((void**)&qp,   g_qp);
    cudaGetSymbolAddress((void**)&kp,   g_kp);
    cudaGetSymbolAddress((void**)&vp,   g_vp);
    cudaGetSymbolAddress((void**)&qpT,  g_qpT);
    cudaGetSymbolAddress((void**)&kpT,  g_kpT);
    cudaGetSymbolAddress((void**)&vpT,  g_vpT);
    cudaGetSymbolAddress((void**)&oW,   g_outW);
    cudaGetSymbolAddress((void**)&oHT,  g_outHT);
    cudaGetSymbolAddress((void**)&oH,   g_outH);
    cudaGetSymbolAddress((void**)&scH,  g_scH);
    cudaGetSymbolAddress((void**)&scW,  g_scW);
    cudaGetSymbolAddress((void**)&xThi, g_xThi);
    cudaGetSymbolAddress((void**)&xTlo, g_xTlo);
    cudaGetSymbolAddress((void**)&wph,  g_wph);
    cudaGetSymbolAddress((void**)&wpl,  g_wpl);
    cudaGetSymbolAddress((void**)&bp,   g_bp);

    cudaFuncSetAttribute(gemm_kernel, cudaFuncAttributeMaxDynamicSharedMemorySize, GEMM_SMEM);
    cudaFuncSetAttribute(attn_mma_kernel, cudaFuncAttributeMaxDynamicSharedMemorySize, ATT2_SMEM);

    // 1-2: pack weights + split, transpose+split x
    prepw_kernel<<<1280, 256>>>(wq, bq, wk, bk, wv, bv, wph, wpl, bp);
    convx_kernel<<<dim3(512, 8, 8), dim3(32, 8)>>>(x, xThi, xTlo);

    // 3: fused qkv projection (tensor cores), packed bf16 hi/lo output
    gemm_kernel<<<dim3(5, 128, 8), 256, GEMM_SMEM>>>(xThi, xTlo, wph, wpl, bp, qp, kp, vp);

    // 4-5: transposed copies (packed 4B elements) for H-direction
    transpose_kernel<<<dim3(16, 2048), dim3(32,8)>>>((const float*)qp, (float*)qpT);
    transpose_kernel<<<dim3(16, 2048), dim3(32,8)>>>((const float*)kp, (float*)kpT);

    // 6: W-direction attention (this is the ncu-profiled launch)
    attn_mma_kernel<<<dim3(128,4,4), 256, ATT2_SMEM>>>(qp, kp, vp, oW);

    // 7: v transpose, 8: H-direction attention, 9: transpose back
    transpose_kernel<<<dim3(16, 1024), dim3(32,8)>>>((const float*)vp, (float*)vpT);
    attn_mma_kernel<<<dim3(128,4,4), 256, ATT2_SMEM>>>(qpT, kpT, vpT, oHT);
    transpose_kernel<<<dim3(16, 1024), dim3(32,8)>>>(oHT, oH);

    // BN side outputs
    bn_stats_kernel<<<128, 256>>>(oH, bnh_w, bnh_b, scH);
    bn_stats_kernel<<<128, 256>>>(oW, bnw_w, bnw_b, scW);
    bn_apply_kernel<<<8192, 256>>>(oH, scH, out + 33554432ull);
    bn_apply_kernel<<<8192, 256>>>(oW, scW, out + 41943040ull);

    // residual epilogue
    final_kernel<<<32768, 256>>>(x, oH, oW, gamma, out);
}

// round 5
// speedup vs baseline: 1.9105x; 1.1859x over previous
#include <cuda_runtime.h>
#include <cuda_bf16.h>
#include <math.h>
#include <stdint.h>

#define HWSZ 16384
#define GEMM_SMEM (1024 + 2*65536 + 2*32768)
#define ATT2_SMEM 176128

// ---------------- scratch (static device arrays; no runtime alloc) ----------------
__device__ uint32_t g_qp [4ull*512*16384];   // packed bf16: hi | lo<<16
__device__ uint32_t g_kp [4ull*512*16384];
__device__ uint32_t g_vp [4ull*256*16384];
__device__ uint32_t g_qpT[4ull*512*16384];
__device__ uint32_t g_kpT[4ull*512*16384];
__device__ uint32_t g_vpT[4ull*256*16384];
__device__ float g_outW [4ull*256*16384];
__device__ float g_outHT[4ull*256*16384];
__device__ float g_outH [4ull*256*16384];
__device__ float g_scH[256];
__device__ float g_scW[256];
__device__ __nv_bfloat16 g_xThi[8ull*16384*256];   // [b*2+g][pix][k]
__device__ __nv_bfloat16 g_xTlo[8ull*16384*256];
__device__ __nv_bfloat16 g_wph[2*640*256];          // [g][m][k]
__device__ __nv_bfloat16 g_wpl[2*640*256];
__device__ float g_bp[2*640];

// ---------------- helpers ----------------
__device__ __forceinline__ uint32_t smem_u32(const void* p) {
    uint32_t a;
    asm("{ .reg .u64 t; cvta.to.shared.u64 t, %1; cvt.u32.u64 %0, t; }" : "=r"(a) : "l"(p));
    return a;
}

#define LDSM_X4(r0, r1, r2, r3, addr) \
    asm volatile("ldmatrix.sync.aligned.m8n8.x4.shared.b16 {%0,%1,%2,%3}, [%4];" \
        : "=r"(r0), "=r"(r1), "=r"(r2), "=r"(r3) : "r"(addr))
#define LDSM_X4_T(r0, r1, r2, r3, addr) \
    asm volatile("ldmatrix.sync.aligned.m8n8.x4.trans.shared.b16 {%0,%1,%2,%3}, [%4];" \
        : "=r"(r0), "=r"(r1), "=r"(r2), "=r"(r3) : "r"(addr))
#define CP_ASYNC16(dst, src) \
    asm volatile("cp.async.cg.shared.global [%0], [%1], 16;" :: "r"(dst), "l"(src))
#define CP_COMMIT() asm volatile("cp.async.commit_group;" ::: "memory")
#define CP_WAIT0()  asm volatile("cp.async.wait_group 0;" ::: "memory")

__device__ __forceinline__ void mma16816(float* d, const uint32_t* a,
                                         uint32_t b0, uint32_t b1) {
    asm volatile(
        "mma.sync.aligned.m16n8k16.row.col.f32.bf16.bf16.f32 "
        "{%0,%1,%2,%3}, {%4,%5,%6,%7}, {%8,%9}, {%0,%1,%2,%3};"
        : "+f"(d[0]), "+f"(d[1]), "+f"(d[2]), "+f"(d[3])
        : "r"(a[0]), "r"(a[1]), "r"(a[2]), "r"(a[3]), "r"(b0), "r"(b1));
}

__device__ __forceinline__ uint32_t pack_bf(float f) {
    __nv_bfloat16 h = __float2bfloat16(f);
    __nv_bfloat16 l = __float2bfloat16(f - __bfloat162float(h));
    return (uint32_t)__bfloat16_as_ushort(h) | ((uint32_t)__bfloat16_as_ushort(l) << 16);
}
__device__ __forceinline__ void split2(float a, float b, uint32_t& h, uint32_t& l) {
    __nv_bfloat16 ha = __float2bfloat16(a);
    __nv_bfloat16 hb = __float2bfloat16(b);
    __nv_bfloat16 la = __float2bfloat16(a - __bfloat162float(ha));
    __nv_bfloat16 lb = __float2bfloat16(b - __bfloat162float(hb));
    h = (uint32_t)__bfloat16_as_ushort(ha) | ((uint32_t)__bfloat16_as_ushort(hb) << 16);
    l = (uint32_t)__bfloat16_as_ushort(la) | ((uint32_t)__bfloat16_as_ushort(lb) << 16);
}

// address of 16B row segment (row, bf16-col kc) in blocked SW128 atom tile layout
__device__ __forceinline__ uint32_t tile_addr(uint32_t tbase, int row, int kc) {
    uint32_t byte = (uint32_t)(((row >> 3) + ((kc >> 6) << 4)) * 1024
                  + ((row & 7) << 7)
                  + ((((kc & 63) << 1)) ^ ((row & 7) << 4)));
    return tbase + byte;
}

// ---------------- weight pack + bf16 split ----------------
__global__ void prepw_kernel(const float* __restrict__ wq, const float* __restrict__ bq,
                             const float* __restrict__ wk, const float* __restrict__ bk,
                             const float* __restrict__ wv, const float* __restrict__ bv,
                             __nv_bfloat16* __restrict__ wph, __nv_bfloat16* __restrict__ wpl,
                             float* __restrict__ bp) {
    int idx = blockIdx.x * 256 + threadIdx.x;
    int g = idx / 163840;
    int r = idx - g * 163840;
    int m = r >> 8, k = r & 255;
    const float* src; float bias;
    if (m < 256)       { src = wq + (size_t)(g*256 + m)       * 256; bias = bq[g*256 + m]; }
    else if (m < 512)  { src = wk + (size_t)(g*256 + (m-256)) * 256; bias = bk[g*256 + m-256]; }
    else               { src = wv + (size_t)(g*128 + (m-512)) * 256; bias = bv[g*128 + m-512]; }
    float w = src[k];
    __nv_bfloat16 h = __float2bfloat16(w);
    wph[idx] = h;
    wpl[idx] = __float2bfloat16(w - __bfloat162float(h));
    if (k == 0) bp[g*640 + m] = bias;
}

// ---------------- x: transpose [k][pix] -> [pix][k] + bf16 hi/lo split ----------------
__global__ void convx_kernel(const float* __restrict__ x,
                             __nv_bfloat16* __restrict__ hi, __nv_bfloat16* __restrict__ lo) {
    __shared__ float t[32][33];
    int px = blockIdx.x * 32;
    int kx = blockIdx.y * 32;
    int z = blockIdx.z;
    int b = z >> 1, gg = z & 1;
    const float* ip = x + ((size_t)b*512 + gg*256 + kx) * HWSZ + px;
    int xx = threadIdx.x, yy = threadIdx.y;
    #pragma unroll
    for (int r = 0; r < 32; r += 8)
        t[yy+r][xx] = ip[(size_t)(yy+r)*HWSZ + xx];
    __syncthreads();
    size_t obase = ((size_t)z * 16384 + px) * 256 + kx;
    #pragma unroll
    for (int r = 0; r < 32; r += 8) {
        float v = t[xx][yy+r];
        __nv_bfloat16 h = __float2bfloat16(v);
        __nv_bfloat16 l = __float2bfloat16(v - __bfloat162float(h));
        hi[obase + (size_t)(yy+r)*256 + xx] = h;
        lo[obase + (size_t)(yy+r)*256 + xx] = l;
    }
}

// ---- stage [128 x 256] bf16 tile (row stride 256) into blocked SW128 layout, async ----
__device__ __forceinline__ void stage_b256(uint32_t smb, const __nv_bfloat16* __restrict__ src,
                                           int tid) {
    #pragma unroll
    for (int it = 0; it < 16; it++) {
        int idx = it * 256 + tid;
        int row = idx >> 5;
        int k8 = (idx & 31) << 3;
        uint32_t byte = (uint32_t)(((row >> 3) + ((k8 >> 6) << 4)) * 1024
                      + ((row & 7) << 7)
                      + (((k8 & 63) << 1) ^ ((row & 7) << 4)));
        CP_ASYNC16(smb + byte, src + (size_t)row * 256 + k8);
    }
}
// ---- stage [128 x 128] bf16 A half-tile (row stride 256, col offset kh*128), async ----
__device__ __forceinline__ void stage_a128(uint32_t smb, const __nv_bfloat16* __restrict__ src,
                                           int tid) {
    #pragma unroll
    for (int it = 0; it < 8; it++) {
        int idx = it * 256 + tid;
        int row = idx >> 4;
        int k8 = (idx & 15) << 3;
        uint32_t byte = (uint32_t)(((row >> 3) + ((k8 >> 6) << 4)) * 1024
                      + ((row & 7) << 7)
                      + (((k8 & 63) << 1) ^ ((row & 7) << 4)));
        CP_ASYNC16(smb + byte, src + (size_t)row * 256 + k8);
    }
}

// ---------------- fused qkv projection GEMM (B-resident, 5 m-tiles per CTA) ----------
// CTA: all 640 channels x 128 pixels. B = X (hi+lo) resident; A = W streamed in k-halves.
__global__ __launch_bounds__(256, 1)
void gemm_kernel(const __nv_bfloat16* __restrict__ xThi, const __nv_bfloat16* __restrict__ xTlo,
                 const __nv_bfloat16* __restrict__ wph, const __nv_bfloat16* __restrict__ wpl,
                 const float* __restrict__ bp,
                 uint32_t* __restrict__ qb, uint32_t* __restrict__ kb2, uint32_t* __restrict__ vb) {
    extern __shared__ char sm[];
    uint32_t sbase = smem_u32(sm);
    const uint32_t AH = 1024, AL = 1024 + 32768, BH = 1024 + 65536, BL = 1024 + 131072;
    int tid = threadIdx.x;
    int lane = tid & 31, wid = tid >> 5;
    int pbase = blockIdx.x * 128;
    int z = blockIdx.y;                 // b*2+g
    int b = z >> 1, g = z & 1;

    // stage B (X hi/lo) once
    stage_b256(sbase + BH, xThi + ((size_t)z*16384 + pbase) * 256, tid);
    stage_b256(sbase + BL, xTlo + ((size_t)z*16384 + pbase) * 256, tid);
    CP_COMMIT(); CP_WAIT0();
    __syncthreads();

    int mb = (wid & 1) * 64;            // warp M offset (64-row warp tile)
    int nb = (wid >> 1) * 32;           // warp N offset (32-col warp tile)
    int laneA_row = ((lane >> 3) & 1) * 8 + (lane & 7);
    int laneA_k8  = (lane >> 4) * 8;
    int laneB_row = ((lane >> 4) & 1) * 8 + (lane & 7);
    int laneB_k8  = ((lane >> 3) & 1) * 8;

    #pragma unroll 1
    for (int mt = 0; mt < 5; mt++) {
        const __nv_bfloat16* ah = wph + ((size_t)g*640 + mt*128) * 256;
        const __nv_bfloat16* al = wpl + ((size_t)g*640 + mt*128) * 256;

        float d[4][4][4];
        #pragma unroll
        for (int mi = 0; mi < 4; mi++)
            #pragma unroll
            for (int nj = 0; nj < 4; nj++)
                #pragma unroll
                for (int c = 0; c < 4; c++) d[mi][nj][c] = 0.f;

        #pragma unroll 1
        for (int kh = 0; kh < 2; kh++) {
            __syncthreads();            // previous mma done before overwriting A
            stage_a128(sbase + AH, ah + kh*128, tid);
            stage_a128(sbase + AL, al + kh*128, tid);
            CP_COMMIT(); CP_WAIT0();
            __syncthreads();

            #pragma unroll 2
            for (int ks = 0; ks < 8; ks++) {
                int kl = ks * 16;               // local k within half for A
                int kk = kh * 128 + kl;         // global k for B
                uint32_t aH[4][4], aL[4][4];
                #pragma unroll
                for (int mi = 0; mi < 4; mi++) {
                    LDSM_X4(aH[mi][0], aH[mi][1], aH[mi][2], aH[mi][3],
                            tile_addr(sbase + AH, mb + mi*16 + laneA_row, kl + laneA_k8));
                    LDSM_X4(aL[mi][0], aL[mi][1], aL[mi][2], aL[mi][3],
                            tile_addr(sbase + AL, mb + mi*16 + laneA_row, kl + laneA_k8));
                }
                uint32_t bH[2][4], bL[2][4];
                #pragma unroll
                for (int p = 0; p < 2; p++) {
                    LDSM_X4(bH[p][0], bH[p][1], bH[p][2], bH[p][3],
                            tile_addr(sbase + BH, nb + p*16 + laneB_row, kk + laneB_k8));
                    LDSM_X4(bL[p][0], bL[p][1], bL[p][2], bL[p][3],
                            tile_addr(sbase + BL, nb + p*16 + laneB_row, kk + laneB_k8));
                }
                #pragma unroll
                for (int mi = 0; mi < 4; mi++)
                    #pragma unroll
                    for (int nj = 0; nj < 4; nj++) {
                        int p = nj >> 1, q = (nj & 1) * 2;
                        mma16816(d[mi][nj], aH[mi], bH[p][q], bH[p][q+1]);
                        mma16816(d[mi][nj], aH[mi], bL[p][q], bL[p][q+1]);
                        mma16816(d[mi][nj], aL[mi], bH[p][q], bH[p][q+1]);
                    }
            }
        }

        // epilogue for this m-tile
        uint32_t* dst; size_t ch0;
        if (mt < 2)      { dst = qb;  ch0 = (size_t)b*512 + g*256 + mt*128; }
        else if (mt < 4) { dst = kb2; ch0 = (size_t)b*512 + g*256 + (mt-2)*128; }
        else             { dst = vb;  ch0 = (size_t)b*256 + g*128; }
        #pragma unroll
        for (int mi = 0; mi < 4; mi++) {
            int r0 = mb + mi*16 + (lane >> 2);
            float bias0 = bp[g*640 + mt*128 + r0];
            float bias1 = bp[g*640 + mt*128 + r0 + 8];
            uint32_t* row0 = dst + (ch0 + r0)     * HWSZ + pbase;
            uint32_t* row1 = dst + (ch0 + r0 + 8) * HWSZ + pbase;
            #pragma unroll
            for (int nj = 0; nj < 4; nj++) {
                int col = nb + nj*8 + (lane & 3)*2;
                uint2 o0 = { pack_bf(d[mi][nj][0] + bias0), pack_bf(d[mi][nj][1] + bias0) };
                uint2 o1 = { pack_bf(d[mi][nj][2] + bias1), pack_bf(d[mi][nj][3] + bias1) };
                *(uint2*)(row0 + col) = o0;
                *(uint2*)(row1 + col) = o1;
            }
        }
    }
}

// ---------------- 128x128 transpose per slice (4-byte elements) ----------------
__global__ void transpose_kernel(const float* __restrict__ in, float* __restrict__ out) {
    __shared__ float t[32][33];
    int tile = blockIdx.x;
    int bx = (tile & 3) * 32, by = (tile >> 2) * 32;
    const float* ip = in  + (size_t)blockIdx.y * HWSZ;
    float*       op = out + (size_t)blockIdx.y * HWSZ;
    int x = threadIdx.x, y = threadIdx.y;
    #pragma unroll
    for (int r = 0; r < 32; r += 8)
        t[y+r][x] = ip[(size_t)(by + y + r)*128 + bx + x];
    __syncthreads();
    #pragma unroll
    for (int r = 0; r < 32; r += 8)
        op[(size_t)(bx + y + r)*128 + by + x] = t[x][y+r];
}

// ---------------- per-slice axial attention (tensor cores, bf16 hi/lo) ----------------
__global__ __launch_bounds__(256, 1)
void attn_mma_kernel(const uint32_t* __restrict__ qp, const uint32_t* __restrict__ kp,
                     const uint32_t* __restrict__ vp, float* __restrict__ out) {
    extern __shared__ char smc[];
    uint32_t sb = smem_u32(smc);
    const uint32_t SQh = 0, SQl = 34816, SKh = 69632, SKl = 104448,
                   SVh = 139264, SVl = 156672;
    float* redM = (float*)(smc + 174080);
    float* redS = (float*)(smc + 175104);
    const float SCALE = 0.08838834764831845f;

    int r = blockIdx.x, n = blockIdx.y, b = blockIdx.z;
    size_t qoff = ((size_t)(b*4 + n) * 128) * HWSZ + (size_t)r * 128;
    size_t voff = ((size_t)(b*4 + n) *  64) * HWSZ + (size_t)r * 128;
    int tid = threadIdx.x;
    int lane = tid & 31, wid = tid >> 5;
    int g = lane >> 2, t = lane & 3;

    {
        const uint32_t* qs = qp + qoff;
        const uint32_t* ks = kp + qoff;
        #pragma unroll
        for (int u = 0; u < 16; u++) {
            int idx = u*256 + tid;
            int row = idx >> 5;
            int p4  = (idx & 31) << 2;
            uint32_t off = row*272 + p4*2;
            uint4 dq = *(const uint4*)(qs + (size_t)row*HWSZ + p4);
            uint2 qh = { (dq.x & 0xffffu) | (dq.y << 16), (dq.z & 0xffffu) | (dq.w << 16) };
            uint2 ql = { (dq.x >> 16) | (dq.y & 0xffff0000u), (dq.z >> 16) | (dq.w & 0xffff0000u) };
            *(uint2*)(smc + SQh + off) = qh;
            *(uint2*)(smc + SQl + off) = ql;
            uint4 dk = *(const uint4*)(ks + (size_t)row*HWSZ + p4);
            uint2 kh = { (dk.x & 0xffffu) | (dk.y << 16), (dk.z & 0xffffu) | (dk.w << 16) };
            uint2 kl = { (dk.x >> 16) | (dk.y & 0xffff0000u), (dk.z >> 16) | (dk.w & 0xffff0000u) };
            *(uint2*)(smc + SKh + off) = kh;
            *(uint2*)(smc + SKl + off) = kl;
        }
        const uint32_t* vs = vp + voff;
        #pragma unroll
        for (int u = 0; u < 8; u++) {
            int idx = u*256 + tid;
            int row = idx >> 5;
            int p4  = (idx & 31) << 2;
            uint32_t off = row*272 + p4*2;
            uint4 dv = *(const uint4*)(vs + (size_t)row*HWSZ + p4);
            uint2 vh = { (dv.x & 0xffffu) | (dv.y << 16), (dv.z & 0xffffu) | (dv.w << 16) };
            uint2 vl = { (dv.x >> 16) | (dv.y & 0xffff0000u), (dv.z >> 16) | (dv.w & 0xffff0000u) };
            *(uint2*)(smc + SVh + off) = vh;
            *(uint2*)(smc + SVl + off) = vl;
        }
    }
    __syncthreads();

    int wm = wid >> 1, wn = wid & 1;
    int m0 = wm * 32, n0 = wn * 64;
    float acc[2][8][4];
    #pragma unroll
    for (int mi = 0; mi < 2; mi++)
        #pragma unroll
        for (int nj = 0; nj < 8; nj++)
            #pragma unroll
            for (int c = 0; c < 4; c++) acc[mi][nj][c] = 0.f;

    int a_r = ((lane >> 4) << 3) + (lane & 7);
    int a_c = ((lane >> 3) & 1) << 3;
    int b_r = (((lane >> 3) & 1) << 3) + (lane & 7);
    int b_c = (lane >> 4) << 3;
    uint32_t aoff0 = (uint32_t)(a_r*272 + (m0 + a_c)*2);
    uint32_t boff0 = (uint32_t)(b_r*272 + (n0 + b_c)*2);

    #pragma unroll
    for (int ks = 0; ks < 8; ks++) {
        uint32_t kb = (uint32_t)(ks * 16 * 272);
        uint32_t aqh[2][4], aql[2][4];
        #pragma unroll
        for (int mi = 0; mi < 2; mi++) {
            uint32_t ad = sb + kb + aoff0 + mi*32;
            LDSM_X4_T(aqh[mi][0], aqh[mi][1], aqh[mi][2], aqh[mi][3], ad + SQh);
            LDSM_X4_T(aql[mi][0], aql[mi][1], aql[mi][2], aql[mi][3], ad + SQl);
        }
        uint32_t bkh[4][4], bkl[4][4];
        #pragma unroll
        for (int p = 0; p < 4; p++) {
            uint32_t bd = sb + kb + boff0 + p*32;
            LDSM_X4_T(bkh[p][0], bkh[p][1], bkh[p][2], bkh[p][3], bd + SKh);
            LDSM_X4_T(bkl[p][0], bkl[p][1], bkl[p][2], bkl[p][3], bd + SKl);
        }
        #pragma unroll
        for (int mi = 0; mi < 2; mi++)
            #pragma unroll
            for (int nj = 0; nj < 8; nj++) {
                int p = nj >> 1, q2 = (nj & 1) * 2;
                mma16816(acc[mi][nj], aqh[mi], bkh[p][q2], bkh[p][q2+1]);
                mma16816(acc[mi][nj], aqh[mi], bkl[p][q2], bkl[p][q2+1]);
                mma16816(acc[mi][nj], aql[mi], bkh[p][q2], bkh[p][q2+1]);
            }
    }
    #pragma unroll
    for (int mi = 0; mi < 2; mi++)
        #pragma unroll
        for (int nj = 0; nj < 8; nj++)
            #pragma unroll
            for (int c = 0; c < 4; c++) acc[mi][nj][c] *= SCALE;

    #pragma unroll
    for (int mi = 0; mi < 2; mi++) {
        int rA = m0 + mi*16 + g, rB = rA + 8;
        float mA = -1e30f, mB = -1e30f;
        #pragma unroll
        for (int nj = 0; nj < 8; nj++) {
            mA = fmaxf(mA, fmaxf(acc[mi][nj][0], acc[mi][nj][1]));
            mB = fmaxf(mB, fmaxf(acc[mi][nj][2], acc[mi][nj][3]));
        }
        mA = fmaxf(mA, __shfl_xor_sync(0xffffffffu, mA, 1));
        mA = fmaxf(mA, __shfl_xor_sync(0xffffffffu, mA, 2));
        mB = fmaxf(mB, __shfl_xor_sync(0xffffffffu, mB, 1));
        mB = fmaxf(mB, __shfl_xor_sync(0xffffffffu, mB, 2));
        if (t == 0) { redM[rA*2 + wn] = mA; redM[rB*2 + wn] = mB; }
    }
    __syncthreads();
    #pragma unroll
    for (int mi = 0; mi < 2; mi++) {
        int rA = m0 + mi*16 + g, rB = rA + 8;
        float mxA = fmaxf(redM[rA*2], redM[rA*2+1]);
        float mxB = fmaxf(redM[rB*2], redM[rB*2+1]);
        float sA = 0.f, sB = 0.f;
        #pragma unroll
        for (int nj = 0; nj < 8; nj++) {
            float e0 = __expf(acc[mi][nj][0] - mxA);
            float e1 = __expf(acc[mi][nj][1] - mxA);
            float e2 = __expf(acc[mi][nj][2] - mxB);
            float e3 = __expf(acc[mi][nj][3] - mxB);
            acc[mi][nj][0] = e0; acc[mi][nj][1] = e1;
            acc[mi][nj][2] = e2; acc[mi][nj][3] = e3;
            sA += e0 + e1; sB += e2 + e3;
        }
        sA += __shfl_xor_sync(0xffffffffu, sA, 1);
        sA += __shfl_xor_sync(0xffffffffu, sA, 2);
        sB += __shfl_xor_sync(0xffffffffu, sB, 1);
        sB += __shfl_xor_sync(0xffffffffu, sB, 2);
        if (t == 0) { redS[rA*2 + wn] = sA; redS[rB*2 + wn] = sB; }
    }
    __syncthreads();

    #pragma unroll
    for (int mi = 0; mi < 2; mi++) {
        int rA = m0 + mi*16 + g, rB = rA + 8;
        float iA = 1.0f / (redS[rA*2] + redS[rA*2+1]);
        float iB = 1.0f / (redS[rB*2] + redS[rB*2+1]);
        #pragma unroll
        for (int nj = 0; nj < 8; nj++) {
            int j0 = n0 + nj*8 + t*2;
            uint32_t h, l;
            split2(acc[mi][nj][0]*iA, acc[mi][nj][1]*iA, h, l);
            *(uint32_t*)(smc + SQh + rA*272 + j0*2) = h;
            *(uint32_t*)(smc + SQl + rA*272 + j0*2) = l;
            split2(acc[mi][nj][2]*iB, acc[mi][nj][3]*iB, h, l);
            *(uint32_t*)(smc + SQh + rB*272 + j0*2) = h;
            *(uint32_t*)(smc + SQl + rB*272 + j0*2) = l;
        }
    }
    __syncthreads();

    int wm2 = wid >> 2, wn2 = wid & 3;
    int c0 = wm2 * 32, i0 = wn2 * 32;
    float oacc[2][4][4];
    #pragma unroll
    for (int mi = 0; mi < 2; mi++)
        #pragma unroll
        for (int nj = 0; nj < 4; nj++)
            #pragma unroll
            for (int c = 0; c < 4; c++) oacc[mi][nj][c] = 0.f;

    int ar2 = (((lane >> 3) & 1) << 3) + (lane & 7);
    int ac2 = (lane >> 4) << 3;
    int br2 = ((lane >> 4) << 3) + (lane & 7);
    int bc2 = ((lane >> 3) & 1) << 3;

    #pragma unroll
    for (int ks = 0; ks < 8; ks++) {
        int kb = ks * 16;
        uint32_t avh[2][4], avl[2][4];
        #pragma unroll
        for (int mi = 0; mi < 2; mi++) {
            uint32_t ad = sb + (uint32_t)((c0 + mi*16 + ar2)*272 + (kb + ac2)*2);
            LDSM_X4(avh[mi][0], avh[mi][1], avh[mi][2], avh[mi][3], ad + SVh);
            LDSM_X4(avl[mi][0], avl[mi][1], avl[mi][2], avl[mi][3], ad + SVl);
        }
        uint32_t bah[2][4], bal[2][4];
        #pragma unroll
        for (int ib2 = 0; ib2 < 2; ib2++) {
            uint32_t bd = sb + (uint32_t)((i0 + ib2*16 + br2)*272 + (kb + bc2)*2);
            LDSM_X4(bah[ib2][0], bah[ib2][1], bah[ib2][2], bah[ib2][3], bd + SQh);
            LDSM_X4(bal[ib2][0], bal[ib2][1], bal[ib2][2], bal[ib2][3], bd + SQl);
        }
        #pragma unroll
        for (int mi = 0; mi < 2; mi++)
            #pragma unroll
            for (int nj = 0; nj < 4; nj++) {
                int ib2 = nj >> 1, q2 = (nj & 1) * 2;
                mma16816(oacc[mi][nj], avh[mi], bah[ib2][q2], bah[ib2][q2+1]);
                mma16816(oacc[mi][nj], avh[mi], bal[ib2][q2], bal[ib2][q2+1]);
                mma16816(oacc[mi][nj], avl[mi], bah[ib2][q2], bah[ib2][q2+1]);
            }
    }

    #pragma unroll
    for (int mi = 0; mi < 2; mi++) {
        int cA = c0 + mi*16 + g, cB = cA + 8;
        float* oA = out + voff + (size_t)cA * HWSZ;
        float* oB = out + voff + (size_t)cB * HWSZ;
        #pragma unroll
        for (int nj = 0; nj < 4; nj++) {
            int i = i0 + nj*8 + t*2;
            float2 vA = { oacc[mi][nj][0], oacc[mi][nj][1] };
            float2 vB = { oacc[mi][nj][2], oacc[mi][nj][3] };
            *(float2*)(oA + i) = vA;
            *(float2*)(oB + i) = vB;
        }
    }
}

// ---------------- BN stats ----------------
__global__ void bn_stats_kernel(const float* __restrict__ x, const float* __restrict__ w,
                                const float* __restrict__ bb, float* __restrict__ sc) {
    int c = blockIdx.x;
    int tid = threadIdx.x;
    float s = 0.f, sq = 0.f;
    for (int b = 0; b < 4; b++) {
        const float* p = x + ((size_t)b*256 + c) * HWSZ;
        for (int i = tid; i < HWSZ; i += 256) { float vv = p[i]; s += vv; sq += vv*vv; }
    }
    __shared__ float ss[256], ssq[256];
    ss[tid] = s; ssq[tid] = sq; __syncthreads();
    for (int st = 128; st > 0; st >>= 1) {
        if (tid < st) { ss[tid] += ss[tid+st]; ssq[tid] += ssq[tid+st]; }
        __syncthreads();
    }
    if (tid == 0) {
        const float N = 65536.0f;
        float mean = ss[0] / N;
        float var  = ssq[0] / N - mean*mean;
        float scale = w[c] * rsqrtf(var + 1e-5f);
        sc[c]       = scale;
        sc[128 + c] = bb[c] - mean*scale;
    }
}

// ---------------- fused epilogue: out + p0 + p1 in one pass ----------------
__global__ void final_fused_kernel(const float* __restrict__ x, const float* __restrict__ oh,
                                   const float* __restrict__ ow, const float* __restrict__ scH,
                                   const float* __restrict__ scW, const float* __restrict__ gamma,
                                   float* __restrict__ out) {
    int idx = blockIdx.x * 256 + threadIdx.x;   // 4,194,304 float4 units
    int b  = idx >> 20;
    int c  = (idx >> 12) & 255;
    int i4 = (idx & 4095) << 2;
    float gm = gamma[0];

    float4 h4 = *(const float4*)(oh + ((size_t)b*256 + c)*HWSZ + i4);
    float4 w4 = *(const float4*)(ow + ((size_t)b*256 + c)*HWSZ + i4);
    float4 x0 = *(const float4*)(x + ((size_t)b*512 + c)      *HWSZ + i4);
    float4 x1 = *(const float4*)(x + ((size_t)b*512 + c + 256)*HWSZ + i4);

    float4 o0, o1;
    o0.x = gm*fmaxf(h4.x, 0.f) + x0.x;  o0.y = gm*fmaxf(h4.y, 0.f) + x0.y;
    o0.z = gm*fmaxf(h4.z, 0.f) + x0.z;  o0.w = gm*fmaxf(h4.w, 0.f) + x0.w;
    o1.x = gm*fmaxf(w4.x, 0.f) + x1.x;  o1.y = gm*fmaxf(w4.y, 0.f) + x1.y;
    o1.z = gm*fmaxf(w4.z, 0.f) + x1.z;  o1.w = gm*fmaxf(w4.w, 0.f) + x1.w;
    *(float4*)(out + ((size_t)b*512 + c)      *HWSZ + i4) = o0;
    *(float4*)(out + ((size_t)b*512 + c + 256)*HWSZ + i4) = o1;

    if (c < 128) {
        float sH = scH[c], shH = scH[128+c];
        float sW = scW[c], shW = scW[128+c];
        float4 p0, p1;
        p0.x = h4.x*sH + shH; p0.y = h4.y*sH + shH; p0.z = h4.z*sH + shH; p0.w = h4.w*sH + shH;
        p1.x = w4.x*sW + shW; p1.y = w4.y*sW + shW; p1.z = w4.z*sW + shW; p1.w = w4.w*sW + shW;
        *(float4*)(out + 33554432ull + ((size_t)b*128 + c)*HWSZ + i4) = p0;
        *(float4*)(out + 41943040ull + ((size_t)b*128 + c)*HWSZ + i4) = p1;
    }
}

// ---------------- launch ----------------
extern "C" void kernel_launch(void* const* d_in, const int* in_sizes, int n_in,
                              void* d_out, int out_size) {
    const float* x     = (const float*)d_in[0];
    const float* wq    = (const float*)d_in[1];
    const float* bq    = (const float*)d_in[2];
    const float* wk    = (const float*)d_in[3];
    const float* bk    = (const float*)d_in[4];
    const float* wv    = (const float*)d_in[5];
    const float* bv    = (const float*)d_in[6];
    const float* bnh_w = (const float*)d_in[7];
    const float* bnh_b = (const float*)d_in[8];
    const float* bnw_w = (const float*)d_in[9];
    const float* bnw_b = (const float*)d_in[10];
    const float* gamma = (const float*)d_in[11];
    float* out = (float*)d_out;

    uint32_t *qp, *kp, *vp, *qpT, *kpT, *vpT;
    float *oW, *oHT, *oH, *scH, *scW, *bp;
    __nv_bfloat16 *xThi, *xTlo, *wph, *wpl;
    cudaGetSymbolAddress((void**)&qp,   g_qp);
    cudaGetSymbolAddress((void**)&kp,   g_kp);
    cudaGetSymbolAddress((void**)&vp,   g_vp);
    cudaGetSymbolAddress((void**)&qpT,  g_qpT);
    cudaGetSymbolAddress((void**)&kpT,  g_kpT);
    cudaGetSymbolAddress((void**)&vpT,  g_vpT);
    cudaGetSymbolAddress((void**)&oW,   g_outW);
    cudaGetSymbolAddress((void**)&oHT,  g_outHT);
    cudaGetSymbolAddress((void**)&oH,   g_outH);
    cudaGetSymbolAddress((void**)&scH,  g_scH);
    cudaGetSymbolAddress((void**)&scW,  g_scW);
    cudaGetSymbolAddress((void**)&xThi, g_xThi);
    cudaGetSymbolAddress((void**)&xTlo, g_xTlo);
    cudaGetSymbolAddress((void**)&wph,  g_wph);
    cudaGetSymbolAddress((void**)&wpl,  g_wpl);
    cudaGetSymbolAddress((void**)&bp,   g_bp);

    cudaFuncSetAttribute(gemm_kernel, cudaFuncAttributeMaxDynamicSharedMemorySize, GEMM_SMEM);
    cudaFuncSetAttribute(attn_mma_kernel, cudaFuncAttributeMaxDynamicSharedMemorySize, ATT2_SMEM);

    prepw_kernel<<<1280, 256>>>(wq, bq, wk, bk, wv, bv, wph, wpl, bp);
    convx_kernel<<<dim3(512, 8, 8), dim3(32, 8)>>>(x, xThi, xTlo);

    // B-resident fused qkv projection
    gemm_kernel<<<dim3(128, 8), 256, GEMM_SMEM>>>(xThi, xTlo, wph, wpl, bp, qp, kp, vp);

    // W-direction attention (no transposes needed)
    attn_mma_kernel<<<dim3(128,4,4), 256, ATT2_SMEM>>>(qp, kp, vp, oW);
    bn_stats_kernel<<<128, 256>>>(oW, bnw_w, bnw_b, scW);

    // transposes + H-direction attention
    transpose_kernel<<<dim3(16, 2048), dim3(32,8)>>>((const float*)qp, (float*)qpT);
    transpose_kernel<<<dim3(16, 2048), dim3(32,8)>>>((const float*)kp, (float*)kpT);
    transpose_kernel<<<dim3(16, 1024), dim3(32,8)>>>((const float*)vp, (float*)vpT);
    attn_mma_kernel<<<dim3(128,4,4), 256, ATT2_SMEM>>>(qpT, kpT, vpT, oHT);
    transpose_kernel<<<dim3(16, 1024), dim3(32,8)>>>(oHT, oH);
    bn_stats_kernel<<<128, 256>>>(oH, bnh_w, bnh_b, scH);

    // fused epilogue: out + p0 + p1
    final_fused_kernel<<<16384, 256>>>(x, oH, oW, scH, scW, gamma, out);
}

// round 6
// speedup vs baseline: 1.9567x; 1.0242x over previous
#include <cuda_runtime.h>
#include <cuda_bf16.h>
#include <math.h>
#include <stdint.h>

#define HWSZ 16384
#define GEMM_SMEM 205824
#define ATT3_SMEM 108544

// ---------------- scratch ----------------
__device__ uint32_t g_qp [4ull*512*16384];   // packed bf16: hi | lo<<16
__device__ uint32_t g_kp [4ull*512*16384];
__device__ uint32_t g_vp [4ull*256*16384];
__device__ uint32_t g_qpT[4ull*512*16384];
__device__ uint32_t g_kpT[4ull*512*16384];
__device__ uint32_t g_vpT[4ull*256*16384];
__device__ float g_outW [4ull*256*16384];
__device__ float g_outHT[4ull*256*16384];
__device__ float g_outH [4ull*256*16384];
__device__ float g_scH[256];
__device__ float g_scW[256];
__device__ __nv_bfloat16 g_wph[2*640*256];   // [g][m][k]
__device__ __nv_bfloat16 g_wpl[2*640*256];
__device__ float g_bp[2*640];

// ---------------- helpers ----------------
__device__ __forceinline__ uint32_t smem_u32(const void* p) {
    uint32_t a;
    asm("{ .reg .u64 t; cvta.to.shared.u64 t, %1; cvt.u32.u64 %0, t; }" : "=r"(a) : "l"(p));
    return a;
}
#define LDSM_X4(r0, r1, r2, r3, addr) \
    asm volatile("ldmatrix.sync.aligned.m8n8.x4.shared.b16 {%0,%1,%2,%3}, [%4];" \
        : "=r"(r0), "=r"(r1), "=r"(r2), "=r"(r3) : "r"(addr))
#define LDSM_X4_T(r0, r1, r2, r3, addr) \
    asm volatile("ldmatrix.sync.aligned.m8n8.x4.trans.shared.b16 {%0,%1,%2,%3}, [%4];" \
        : "=r"(r0), "=r"(r1), "=r"(r2), "=r"(r3) : "r"(addr))
#define CP_ASYNC16(dst, src) \
    asm volatile("cp.async.cg.shared.global [%0], [%1], 16;" :: "r"(dst), "l"(src))
#define CP_COMMIT() asm volatile("cp.async.commit_group;" ::: "memory")
#define CP_WAIT0()  asm volatile("cp.async.wait_group 0;" ::: "memory")

__device__ __forceinline__ void mma16816(float* d, const uint32_t* a,
                                         uint32_t b0, uint32_t b1) {
    asm volatile(
        "mma.sync.aligned.m16n8k16.row.col.f32.bf16.bf16.f32 "
        "{%0,%1,%2,%3}, {%4,%5,%6,%7}, {%8,%9}, {%0,%1,%2,%3};"
        : "+f"(d[0]), "+f"(d[1]), "+f"(d[2]), "+f"(d[3])
        : "r"(a[0]), "r"(a[1]), "r"(a[2]), "r"(a[3]), "r"(b0), "r"(b1));
}
__device__ __forceinline__ uint32_t pack_bf(float f) {
    __nv_bfloat16 h = __float2bfloat16(f);
    __nv_bfloat16 l = __float2bfloat16(f - __bfloat162float(h));
    return (uint32_t)__bfloat16_as_ushort(h) | ((uint32_t)__bfloat16_as_ushort(l) << 16);
}
__device__ __forceinline__ void split2(float a, float b, uint32_t& h, uint32_t& l) {
    __nv_bfloat16 ha = __float2bfloat16(a);
    __nv_bfloat16 hb = __float2bfloat16(b);
    __nv_bfloat16 la = __float2bfloat16(a - __bfloat162float(ha));
    __nv_bfloat16 lb = __float2bfloat16(b - __bfloat162float(hb));
    h = (uint32_t)__bfloat16_as_ushort(ha) | ((uint32_t)__bfloat16_as_ushort(hb) << 16);
    l = (uint32_t)__bfloat16_as_ushort(la) | ((uint32_t)__bfloat16_as_ushort(lb) << 16);
}
// f32x4 -> hi uint2 + lo uint2
__device__ __forceinline__ void cvt4(float4 v, uint2& h, uint2& l) {
    uint32_t h0, l0, h1, l1;
    split2(v.x, v.y, h0, l0);
    split2(v.z, v.w, h1, l1);
    h.x = h0; h.y = h1; l.x = l0; l.y = l1;
}
// blocked SW128 atom tile address (A operand)
__device__ __forceinline__ uint32_t tile_addr(uint32_t tbase, int row, int kc) {
    uint32_t byte = (uint32_t)(((row >> 3) + ((kc >> 6) << 4)) * 1024
                  + ((row & 7) << 7)
                  + ((((kc & 63) << 1)) ^ ((row & 7) << 4)));
    return tbase + byte;
}

// ---------------- weight pack + bf16 split ----------------
__global__ void prepw_kernel(const float* __restrict__ wq, const float* __restrict__ bq,
                             const float* __restrict__ wk, const float* __restrict__ bk,
                             const float* __restrict__ wv, const float* __restrict__ bv,
                             __nv_bfloat16* __restrict__ wph, __nv_bfloat16* __restrict__ wpl,
                             float* __restrict__ bp) {
    int idx = blockIdx.x * 256 + threadIdx.x;
    int g = idx / 163840;
    int r = idx - g * 163840;
    int m = r >> 8, k = r & 255;
    const float* src; float bias;
    if (m < 256)       { src = wq + (size_t)(g*256 + m)       * 256; bias = bq[g*256 + m]; }
    else if (m < 512)  { src = wk + (size_t)(g*256 + (m-256)) * 256; bias = bk[g*256 + m-256]; }
    else               { src = wv + (size_t)(g*128 + (m-512)) * 256; bias = bv[g*128 + m-512]; }
    float w = src[k];
    __nv_bfloat16 h = __float2bfloat16(w);
    wph[idx] = h;
    wpl[idx] = __float2bfloat16(w - __bfloat162float(h));
    if (k == 0) bp[g*640 + m] = bias;
}

// ---- stage [128 x 128] bf16 A half-tile into blocked SW128 layout, async ----
__device__ __forceinline__ void stage_a128(uint32_t smb, const __nv_bfloat16* __restrict__ src,
                                           int tid) {
    #pragma unroll
    for (int it = 0; it < 8; it++) {
        int idx = it * 256 + tid;
        int row = idx >> 4;
        int k8 = (idx & 15) << 3;
        uint32_t byte = (uint32_t)(((row >> 3) + ((k8 >> 6) << 4)) * 1024
                      + ((row & 7) << 7)
                      + (((k8 & 63) << 1) ^ ((row & 7) << 4)));
        CP_ASYNC16(smb + byte, src + (size_t)row * 256 + k8);
    }
}

// ---------------- fused qkv projection GEMM (x read + convert inline) -------------
// CTA: 640 channels x 128 pixels. B = x tile converted to hi/lo bf16 [k=256][pix=128],
// consumed via ldmatrix.trans. A = W streamed in k-halves (blocked SW128).
__global__ __launch_bounds__(256, 1)
void gemm_kernel(const float* __restrict__ x,
                 const __nv_bfloat16* __restrict__ wph, const __nv_bfloat16* __restrict__ wpl,
                 const float* __restrict__ bp,
                 uint32_t* __restrict__ qb, uint32_t* __restrict__ kb2, uint32_t* __restrict__ vb) {
    extern __shared__ char sm[];
    uint32_t sbase = smem_u32(sm);
    const uint32_t AH = 1024, AL = 33792, BH = 66560, BL = 136192;
    int tid = threadIdx.x;
    int lane = tid & 31, wid = tid >> 5;
    int pbase = blockIdx.x * 128;
    int z = blockIdx.y;                 // b*2+g
    int b = z >> 1, g = z & 1;

    // stage B: read x [k=256][pix=128] f32, convert to hi/lo bf16, stride 272B rows
    {
        const float* xb = x + ((size_t)b*512 + g*256) * HWSZ + pbase;
        #pragma unroll 4
        for (int it = 0; it < 32; it++) {
            int idx = it * 256 + tid;
            int row = idx >> 5;
            int p4  = (idx & 31) << 2;
            float4 v = *(const float4*)(xb + (size_t)row * HWSZ + p4);
            uint2 h, l;
            cvt4(v, h, l);
            uint32_t off = (uint32_t)(row * 272 + p4 * 2);
            *(uint2*)(sm + BH + off) = h;
            *(uint2*)(sm + BL + off) = l;
        }
    }

    int mb = (wid & 1) * 64;
    int nb = (wid >> 1) * 32;
    int laneA_row = ((lane >> 3) & 1) * 8 + (lane & 7);
    int laneA_k8  = (lane >> 4) * 8;
    int bt_r = (((lane >> 3) & 1) << 3) + (lane & 7);   // k within 16
    int bt_c = (lane >> 4) << 3;                        // pix offset

    #pragma unroll 1
    for (int mt = 0; mt < 5; mt++) {
        const __nv_bfloat16* ah = wph + ((size_t)g*640 + mt*128) * 256;
        const __nv_bfloat16* al = wpl + ((size_t)g*640 + mt*128) * 256;

        float d[4][4][4];
        #pragma unroll
        for (int mi = 0; mi < 4; mi++)
            #pragma unroll
            for (int nj = 0; nj < 4; nj++)
                #pragma unroll
                for (int c = 0; c < 4; c++) d[mi][nj][c] = 0.f;

        #pragma unroll 1
        for (int kh = 0; kh < 2; kh++) {
            __syncthreads();
            stage_a128(sbase + AH, ah + kh*128, tid);
            stage_a128(sbase + AL, al + kh*128, tid);
            CP_COMMIT(); CP_WAIT0();
            __syncthreads();

            #pragma unroll 2
            for (int ks = 0; ks < 8; ks++) {
                int kl = ks * 16;
                int kk = kh * 128 + kl;
                uint32_t aH[4][4], aL[4][4];
                #pragma unroll
                for (int mi = 0; mi < 4; mi++) {
                    LDSM_X4(aH[mi][0], aH[mi][1], aH[mi][2], aH[mi][3],
                            tile_addr(sbase + AH, mb + mi*16 + laneA_row, kl + laneA_k8));
                    LDSM_X4(aL[mi][0], aL[mi][1], aL[mi][2], aL[mi][3],
                            tile_addr(sbase + AL, mb + mi*16 + laneA_row, kl + laneA_k8));
                }
                uint32_t bHf[2][4], bLf[2][4];
                #pragma unroll
                for (int p = 0; p < 2; p++) {
                    uint32_t bd = sbase + (uint32_t)((kk + bt_r)*272 + (nb + p*16 + bt_c)*2);
                    LDSM_X4_T(bHf[p][0], bHf[p][1], bHf[p][2], bHf[p][3], bd + BH);
                    LDSM_X4_T(bLf[p][0], bLf[p][1], bLf[p][2], bLf[p][3], bd + BL);
                }
                #pragma unroll
                for (int mi = 0; mi < 4; mi++)
                    #pragma unroll
                    for (int nj = 0; nj < 4; nj++) {
                        int p = nj >> 1, q = (nj & 1) * 2;
                        mma16816(d[mi][nj], aH[mi], bHf[p][q], bHf[p][q+1]);
                        mma16816(d[mi][nj], aH[mi], bLf[p][q], bLf[p][q+1]);
                        mma16816(d[mi][nj], aL[mi], bHf[p][q], bHf[p][q+1]);
                    }
            }
        }

        uint32_t* dst; size_t ch0;
        if (mt < 2)      { dst = qb;  ch0 = (size_t)b*512 + g*256 + mt*128; }
        else if (mt < 4) { dst = kb2; ch0 = (size_t)b*512 + g*256 + (mt-2)*128; }
        else             { dst = vb;  ch0 = (size_t)b*256 + g*128; }
        #pragma unroll
        for (int mi = 0; mi < 4; mi++) {
            int r0 = mb + mi*16 + (lane >> 2);
            float bias0 = bp[g*640 + mt*128 + r0];
            float bias1 = bp[g*640 + mt*128 + r0 + 8];
            uint32_t* row0 = dst + (ch0 + r0)     * HWSZ + pbase;
            uint32_t* row1 = dst + (ch0 + r0 + 8) * HWSZ + pbase;
            #pragma unroll
            for (int nj = 0; nj < 4; nj++) {
                int col = nb + nj*8 + (lane & 3)*2;
                uint2 o0 = { pack_bf(d[mi][nj][0] + bias0), pack_bf(d[mi][nj][1] + bias0) };
                uint2 o1 = { pack_bf(d[mi][nj][2] + bias1), pack_bf(d[mi][nj][3] + bias1) };
                *(uint2*)(row0 + col) = o0;
                *(uint2*)(row1 + col) = o1;
            }
        }
    }
}

// ---------------- 128x128 transpose per slice (4-byte elements) ----------------
__global__ void transpose_kernel(const float* __restrict__ in, float* __restrict__ out) {
    __shared__ float t[32][33];
    int tile = blockIdx.x;
    int bx = (tile & 3) * 32, by = (tile >> 2) * 32;
    const float* ip = in  + (size_t)blockIdx.y * HWSZ;
    float*       op = out + (size_t)blockIdx.y * HWSZ;
    int x = threadIdx.x, y = threadIdx.y;
    #pragma unroll
    for (int r = 0; r < 32; r += 8)
        t[y+r][x] = ip[(size_t)(by + y + r)*128 + bx + x];
    __syncthreads();
    #pragma unroll
    for (int r = 0; r < 32; r += 8)
        op[(size_t)(bx + y + r)*128 + by + x] = t[x][y+r];
}

// ---------------- axial attention: 64 queries/CTA, 2 CTAs/SM ----------------
// Q [c=128][i=64] (stride 144B), K [c=128][j=128] (stride 272B);
// after phase1, V [c=64][j=128] loads into K slots; A [i=64][j=128] into Q slots.
__global__ __launch_bounds__(256, 2)
void attn_mma_kernel(const uint32_t* __restrict__ qp, const uint32_t* __restrict__ kp,
                     const uint32_t* __restrict__ vp, float* __restrict__ out) {
    extern __shared__ char smc[];
    uint32_t sb = smem_u32(smc);
    const uint32_t SQh = 0, SQl = 18432, SKh = 36864, SKl = 71680;
    float* redM = (float*)(smc + 106496);   // [64][4]
    float* redS = (float*)(smc + 107520);   // [64][4]
    const float SCALE = 0.08838834764831845f;

    int r = blockIdx.x;
    int n = blockIdx.y >> 1, half = blockIdx.y & 1;
    int b = blockIdx.z;
    size_t qoff = ((size_t)(b*4 + n) * 128) * HWSZ + (size_t)r * 128;
    size_t voff = ((size_t)(b*4 + n) *  64) * HWSZ + (size_t)r * 128;
    int ibq = half * 64;
    int tid = threadIdx.x;
    int lane = tid & 31, wid = tid >> 5;
    int g = lane >> 2, t = lane & 3;

    // ---- stage Q (64 cols) and K (full) ----
    {
        const uint32_t* qs = qp + qoff + ibq;
        #pragma unroll
        for (int u = 0; u < 8; u++) {
            int idx = u*256 + tid;
            int row = idx >> 4, p4 = (idx & 15) << 2;
            uint32_t off = (uint32_t)(row*144 + p4*2);
            uint4 dq = *(const uint4*)(qs + (size_t)row*HWSZ + p4);
            uint2 qh = { (dq.x & 0xffffu) | (dq.y << 16), (dq.z & 0xffffu) | (dq.w << 16) };
            uint2 ql = { (dq.x >> 16) | (dq.y & 0xffff0000u), (dq.z >> 16) | (dq.w & 0xffff0000u) };
            *(uint2*)(smc + SQh + off) = qh;
            *(uint2*)(smc + SQl + off) = ql;
        }
        const uint32_t* ks2 = kp + qoff;
        #pragma unroll
        for (int u = 0; u < 16; u++) {
            int idx = u*256 + tid;
            int row = idx >> 5, p4 = (idx & 31) << 2;
            uint32_t off = (uint32_t)(row*272 + p4*2);
            uint4 dk = *(const uint4*)(ks2 + (size_t)row*HWSZ + p4);
            uint2 kh = { (dk.x & 0xffffu) | (dk.y << 16), (dk.z & 0xffffu) | (dk.w << 16) };
            uint2 kl = { (dk.x >> 16) | (dk.y & 0xffff0000u), (dk.z >> 16) | (dk.w & 0xffff0000u) };
            *(uint2*)(smc + SKh + off) = kh;
            *(uint2*)(smc + SKl + off) = kl;
        }
    }
    __syncthreads();

    // ---- phase 1: S[i 64][j 128] = Q^T K ----
    int wm = wid >> 2, wn = wid & 3;
    int m0 = wm * 32, n0 = wn * 32;
    float acc[2][4][4];
    #pragma unroll
    for (int mi = 0; mi < 2; mi++)
        #pragma unroll
        for (int nj = 0; nj < 4; nj++)
            #pragma unroll
            for (int c = 0; c < 4; c++) acc[mi][nj][c] = 0.f;

    int a_r = ((lane >> 4) << 3) + (lane & 7);
    int a_c = ((lane >> 3) & 1) << 3;
    int b_r = (((lane >> 3) & 1) << 3) + (lane & 7);
    int b_c = (lane >> 4) << 3;
    uint32_t aoff0 = (uint32_t)(a_r*144 + (m0 + a_c)*2);
    uint32_t boff0 = (uint32_t)(b_r*272 + (n0 + b_c)*2);

    #pragma unroll
    for (int ks = 0; ks < 8; ks++) {
        uint32_t kq = (uint32_t)(ks * 16 * 144);
        uint32_t kk2 = (uint32_t)(ks * 16 * 272);
        uint32_t aqh[2][4], aql[2][4];
        #pragma unroll
        for (int mi = 0; mi < 2; mi++) {
            uint32_t ad = sb + kq + aoff0 + mi*32;
            LDSM_X4_T(aqh[mi][0], aqh[mi][1], aqh[mi][2], aqh[mi][3], ad + SQh);
            LDSM_X4_T(aql[mi][0], aql[mi][1], aql[mi][2], aql[mi][3], ad + SQl);
        }
        uint32_t bkh[2][4], bkl[2][4];
        #pragma unroll
        for (int p = 0; p < 2; p++) {
            uint32_t bd = sb + kk2 + boff0 + p*32;
            LDSM_X4_T(bkh[p][0], bkh[p][1], bkh[p][2], bkh[p][3], bd + SKh);
            LDSM_X4_T(bkl[p][0], bkl[p][1], bkl[p][2], bkl[p][3], bd + SKl);
        }
        #pragma unroll
        for (int mi = 0; mi < 2; mi++)
            #pragma unroll
            for (int nj = 0; nj < 4; nj++) {
                int p = nj >> 1, q2 = (nj & 1) * 2;
                mma16816(acc[mi][nj], aqh[mi], bkh[p][q2], bkh[p][q2+1]);
                mma16816(acc[mi][nj], aqh[mi], bkl[p][q2], bkl[p][q2+1]);
                mma16816(acc[mi][nj], aql[mi], bkh[p][q2], bkh[p][q2+1]);
            }
    }
    #pragma unroll
    for (int mi = 0; mi < 2; mi++)
        #pragma unroll
        for (int nj = 0; nj < 4; nj++)
            #pragma unroll
            for (int c = 0; c < 4; c++) acc[mi][nj][c] *= SCALE;

    // ---- softmax over j (4-warp reduce per row) ----
    #pragma unroll
    for (int mi = 0; mi < 2; mi++) {
        int rA = m0 + mi*16 + g, rB = rA + 8;
        float mA = -1e30f, mB = -1e30f;
        #pragma unroll
        for (int nj = 0; nj < 4; nj++) {
            mA = fmaxf(mA, fmaxf(acc[mi][nj][0], acc[mi][nj][1]));
            mB = fmaxf(mB, fmaxf(acc[mi][nj][2], acc[mi][nj][3]));
        }
        mA = fmaxf(mA, __shfl_xor_sync(0xffffffffu, mA, 1));
        mA = fmaxf(mA, __shfl_xor_sync(0xffffffffu, mA, 2));
        mB = fmaxf(mB, __shfl_xor_sync(0xffffffffu, mB, 1));
        mB = fmaxf(mB, __shfl_xor_sync(0xffffffffu, mB, 2));
        if (t == 0) { redM[rA*4 + wn] = mA; redM[rB*4 + wn] = mB; }
    }
    __syncthreads();
    #pragma unroll
    for (int mi = 0; mi < 2; mi++) {
        int rA = m0 + mi*16 + g, rB = rA + 8;
        float mxA = fmaxf(fmaxf(redM[rA*4], redM[rA*4+1]), fmaxf(redM[rA*4+2], redM[rA*4+3]));
        float mxB = fmaxf(fmaxf(redM[rB*4], redM[rB*4+1]), fmaxf(redM[rB*4+2], redM[rB*4+3]));
        float sA = 0.f, sB = 0.f;
        #pragma unroll
        for (int nj = 0; nj < 4; nj++) {
            float e0 = __expf(acc[mi][nj][0] - mxA);
            float e1 = __expf(acc[mi][nj][1] - mxA);
            float e2 = __expf(acc[mi][nj][2] - mxB);
            float e3 = __expf(acc[mi][nj][3] - mxB);
            acc[mi][nj][0] = e0; acc[mi][nj][1] = e1;
            acc[mi][nj][2] = e2; acc[mi][nj][3] = e3;
            sA += e0 + e1; sB += e2 + e3;
        }
        sA += __shfl_xor_sync(0xffffffffu, sA, 1);
        sA += __shfl_xor_sync(0xffffffffu, sA, 2);
        sB += __shfl_xor_sync(0xffffffffu, sB, 1);
        sB += __shfl_xor_sync(0xffffffffu, sB, 2);
        if (t == 0) { redS[rA*4 + wn] = sA; redS[rB*4 + wn] = sB; }
    }
    __syncthreads();

    // ---- write normalized A hi/lo into Q slots, layout [i][j] stride 272 ----
    #pragma unroll
    for (int mi = 0; mi < 2; mi++) {
        int rA = m0 + mi*16 + g, rB = rA + 8;
        float iA = 1.0f / (redS[rA*4] + redS[rA*4+1] + redS[rA*4+2] + redS[rA*4+3]);
        float iB = 1.0f / (redS[rB*4] + redS[rB*4+1] + redS[rB*4+2] + redS[rB*4+3]);
        #pragma unroll
        for (int nj = 0; nj < 4; nj++) {
            int j0 = n0 + nj*8 + t*2;
            uint32_t h, l;
            split2(acc[mi][nj][0]*iA, acc[mi][nj][1]*iA, h, l);
            *(uint32_t*)(smc + SQh + rA*272 + j0*2) = h;
            *(uint32_t*)(smc + SQl + rA*272 + j0*2) = l;
            split2(acc[mi][nj][2]*iB, acc[mi][nj][3]*iB, h, l);
            *(uint32_t*)(smc + SQh + rB*272 + j0*2) = h;
            *(uint32_t*)(smc + SQl + rB*272 + j0*2) = l;
        }
    }
    __syncthreads();

    // ---- stage V into K slots (K dead after phase1) ----
    {
        const uint32_t* vs = vp + voff;
        #pragma unroll
        for (int u = 0; u < 8; u++) {
            int idx = u*256 + tid;
            int row = idx >> 5, p4 = (idx & 31) << 2;
            uint32_t off = (uint32_t)(row*272 + p4*2);
            uint4 dv = *(const uint4*)(vs + (size_t)row*HWSZ + p4);
            uint2 vh = { (dv.x & 0xffffu) | (dv.y << 16), (dv.z & 0xffffu) | (dv.w << 16) };
            uint2 vl = { (dv.x >> 16) | (dv.y & 0xffff0000u), (dv.z >> 16) | (dv.w & 0xffff0000u) };
            *(uint2*)(smc + SKh + off) = vh;
            *(uint2*)(smc + SKl + off) = vl;
        }
    }
    __syncthreads();

    // ---- phase 2: O[c 64][i 64] = V * A^T ----
    int c0 = (wid & 3) * 16, i0 = (wid >> 2) * 32;
    float oacc[4][4];
    #pragma unroll
    for (int nj = 0; nj < 4; nj++)
        #pragma unroll
        for (int c = 0; c < 4; c++) oacc[nj][c] = 0.f;

    int ar2 = (((lane >> 3) & 1) << 3) + (lane & 7);
    int ac2 = (lane >> 4) << 3;
    int br2 = ((lane >> 4) << 3) + (lane & 7);
    int bc2 = ((lane >> 3) & 1) << 3;

    #pragma unroll
    for (int ks = 0; ks < 8; ks++) {
        int kb = ks * 16;
        uint32_t avh[4], avl[4];
        {
            uint32_t ad = sb + (uint32_t)((c0 + ar2)*272 + (kb + ac2)*2);
            LDSM_X4(avh[0], avh[1], avh[2], avh[3], ad + SKh);
            LDSM_X4(avl[0], avl[1], avl[2], avl[3], ad + SKl);
        }
        uint32_t bah[2][4], bal[2][4];
        #pragma unroll
        for (int ib2 = 0; ib2 < 2; ib2++) {
            uint32_t bd = sb + (uint32_t)((i0 + ib2*16 + br2)*272 + (kb + bc2)*2);
            LDSM_X4(bah[ib2][0], bah[ib2][1], bah[ib2][2], bah[ib2][3], bd + SQh);
            LDSM_X4(bal[ib2][0], bal[ib2][1], bal[ib2][2], bal[ib2][3], bd + SQl);
        }
        #pragma unroll
        for (int nj = 0; nj < 4; nj++) {
            int ib2 = nj >> 1, q2 = (nj & 1) * 2;
            mma16816(oacc[nj], avh, bah[ib2][q2], bah[ib2][q2+1]);
            mma16816(oacc[nj], avh, bal[ib2][q2], bal[ib2][q2+1]);
            mma16816(oacc[nj], avl, bah[ib2][q2], bah[ib2][q2+1]);
        }
    }

    // ---- store O ----
    {
        int cA = c0 + g, cB = cA + 8;
        float* oA = out + voff + (size_t)cA * HWSZ + ibq;
        float* oB = out + voff + (size_t)cB * HWSZ + ibq;
        #pragma unroll
        for (int nj = 0; nj < 4; nj++) {
            int i = i0 + nj*8 + t*2;
            float2 vA = { oacc[nj][0], oacc[nj][1] };
            float2 vB = { oacc[nj][2], oacc[nj][3] };
            *(float2*)(oA + i) = vA;
            *(float2*)(oB + i) = vB;
        }
    }
}

// ---------------- BN stats ----------------
__global__ void bn_stats_kernel(const float* __restrict__ x, const float* __restrict__ w,
                                const float* __restrict__ bb, float* __restrict__ sc) {
    int c = blockIdx.x;
    int tid = threadIdx.x;
    float s = 0.f, sq = 0.f;
    for (int b = 0; b < 4; b++) {
        const float* p = x + ((size_t)b*256 + c) * HWSZ;
        for (int i = tid; i < HWSZ; i += 256) { float vv = p[i]; s += vv; sq += vv*vv; }
    }
    __shared__ float ss[256], ssq[256];
    ss[tid] = s; ssq[tid] = sq; __syncthreads();
    for (int st = 128; st > 0; st >>= 1) {
        if (tid < st) { ss[tid] += ss[tid+st]; ssq[tid] += ssq[tid+st]; }
        __syncthreads();
    }
    if (tid == 0) {
        const float N = 65536.0f;
        float mean = ss[0] / N;
        float var  = ssq[0] / N - mean*mean;
        float scale = w[c] * rsqrtf(var + 1e-5f);
        sc[c]       = scale;
        sc[128 + c] = bb[c] - mean*scale;
    }
}

// ---------------- fused epilogue ----------------
__global__ void final_fused_kernel(const float* __restrict__ x, const float* __restrict__ oh,
                                   const float* __restrict__ ow, const float* __restrict__ scH,
                                   const float* __restrict__ scW, const float* __restrict__ gamma,
                                   float* __restrict__ out) {
    int idx = blockIdx.x * 256 + threadIdx.x;
    int b  = idx >> 20;
    int c  = (idx >> 12) & 255;
    int i4 = (idx & 4095) << 2;
    float gm = gamma[0];

    float4 h4 = *(const float4*)(oh + ((size_t)b*256 + c)*HWSZ + i4);
    float4 w4 = *(const float4*)(ow + ((size_t)b*256 + c)*HWSZ + i4);
    float4 x0 = *(const float4*)(x + ((size_t)b*512 + c)      *HWSZ + i4);
    float4 x1 = *(const float4*)(x + ((size_t)b*512 + c + 256)*HWSZ + i4);

    float4 o0, o1;
    o0.x = gm*fmaxf(h4.x, 0.f) + x0.x;  o0.y = gm*fmaxf(h4.y, 0.f) + x0.y;
    o0.z = gm*fmaxf(h4.z, 0.f) + x0.z;  o0.w = gm*fmaxf(h4.w, 0.f) + x0.w;
    o1.x = gm*fmaxf(w4.x, 0.f) + x1.x;  o1.y = gm*fmaxf(w4.y, 0.f) + x1.y;
    o1.z = gm*fmaxf(w4.z, 0.f) + x1.z;  o1.w = gm*fmaxf(w4.w, 0.f) + x1.w;
    *(float4*)(out + ((size_t)b*512 + c)      *HWSZ + i4) = o0;
    *(float4*)(out + ((size_t)b*512 + c + 256)*HWSZ + i4) = o1;

    if (c < 128) {
        float sH = scH[c], shH = scH[128+c];
        float sW = scW[c], shW = scW[128+c];
        float4 p0, p1;
        p0.x = h4.x*sH + shH; p0.y = h4.y*sH + shH; p0.z = h4.z*sH + shH; p0.w = h4.w*sH + shH;
        p1.x = w4.x*sW + shW; p1.y = w4.y*sW + shW; p1.z = w4.z*sW + shW; p1.w = w4.w*sW + shW;
        *(float4*)(out + 33554432ull + ((size_t)b*128 + c)*HWSZ + i4) = p0;
        *(float4*)(out + 41943040ull + ((size_t)b*128 + c)*HWSZ + i4) = p1;
    }
}

// ---------------- launch ----------------
extern "C" void kernel_launch(void* const* d_in, const int* in_sizes, int n_in,
                              void* d_out, int out_size) {
    const float* x     = (const float*)d_in[0];
    const float* wq    = (const float*)d_in[1];
    const float* bq    = (const float*)d_in[2];
    const float* wk    = (const float*)d_in[3];
    const float* bk    = (const float*)d_in[4];
    const float* wv    = (const float*)d_in[5];
    const float* bv    = (const float*)d_in[6];
    const float* bnh_w = (const float*)d_in[7];
    const float* bnh_b = (const float*)d_in[8];
    const float* bnw_w = (const float*)d_in[9];
    const float* bnw_b = (const float*)d_in[10];
    const float* gamma = (const float*)d_in[11];
    float* out = (float*)d_out;

    uint32_t *qp, *kp, *vp, *qpT, *kpT, *vpT;
    float *oW, *oHT, *oH, *scH, *scW, *bp;
    __nv_bfloat16 *wph, *wpl;
    cudaGetSymbolAddress((void**)&qp,   g_qp);
    cudaGetSymbolAddress((void**)&kp,   g_kp);
    cudaGetSymbolAddress((void**)&vp,   g_vp);
    cudaGetSymbolAddress((void**)&qpT,  g_qpT);
    cudaGetSymbolAddress((void**)&kpT,  g_kpT);
    cudaGetSymbolAddress((void**)&vpT,  g_vpT);
    cudaGetSymbolAddress((void**)&oW,   g_outW);
    cudaGetSymbolAddress((void**)&oHT,  g_outHT);
    cudaGetSymbolAddress((void**)&oH,   g_outH);
    cudaGetSymbolAddress((void**)&scH,  g_scH);
    cudaGetSymbolAddress((void**)&scW,  g_scW);
    cudaGetSymbolAddress((void**)&wph,  g_wph);
    cudaGetSymbolAddress((void**)&wpl,  g_wpl);
    cudaGetSymbolAddress((void**)&bp,   g_bp);

    cudaFuncSetAttribute(gemm_kernel, cudaFuncAttributeMaxDynamicSharedMemorySize, GEMM_SMEM);
    cudaFuncSetAttribute(attn_mma_kernel, cudaFuncAttributeMaxDynamicSharedMemorySize, ATT3_SMEM);

    prepw_kernel<<<1280, 256>>>(wq, bq, wk, bk, wv, bv, wph, wpl, bp);
    gemm_kernel<<<dim3(128, 8), 256, GEMM_SMEM>>>(x, wph, wpl, bp, qp, kp, vp);

    transpose_kernel<<<dim3(16, 2048), dim3(32,8)>>>((const float*)qp, (float*)qpT);
    // #4: W-direction attention (profiled launch)
    attn_mma_kernel<<<dim3(128, 8, 4), 256, ATT3_SMEM>>>(qp, kp, vp, oW);
    transpose_kernel<<<dim3(16, 2048), dim3(32,8)>>>((const float*)kp, (float*)kpT);
    transpose_kernel<<<dim3(16, 1024), dim3(32,8)>>>((const float*)vp, (float*)vpT);
    attn_mma_kernel<<<dim3(128, 8, 4), 256, ATT3_SMEM>>>(qpT, kpT, vpT, oHT);
    transpose_kernel<<<dim3(16, 1024), dim3(32,8)>>>(oHT, oH);

    bn_stats_kernel<<<128, 256>>>(oW, bnw_w, bnw_b, scW);
    bn_stats_kernel<<<128, 256>>>(oH, bnh_w, bnh_b, scH);

    final_fused_kernel<<<16384, 256>>>(x, oH, oW, scH, scW, gamma, out);
}

// round 7
// speedup vs baseline: 1.9876x; 1.0158x over previous
#include <cuda_runtime.h>
#include <cuda_bf16.h>
#include <math.h>
#include <stdint.h>

#define HWSZ 16384
#define GEMM_SMEM 205824
#define ATT3_SMEM 108544

// ---------------- scratch ----------------
__device__ uint32_t g_qp [4ull*512*16384];   // packed bf16: hi | lo<<16
__device__ uint32_t g_kp [4ull*512*16384];
__device__ uint32_t g_vp [4ull*256*16384];
__device__ uint32_t g_qpT[4ull*512*16384];
__device__ uint32_t g_kpT[4ull*512*16384];
__device__ uint32_t g_vpT[4ull*256*16384];
__device__ float g_outW [4ull*256*16384];
__device__ float g_outHT[4ull*256*16384];
__device__ float g_outH [4ull*256*16384];
__device__ float g_scH[256];
__device__ float g_scW[256];
__device__ float g_bnsW[512];   // [0..255]=sum, [256..511]=sumsq
__device__ float g_bnsH[512];
__device__ __nv_bfloat16 g_wph[2*640*256];   // [g][m][k]
__device__ __nv_bfloat16 g_wpl[2*640*256];
__device__ float g_bp[2*640];

// ---------------- helpers ----------------
__device__ __forceinline__ uint32_t smem_u32(const void* p) {
    uint32_t a;
    asm("{ .reg .u64 t; cvta.to.shared.u64 t, %1; cvt.u32.u64 %0, t; }" : "=r"(a) : "l"(p));
    return a;
}
#define LDSM_X4(r0, r1, r2, r3, addr) \
    asm volatile("ldmatrix.sync.aligned.m8n8.x4.shared.b16 {%0,%1,%2,%3}, [%4];" \
        : "=r"(r0), "=r"(r1), "=r"(r2), "=r"(r3) : "r"(addr))
#define LDSM_X4_T(r0, r1, r2, r3, addr) \
    asm volatile("ldmatrix.sync.aligned.m8n8.x4.trans.shared.b16 {%0,%1,%2,%3}, [%4];" \
        : "=r"(r0), "=r"(r1), "=r"(r2), "=r"(r3) : "r"(addr))
#define CP_ASYNC16(dst, src) \
    asm volatile("cp.async.cg.shared.global [%0], [%1], 16;" :: "r"(dst), "l"(src))
#define CP_COMMIT() asm volatile("cp.async.commit_group;" ::: "memory")
#define CP_WAIT0()  asm volatile("cp.async.wait_group 0;" ::: "memory")

__device__ __forceinline__ void mma16816(float* d, const uint32_t* a,
                                         uint32_t b0, uint32_t b1) {
    asm volatile(
        "mma.sync.aligned.m16n8k16.row.col.f32.bf16.bf16.f32 "
        "{%0,%1,%2,%3}, {%4,%5,%6,%7}, {%8,%9}, {%0,%1,%2,%3};"
        : "+f"(d[0]), "+f"(d[1]), "+f"(d[2]), "+f"(d[3])
        : "r"(a[0]), "r"(a[1]), "r"(a[2]), "r"(a[3]), "r"(b0), "r"(b1));
}
__device__ __forceinline__ uint32_t pack_bf(float f) {
    __nv_bfloat16 h = __float2bfloat16(f);
    __nv_bfloat16 l = __float2bfloat16(f - __bfloat162float(h));
    return (uint32_t)__bfloat16_as_ushort(h) | ((uint32_t)__bfloat16_as_ushort(l) << 16);
}
__device__ __forceinline__ void split2(float a, float b, uint32_t& h, uint32_t& l) {
    __nv_bfloat16 ha = __float2bfloat16(a);
    __nv_bfloat16 hb = __float2bfloat16(b);
    __nv_bfloat16 la = __float2bfloat16(a - __bfloat162float(ha));
    __nv_bfloat16 lb = __float2bfloat16(b - __bfloat162float(hb));
    h = (uint32_t)__bfloat16_as_ushort(ha) | ((uint32_t)__bfloat16_as_ushort(hb) << 16);
    l = (uint32_t)__bfloat16_as_ushort(la) | ((uint32_t)__bfloat16_as_ushort(lb) << 16);
}
__device__ __forceinline__ void cvt4(float4 v, uint2& h, uint2& l) {
    uint32_t h0, l0, h1, l1;
    split2(v.x, v.y, h0, l0);
    split2(v.z, v.w, h1, l1);
    h.x = h0; h.y = h1; l.x = l0; l.y = l1;
}
// blocked SW128 atom tile address (A operand)
__device__ __forceinline__ uint32_t tile_addr(uint32_t tbase, int row, int kc) {
    uint32_t byte = (uint32_t)(((row >> 3) + ((kc >> 6) << 4)) * 1024
                  + ((row & 7) << 7)
                  + ((((kc & 63) << 1)) ^ ((row & 7) << 4)));
    return tbase + byte;
}
// transpose-staging buffer word address (conflict-free both phases)
__device__ __forceinline__ uint32_t t_word(int ch, int p) {
    return (uint32_t)(ch * 128 + (p ^ ((ch & 7) << 1) ^ (((p >> 5) & 3) << 3)));
}

// ---------------- weight pack + bf16 split ----------------
__global__ void prepw_kernel(const float* __restrict__ wq, const float* __restrict__ bq,
                             const float* __restrict__ wk, const float* __restrict__ bk,
                             const float* __restrict__ wv, const float* __restrict__ bv,
                             __nv_bfloat16* __restrict__ wph, __nv_bfloat16* __restrict__ wpl,
                             float* __restrict__ bp) {
    int idx = blockIdx.x * 256 + threadIdx.x;
    int g = idx / 163840;
    int r = idx - g * 163840;
    int m = r >> 8, k = r & 255;
    const float* src; float bias;
    if (m < 256)       { src = wq + (size_t)(g*256 + m)       * 256; bias = bq[g*256 + m]; }
    else if (m < 512)  { src = wk + (size_t)(g*256 + (m-256)) * 256; bias = bk[g*256 + m-256]; }
    else               { src = wv + (size_t)(g*128 + (m-512)) * 256; bias = bv[g*128 + m-512]; }
    float w = src[k];
    __nv_bfloat16 h = __float2bfloat16(w);
    wph[idx] = h;
    wpl[idx] = __float2bfloat16(w - __bfloat162float(h));
    if (k == 0) bp[g*640 + m] = bias;
}

// ---- stage [128 x 128] bf16 A half-tile into blocked SW128 layout, async ----
__device__ __forceinline__ void stage_a128(uint32_t smb, const __nv_bfloat16* __restrict__ src,
                                           int tid) {
    #pragma unroll
    for (int it = 0; it < 8; it++) {
        int idx = it * 256 + tid;
        int row = idx >> 4;
        int k8 = (idx & 15) << 3;
        uint32_t byte = (uint32_t)(((row >> 3) + ((k8 >> 6) << 4)) * 1024
                      + ((row & 7) << 7)
                      + (((k8 & 63) << 1) ^ ((row & 7) << 4)));
        CP_ASYNC16(smb + byte, src + (size_t)row * 256 + k8);
    }
}

// ---------------- fused qkv projection GEMM with dual-layout epilogue -------------
// CTA: 640 channels x one 16h x 8w pixel patch. Writes normal AND transposed copies.
__global__ __launch_bounds__(256, 1)
void gemm_kernel(const float* __restrict__ x,
                 const __nv_bfloat16* __restrict__ wph, const __nv_bfloat16* __restrict__ wpl,
                 const float* __restrict__ bp,
                 uint32_t* __restrict__ qb, uint32_t* __restrict__ kb2, uint32_t* __restrict__ vb,
                 uint32_t* __restrict__ qbT, uint32_t* __restrict__ kbT, uint32_t* __restrict__ vbT) {
    extern __shared__ char sm[];
    uint32_t sbase = smem_u32(sm);
    const uint32_t AH = 1024, AL = 33792, BH = 66560, BL = 136192, T0 = 1024;
    int tid = threadIdx.x;
    int lane = tid & 31, wid = tid >> 5;
    int tileIdx = blockIdx.x;
    int h0 = (tileIdx >> 4) << 4;       // 8 h-tiles of 16
    int w0 = (tileIdx & 15) << 3;       // 16 w-tiles of 8
    int pix0 = h0 * 128 + w0;
    int z = blockIdx.y;                 // b*2+g
    int b = z >> 1, g = z & 1;

    // stage B: x patch [k=256][16h x 8w] f32 -> hi/lo bf16, rows stride 272B
    {
        const float* xb = x + ((size_t)b*512 + g*256) * HWSZ + pix0;
        #pragma unroll 4
        for (int it = 0; it < 32; it++) {
            int idx = it * 256 + tid;
            int row = idx >> 5;
            int sub = idx & 31;
            int hh = sub >> 1, ww4 = (sub & 1) << 2;
            float4 v = *(const float4*)(xb + (size_t)row * HWSZ + hh*128 + ww4);
            uint2 h, l;
            cvt4(v, h, l);
            uint32_t off = (uint32_t)(row * 272 + (hh*8 + ww4) * 2);
            *(uint2*)(sm + BH + off) = h;
            *(uint2*)(sm + BL + off) = l;
        }
    }

    int mb = (wid & 1) * 64;
    int nb = (wid >> 1) * 32;
    int laneA_row = ((lane >> 3) & 1) * 8 + (lane & 7);
    int laneA_k8  = (lane >> 4) * 8;
    int bt_r = (((lane >> 3) & 1) << 3) + (lane & 7);
    int bt_c = (lane >> 4) << 3;

    #pragma unroll 1
    for (int mt = 0; mt < 5; mt++) {
        const __nv_bfloat16* ah = wph + ((size_t)g*640 + mt*128) * 256;
        const __nv_bfloat16* al = wpl + ((size_t)g*640 + mt*128) * 256;

        float d[4][4][4];
        #pragma unroll
        for (int mi = 0; mi < 4; mi++)
            #pragma unroll
            for (int nj = 0; nj < 4; nj++)
                #pragma unroll
                for (int c = 0; c < 4; c++) d[mi][nj][c] = 0.f;

        #pragma unroll 1
        for (int kh = 0; kh < 2; kh++) {
            __syncthreads();            // A/T region free before overwrite
            stage_a128(sbase + AH, ah + kh*128, tid);
            stage_a128(sbase + AL, al + kh*128, tid);
            CP_COMMIT(); CP_WAIT0();
            __syncthreads();

            #pragma unroll 2
            for (int ks = 0; ks < 8; ks++) {
                int kl = ks * 16;
                int kk = kh * 128 + kl;
                uint32_t aH[4][4], aL[4][4];
                #pragma unroll
                for (int mi = 0; mi < 4; mi++) {
                    LDSM_X4(aH[mi][0], aH[mi][1], aH[mi][2], aH[mi][3],
                            tile_addr(sbase + AH, mb + mi*16 + laneA_row, kl + laneA_k8));
                    LDSM_X4(aL[mi][0], aL[mi][1], aL[mi][2], aL[mi][3],
                            tile_addr(sbase + AL, mb + mi*16 + laneA_row, kl + laneA_k8));
                }
                uint32_t bHf[2][4], bLf[2][4];
                #pragma unroll
                for (int p = 0; p < 2; p++) {
                    uint32_t bd = sbase + (uint32_t)((kk + bt_r)*272 + (nb + p*16 + bt_c)*2);
                    LDSM_X4_T(bHf[p][0], bHf[p][1], bHf[p][2], bHf[p][3], bd + BH);
                    LDSM_X4_T(bLf[p][0], bLf[p][1], bLf[p][2], bLf[p][3], bd + BL);
                }
                #pragma unroll
                for (int mi = 0; mi < 4; mi++)
                    #pragma unroll
                    for (int nj = 0; nj < 4; nj++) {
                        int p = nj >> 1, q = (nj & 1) * 2;
                        mma16816(d[mi][nj], aH[mi], bHf[p][q], bHf[p][q+1]);
                        mma16816(d[mi][nj], aH[mi], bLf[p][q], bLf[p][q+1]);
                        mma16816(d[mi][nj], aL[mi], bHf[p][q], bHf[p][q+1]);
                    }
            }
        }

        uint32_t *dst, *dstT; size_t ch0;
        if (mt < 2)      { dst = qb;  dstT = qbT; ch0 = (size_t)b*512 + g*256 + mt*128; }
        else if (mt < 4) { dst = kb2; dstT = kbT; ch0 = (size_t)b*512 + g*256 + (mt-2)*128; }
        else             { dst = vb;  dstT = vbT; ch0 = (size_t)b*256 + g*128; }

        __syncthreads();    // all LDSM on A done; T region safe to overwrite
        // pack results; store normal layout + T staging buffer
        #pragma unroll
        for (int mi = 0; mi < 4; mi++) {
            int r0 = mb + mi*16 + (lane >> 2);
            float bias0 = bp[g*640 + mt*128 + r0];
            float bias1 = bp[g*640 + mt*128 + r0 + 8];
            #pragma unroll
            for (int nj = 0; nj < 4; nj++) {
                int col = nb + nj*8 + (lane & 3)*2;
                int hh = col >> 3, ww = col & 7;
                uint2 o0 = { pack_bf(d[mi][nj][0] + bias0), pack_bf(d[mi][nj][1] + bias0) };
                uint2 o1 = { pack_bf(d[mi][nj][2] + bias1), pack_bf(d[mi][nj][3] + bias1) };
                *(uint2*)(sm + T0 + 4*t_word(r0,     col)) = o0;
                *(uint2*)(sm + T0 + 4*t_word(r0 + 8, col)) = o1;
                *(uint2*)(dst + (ch0 + r0)     * HWSZ + pix0 + hh*128 + ww) = o0;
                *(uint2*)(dst + (ch0 + r0 + 8) * HWSZ + pix0 + hh*128 + ww) = o1;
            }
        }
        __syncthreads();
        // pass 2: coalesced transposed stores (runs of 16 h)
        #pragma unroll
        for (int it2 = 0; it2 < 16; it2++) {
            int chl = it2*8 + (wid);
            int hh4 = lane & 3, ww = (lane >> 2) & 7;
            const uint32_t* Tb = (const uint32_t*)(sm + T0);
            uint4 val;
            val.x = Tb[t_word(chl, (hh4*4 + 0)*8 + ww)];
            val.y = Tb[t_word(chl, (hh4*4 + 1)*8 + ww)];
            val.z = Tb[t_word(chl, (hh4*4 + 2)*8 + ww)];
            val.w = Tb[t_word(chl, (hh4*4 + 3)*8 + ww)];
            *(uint4*)(dstT + (ch0 + chl) * HWSZ + (size_t)(w0 + ww)*128 + h0 + hh4*4) = val;
        }
    }
}

// ---------------- 128x128 transpose per slice (oHT -> oH only) ----------------
__global__ void transpose_kernel(const float* __restrict__ in, float* __restrict__ out) {
    __shared__ float t[32][33];
    int tile = blockIdx.x;
    int bx = (tile & 3) * 32, by = (tile >> 2) * 32;
    const float* ip = in  + (size_t)blockIdx.y * HWSZ;
    float*       op = out + (size_t)blockIdx.y * HWSZ;
    int x = threadIdx.x, y = threadIdx.y;
    #pragma unroll
    for (int r = 0; r < 32; r += 8)
        t[y+r][x] = ip[(size_t)(by + y + r)*128 + bx + x];
    __syncthreads();
    #pragma unroll
    for (int r = 0; r < 32; r += 8)
        op[(size_t)(bx + y + r)*128 + by + x] = t[x][y+r];
}

// ---------------- axial attention: 64 queries/CTA, 2 CTAs/SM, fused BN sums --------
__global__ __launch_bounds__(256, 2)
void attn_mma_kernel(const uint32_t* __restrict__ qp, const uint32_t* __restrict__ kp,
                     const uint32_t* __restrict__ vp, float* __restrict__ out,
                     float* __restrict__ bns) {
    extern __shared__ char smc[];
    uint32_t sb = smem_u32(smc);
    const uint32_t SQh = 0, SQl = 18432, SKh = 36864, SKl = 71680;
    float* redM = (float*)(smc + 106496);
    float* redS = (float*)(smc + 107520);
    const float SCALE = 0.08838834764831845f;

    int r = blockIdx.x;
    int n = blockIdx.y >> 1, half = blockIdx.y & 1;
    int b = blockIdx.z;
    size_t qoff = ((size_t)(b*4 + n) * 128) * HWSZ + (size_t)r * 128;
    size_t voff = ((size_t)(b*4 + n) *  64) * HWSZ + (size_t)r * 128;
    int ibq = half * 64;
    int tid = threadIdx.x;
    int lane = tid & 31, wid = tid >> 5;
    int g = lane >> 2, t = lane & 3;

    {
        const uint32_t* qs = qp + qoff + ibq;
        #pragma unroll
        for (int u = 0; u < 8; u++) {
            int idx = u*256 + tid;
            int row = idx >> 4, p4 = (idx & 15) << 2;
            uint32_t off = (uint32_t)(row*144 + p4*2);
            uint4 dq = *(const uint4*)(qs + (size_t)row*HWSZ + p4);
            uint2 qh = { (dq.x & 0xffffu) | (dq.y << 16), (dq.z & 0xffffu) | (dq.w << 16) };
            uint2 ql = { (dq.x >> 16) | (dq.y & 0xffff0000u), (dq.z >> 16) | (dq.w & 0xffff0000u) };
            *(uint2*)(smc + SQh + off) = qh;
            *(uint2*)(smc + SQl + off) = ql;
        }
        const uint32_t* ks2 = kp + qoff;
        #pragma unroll
        for (int u = 0; u < 16; u++) {
            int idx = u*256 + tid;
            int row = idx >> 5, p4 = (idx & 31) << 2;
            uint32_t off = (uint32_t)(row*272 + p4*2);
            uint4 dk = *(const uint4*)(ks2 + (size_t)row*HWSZ + p4);
            uint2 kh = { (dk.x & 0xffffu) | (dk.y << 16), (dk.z & 0xffffu) | (dk.w << 16) };
            uint2 kl = { (dk.x >> 16) | (dk.y & 0xffff0000u), (dk.z >> 16) | (dk.w & 0xffff0000u) };
            *(uint2*)(smc + SKh + off) = kh;
            *(uint2*)(smc + SKl + off) = kl;
        }
    }
    __syncthreads();

    int wm = wid >> 2, wn = wid & 3;
    int m0 = wm * 32, n0 = wn * 32;
    float acc[2][4][4];
    #pragma unroll
    for (int mi = 0; mi < 2; mi++)
        #pragma unroll
        for (int nj = 0; nj < 4; nj++)
            #pragma unroll
            for (int c = 0; c < 4; c++) acc[mi][nj][c] = 0.f;

    int a_r = ((lane >> 4) << 3) + (lane & 7);
    int a_c = ((lane >> 3) & 1) << 3;
    int b_r = (((lane >> 3) & 1) << 3) + (lane & 7);
    int b_c = (lane >> 4) << 3;
    uint32_t aoff0 = (uint32_t)(a_r*144 + (m0 + a_c)*2);
    uint32_t boff0 = (uint32_t)(b_r*272 + (n0 + b_c)*2);

    #pragma unroll
    for (int ks = 0; ks < 8; ks++) {
        uint32_t kq = (uint32_t)(ks * 16 * 144);
        uint32_t kk2 = (uint32_t)(ks * 16 * 272);
        uint32_t aqh[2][4], aql[2][4];
        #pragma unroll
        for (int mi = 0; mi < 2; mi++) {
            uint32_t ad = sb + kq + aoff0 + mi*32;
            LDSM_X4_T(aqh[mi][0], aqh[mi][1], aqh[mi][2], aqh[mi][3], ad + SQh);
            LDSM_X4_T(aql[mi][0], aql[mi][1], aql[mi][2], aql[mi][3], ad + SQl);
        }
        uint32_t bkh[2][4], bkl[2][4];
        #pragma unroll
        for (int p = 0; p < 2; p++) {
            uint32_t bd = sb + kk2 + boff0 + p*32;
            LDSM_X4_T(bkh[p][0], bkh[p][1], bkh[p][2], bkh[p][3], bd + SKh);
            LDSM_X4_T(bkl[p][0], bkl[p][1], bkl[p][2], bkl[p][3], bd + SKl);
        }
        #pragma unroll
        for (int mi = 0; mi < 2; mi++)
            #pragma unroll
            for (int nj = 0; nj < 4; nj++) {
                int p = nj >> 1, q2 = (nj & 1) * 2;
                mma16816(acc[mi][nj], aqh[mi], bkh[p][q2], bkh[p][q2+1]);
                mma16816(acc[mi][nj], aqh[mi], bkl[p][q2], bkl[p][q2+1]);
                mma16816(acc[mi][nj], aql[mi], bkh[p][q2], bkh[p][q2+1]);
            }
    }
    #pragma unroll
    for (int mi = 0; mi < 2; mi++)
        #pragma unroll
        for (int nj = 0; nj < 4; nj++)
            #pragma unroll
            for (int c = 0; c < 4; c++) acc[mi][nj][c] *= SCALE;

    #pragma unroll
    for (int mi = 0; mi < 2; mi++) {
        int rA = m0 + mi*16 + g, rB = rA + 8;
        float mA = -1e30f, mB = -1e30f;
        #pragma unroll
        for (int nj = 0; nj < 4; nj++) {
            mA = fmaxf(mA, fmaxf(acc[mi][nj][0], acc[mi][nj][1]));
            mB = fmaxf(mB, fmaxf(acc[mi][nj][2], acc[mi][nj][3]));
        }
        mA = fmaxf(mA, __shfl_xor_sync(0xffffffffu, mA, 1));
        mA = fmaxf(mA, __shfl_xor_sync(0xffffffffu, mA, 2));
        mB = fmaxf(mB, __shfl_xor_sync(0xffffffffu, mB, 1));
        mB = fmaxf(mB, __shfl_xor_sync(0xffffffffu, mB, 2));
        if (t == 0) { redM[rA*4 + wn] = mA; redM[rB*4 + wn] = mB; }
    }
    __syncthreads();
    #pragma unroll
    for (int mi = 0; mi < 2; mi++) {
        int rA = m0 + mi*16 + g, rB = rA + 8;
        float mxA = fmaxf(fmaxf(redM[rA*4], redM[rA*4+1]), fmaxf(redM[rA*4+2], redM[rA*4+3]));
        float mxB = fmaxf(fmaxf(redM[rB*4], redM[rB*4+1]), fmaxf(redM[rB*4+2], redM[rB*4+3]));
        float sA = 0.f, sB = 0.f;
        #pragma unroll
        for (int nj = 0; nj < 4; nj++) {
            float e0 = __expf(acc[mi][nj][0] - mxA);
            float e1 = __expf(acc[mi][nj][1] - mxA);
            float e2 = __expf(acc[mi][nj][2] - mxB);
            float e3 = __expf(acc[mi][nj][3] - mxB);
            acc[mi][nj][0] = e0; acc[mi][nj][1] = e1;
            acc[mi][nj][2] = e2; acc[mi][nj][3] = e3;
            sA += e0 + e1; sB += e2 + e3;
        }
        sA += __shfl_xor_sync(0xffffffffu, sA, 1);
        sA += __shfl_xor_sync(0xffffffffu, sA, 2);
        sB += __shfl_xor_sync(0xffffffffu, sB, 1);
        sB += __shfl_xor_sync(0xffffffffu, sB, 2);
        if (t == 0) { redS[rA*4 + wn] = sA; redS[rB*4 + wn] = sB; }
    }
    __syncthreads();

    #pragma unroll
    for (int mi = 0; mi < 2; mi++) {
        int rA = m0 + mi*16 + g, rB = rA + 8;
        float iA = 1.0f / (redS[rA*4] + redS[rA*4+1] + redS[rA*4+2] + redS[rA*4+3]);
        float iB = 1.0f / (redS[rB*4] + redS[rB*4+1] + redS[rB*4+2] + redS[rB*4+3]);
        #pragma unroll
        for (int nj = 0; nj < 4; nj++) {
            int j0 = n0 + nj*8 + t*2;
            uint32_t h, l;
            split2(acc[mi][nj][0]*iA, acc[mi][nj][1]*iA, h, l);
            *(uint32_t*)(smc + SQh + rA*272 + j0*2) = h;
            *(uint32_t*)(smc + SQl + rA*272 + j0*2) = l;
            split2(acc[mi][nj][2]*iB, acc[mi][nj][3]*iB, h, l);
            *(uint32_t*)(smc + SQh + rB*272 + j0*2) = h;
            *(uint32_t*)(smc + SQl + rB*272 + j0*2) = l;
        }
    }
    __syncthreads();

    {
        const uint32_t* vs = vp + voff;
        #pragma unroll
        for (int u = 0; u < 8; u++) {
            int idx = u*256 + tid;
            int row = idx >> 5, p4 = (idx & 31) << 2;
            uint32_t off = (uint32_t)(row*272 + p4*2);
            uint4 dv = *(const uint4*)(vs + (size_t)row*HWSZ + p4);
            uint2 vh = { (dv.x & 0xffffu) | (dv.y << 16), (dv.z & 0xffffu) | (dv.w << 16) };
            uint2 vl = { (dv.x >> 16) | (dv.y & 0xffff0000u), (dv.z >> 16) | (dv.w & 0xffff0000u) };
            *(uint2*)(smc + SKh + off) = vh;
            *(uint2*)(smc + SKl + off) = vl;
        }
    }
    __syncthreads();

    int c0 = (wid & 3) * 16, i0 = (wid >> 2) * 32;
    float oacc[4][4];
    #pragma unroll
    for (int nj = 0; nj < 4; nj++)
        #pragma unroll
        for (int c = 0; c < 4; c++) oacc[nj][c] = 0.f;

    int ar2 = (((lane >> 3) & 1) << 3) + (lane & 7);
    int ac2 = (lane >> 4) << 3;
    int br2 = ((lane >> 4) << 3) + (lane & 7);
    int bc2 = ((lane >> 3) & 1) << 3;

    #pragma unroll
    for (int ks = 0; ks < 8; ks++) {
        int kb = ks * 16;
        uint32_t avh[4], avl[4];
        {
            uint32_t ad = sb + (uint32_t)((c0 + ar2)*272 + (kb + ac2)*2);
            LDSM_X4(avh[0], avh[1], avh[2], avh[3], ad + SKh);
            LDSM_X4(avl[0], avl[1], avl[2], avl[3], ad + SKl);
        }
        uint32_t bah[2][4], bal[2][4];
        #pragma unroll
        for (int ib2 = 0; ib2 < 2; ib2++) {
            uint32_t bd = sb + (uint32_t)((i0 + ib2*16 + br2)*272 + (kb + bc2)*2);
            LDSM_X4(bah[ib2][0], bah[ib2][1], bah[ib2][2], bah[ib2][3], bd + SQh);
            LDSM_X4(bal[ib2][0], bal[ib2][1], bal[ib2][2], bal[ib2][3], bd + SQl);
        }
        #pragma unroll
        for (int nj = 0; nj < 4; nj++) {
            int ib2 = nj >> 1, q2 = (nj & 1) * 2;
            mma16816(oacc[nj], avh, bah[ib2][q2], bah[ib2][q2+1]);
            mma16816(oacc[nj], avh, bal[ib2][q2], bal[ib2][q2+1]);
            mma16816(oacc[nj], avl, bah[ib2][q2], bah[ib2][q2+1]);
        }
    }

    {
        int cA = c0 + g, cB = cA + 8;
        float* oA = out + voff + (size_t)cA * HWSZ + ibq;
        float* oB = out + voff + (size_t)cB * HWSZ + ibq;
        #pragma unroll
        for (int nj = 0; nj < 4; nj++) {
            int i = i0 + nj*8 + t*2;
            float2 vA = { oacc[nj][0], oacc[nj][1] };
            float2 vB = { oacc[nj][2], oacc[nj][3] };
            *(float2*)(oA + i) = vA;
            *(float2*)(oB + i) = vB;
        }
    }

    // fused BN partial sums (only channels < 128 are needed -> heads n < 2)
    if (n < 2) {
        float s0 = 0.f, q0 = 0.f, s1 = 0.f, q1 = 0.f;
        #pragma unroll
        for (int nj = 0; nj < 4; nj++) {
            s0 += oacc[nj][0] + oacc[nj][1];
            q0 += oacc[nj][0]*oacc[nj][0] + oacc[nj][1]*oacc[nj][1];
            s1 += oacc[nj][2] + oacc[nj][3];
            q1 += oacc[nj][2]*oacc[nj][2] + oacc[nj][3]*oacc[nj][3];
        }
        s0 += __shfl_xor_sync(0xffffffffu, s0, 1);
        s0 += __shfl_xor_sync(0xffffffffu, s0, 2);
        q0 += __shfl_xor_sync(0xffffffffu, q0, 1);
        q0 += __shfl_xor_sync(0xffffffffu, q0, 2);
        s1 += __shfl_xor_sync(0xffffffffu, s1, 1);
        s1 += __shfl_xor_sync(0xffffffffu, s1, 2);
        q1 += __shfl_xor_sync(0xffffffffu, q1, 1);
        q1 += __shfl_xor_sync(0xffffffffu, q1, 2);
        if (t == 0) {
            int chA = n*64 + c0 + g, chB = chA + 8;
            atomicAdd(&bns[chA], s0);       atomicAdd(&bns[256 + chA], q0);
            atomicAdd(&bns[chB], s1);       atomicAdd(&bns[256 + chB], q1);
        }
    }
}

// ---------------- BN finalize (fold stats into scale/shift) ----------------
__global__ void bn_finalize_kernel(const float* __restrict__ bnsW, const float* __restrict__ bnsH,
                                   const float* __restrict__ bnh_w, const float* __restrict__ bnh_b,
                                   const float* __restrict__ bnw_w, const float* __restrict__ bnw_b,
                                   float* __restrict__ scH, float* __restrict__ scW) {
    int tid = threadIdx.x;
    const float N = 65536.0f;
    if (tid < 128) {
        float mean = bnsW[tid] / N;
        float var  = bnsW[256 + tid] / N - mean*mean;
        float scale = bnw_w[tid] * rsqrtf(var + 1e-5f);
        scW[tid] = scale;
        scW[128 + tid] = bnw_b[tid] - mean*scale;
    } else {
        int c = tid - 128;
        float mean = bnsH[c] / N;
        float var  = bnsH[256 + c] / N - mean*mean;
        float scale = bnh_w[c] * rsqrtf(var + 1e-5f);
        scH[c] = scale;
        scH[128 + c] = bnh_b[c] - mean*scale;
    }
}

// ---------------- fused epilogue ----------------
__global__ void final_fused_kernel(const float* __restrict__ x, const float* __restrict__ oh,
                                   const float* __restrict__ ow, const float* __restrict__ scH,
                                   const float* __restrict__ scW, const float* __restrict__ gamma,
                                   float* __restrict__ out) {
    int idx = blockIdx.x * 256 + threadIdx.x;
    int b  = idx >> 20;
    int c  = (idx >> 12) & 255;
    int i4 = (idx & 4095) << 2;
    float gm = gamma[0];

    float4 h4 = *(const float4*)(oh + ((size_t)b*256 + c)*HWSZ + i4);
    float4 w4 = *(const float4*)(ow + ((size_t)b*256 + c)*HWSZ + i4);
    float4 x0 = *(const float4*)(x + ((size_t)b*512 + c)      *HWSZ + i4);
    float4 x1 = *(const float4*)(x + ((size_t)b*512 + c + 256)*HWSZ + i4);

    float4 o0, o1;
    o0.x = gm*fmaxf(h4.x, 0.f) + x0.x;  o0.y = gm*fmaxf(h4.y, 0.f) + x0.y;
    o0.z = gm*fmaxf(h4.z, 0.f) + x0.z;  o0.w = gm*fmaxf(h4.w, 0.f) + x0.w;
    o1.x = gm*fmaxf(w4.x, 0.f) + x1.x;  o1.y = gm*fmaxf(w4.y, 0.f) + x1.y;
    o1.z = gm*fmaxf(w4.z, 0.f) + x1.z;  o1.w = gm*fmaxf(w4.w, 0.f) + x1.w;
    *(float4*)(out + ((size_t)b*512 + c)      *HWSZ + i4) = o0;
    *(float4*)(out + ((size_t)b*512 + c + 256)*HWSZ + i4) = o1;

    if (c < 128) {
        float sH = scH[c], shH = scH[128+c];
        float sW = scW[c], shW = scW[128+c];
        float4 p0, p1;
        p0.x = h4.x*sH + shH; p0.y = h4.y*sH + shH; p0.z = h4.z*sH + shH; p0.w = h4.w*sH + shH;
        p1.x = w4.x*sW + shW; p1.y = w4.y*sW + shW; p1.z = w4.z*sW + shW; p1.w = w4.w*sW + shW;
        *(float4*)(out + 33554432ull + ((size_t)b*128 + c)*HWSZ + i4) = p0;
        *(float4*)(out + 41943040ull + ((size_t)b*128 + c)*HWSZ + i4) = p1;
    }
}

// ---------------- launch ----------------
extern "C" void kernel_launch(void* const* d_in, const int* in_sizes, int n_in,
                              void* d_out, int out_size) {
    const float* x     = (const float*)d_in[0];
    const float* wq    = (const float*)d_in[1];
    const float* bq    = (const float*)d_in[2];
    const float* wk    = (const float*)d_in[3];
    const float* bk    = (const float*)d_in[4];
    const float* wv    = (const float*)d_in[5];
    const float* bv    = (const float*)d_in[6];
    const float* bnh_w = (const float*)d_in[7];
    const float* bnh_b = (const float*)d_in[8];
    const float* bnw_w = (const float*)d_in[9];
    const float* bnw_b = (const float*)d_in[10];
    const float* gamma = (const float*)d_in[11];
    float* out = (float*)d_out;

    uint32_t *qp, *kp, *vp, *qpT, *kpT, *vpT;
    float *oW, *oHT, *oH, *scH, *scW, *bp, *bnsW, *bnsH;
    __nv_bfloat16 *wph, *wpl;
    cudaGetSymbolAddress((void**)&qp,   g_qp);
    cudaGetSymbolAddress((void**)&kp,   g_kp);
    cudaGetSymbolAddress((void**)&vp,   g_vp);
    cudaGetSymbolAddress((void**)&qpT,  g_qpT);
    cudaGetSymbolAddress((void**)&kpT,  g_kpT);
    cudaGetSymbolAddress((void**)&vpT,  g_vpT);
    cudaGetSymbolAddress((void**)&oW,   g_outW);
    cudaGetSymbolAddress((void**)&oHT,  g_outHT);
    cudaGetSymbolAddress((void**)&oH,   g_outH);
    cudaGetSymbolAddress((void**)&scH,  g_scH);
    cudaGetSymbolAddress((void**)&scW,  g_scW);
    cudaGetSymbolAddress((void**)&bnsW, g_bnsW);
    cudaGetSymbolAddress((void**)&bnsH, g_bnsH);
    cudaGetSymbolAddress((void**)&wph,  g_wph);
    cudaGetSymbolAddress((void**)&wpl,  g_wpl);
    cudaGetSymbolAddress((void**)&bp,   g_bp);

    cudaFuncSetAttribute(gemm_kernel, cudaFuncAttributeMaxDynamicSharedMemorySize, GEMM_SMEM);
    cudaFuncSetAttribute(attn_mma_kernel, cudaFuncAttributeMaxDynamicSharedMemorySize, ATT3_SMEM);

    cudaMemsetAsync(bnsW, 0, 512 * sizeof(float));
    cudaMemsetAsync(bnsH, 0, 512 * sizeof(float));

    prepw_kernel<<<1280, 256>>>(wq, bq, wk, bk, wv, bv, wph, wpl, bp);
    gemm_kernel<<<dim3(128, 8), 256, GEMM_SMEM>>>(x, wph, wpl, bp,
                                                  qp, kp, vp, qpT, kpT, vpT);

    attn_mma_kernel<<<dim3(128, 8, 4), 256, ATT3_SMEM>>>(qp,  kp,  vp,  oW,  bnsW);
    attn_mma_kernel<<<dim3(128, 8, 4), 256, ATT3_SMEM>>>(qpT, kpT, vpT, oHT, bnsH);
    transpose_kernel<<<dim3(16, 1024), dim3(32,8)>>>(oHT, oH);

    bn_finalize_kernel<<<1, 256>>>(bnsW, bnsH, bnh_w, bnh_b, bnw_w, bnw_b, scH, scW);
    final_fused_kernel<<<16384, 256>>>(x, oH, oW, scH, scW, gamma, out);
}

// round 8
// speedup vs baseline: 2.0568x; 1.0349x over previous
#include <cuda_runtime.h>
#include <cuda_bf16.h>
#include <math.h>
#include <stdint.h>

#define HWSZ 16384
#define GEMM_SMEM 205824
#define ATT3_SMEM 108544

// ---------------- scratch ----------------
__device__ uint32_t g_qp [4ull*512*16384];   // packed bf16: hi | lo<<16
__device__ uint32_t g_kp [4ull*512*16384];
__device__ uint32_t g_vp [4ull*256*16384];
__device__ uint32_t g_qpT[4ull*512*16384];
__device__ uint32_t g_kpT[4ull*512*16384];
__device__ uint32_t g_vpT[4ull*256*16384];
__device__ float g_outW [4ull*256*16384];
__device__ float g_outHT[4ull*256*16384];
__device__ float g_outH [4ull*256*16384];
__device__ float g_scH[256];
__device__ float g_scW[256];
__device__ float g_bnsW[512];   // [0..255]=sum, [256..511]=sumsq
__device__ float g_bnsH[512];
__device__ __nv_bfloat16 g_wph[2*640*256];   // [g][m][k]
__device__ __nv_bfloat16 g_wpl[2*640*256];
__device__ float g_bp[2*640];

// ---------------- helpers ----------------
__device__ __forceinline__ uint32_t smem_u32(const void* p) {
    uint32_t a;
    asm("{ .reg .u64 t; cvta.to.shared.u64 t, %1; cvt.u32.u64 %0, t; }" : "=r"(a) : "l"(p));
    return a;
}
#define LDSM_X4(r0, r1, r2, r3, addr) \
    asm volatile("ldmatrix.sync.aligned.m8n8.x4.shared.b16 {%0,%1,%2,%3}, [%4];" \
        : "=r"(r0), "=r"(r1), "=r"(r2), "=r"(r3) : "r"(addr))
#define LDSM_X4_T(r0, r1, r2, r3, addr) \
    asm volatile("ldmatrix.sync.aligned.m8n8.x4.trans.shared.b16 {%0,%1,%2,%3}, [%4];" \
        : "=r"(r0), "=r"(r1), "=r"(r2), "=r"(r3) : "r"(addr))
#define CP_ASYNC16(dst, src) \
    asm volatile("cp.async.cg.shared.global [%0], [%1], 16;" :: "r"(dst), "l"(src))
#define CP_COMMIT() asm volatile("cp.async.commit_group;" ::: "memory")
#define CP_WAIT1()  asm volatile("cp.async.wait_group 1;" ::: "memory")
#define CP_WAIT0()  asm volatile("cp.async.wait_group 0;" ::: "memory")

__device__ __forceinline__ void mma16816(float* d, const uint32_t* a,
                                         uint32_t b0, uint32_t b1) {
    asm volatile(
        "mma.sync.aligned.m16n8k16.row.col.f32.bf16.bf16.f32 "
        "{%0,%1,%2,%3}, {%4,%5,%6,%7}, {%8,%9}, {%0,%1,%2,%3};"
        : "+f"(d[0]), "+f"(d[1]), "+f"(d[2]), "+f"(d[3])
        : "r"(a[0]), "r"(a[1]), "r"(a[2]), "r"(a[3]), "r"(b0), "r"(b1));
}
__device__ __forceinline__ uint32_t pack_bf(float f) {
    __nv_bfloat16 h = __float2bfloat16(f);
    __nv_bfloat16 l = __float2bfloat16(f - __bfloat162float(h));
    return (uint32_t)__bfloat16_as_ushort(h) | ((uint32_t)__bfloat16_as_ushort(l) << 16);
}
__device__ __forceinline__ void split2(float a, float b, uint32_t& h, uint32_t& l) {
    __nv_bfloat16 ha = __float2bfloat16(a);
    __nv_bfloat16 hb = __float2bfloat16(b);
    __nv_bfloat16 la = __float2bfloat16(a - __bfloat162float(ha));
    __nv_bfloat16 lb = __float2bfloat16(b - __bfloat162float(hb));
    h = (uint32_t)__bfloat16_as_ushort(ha) | ((uint32_t)__bfloat16_as_ushort(hb) << 16);
    l = (uint32_t)__bfloat16_as_ushort(la) | ((uint32_t)__bfloat16_as_ushort(lb) << 16);
}
__device__ __forceinline__ void cvt4(float4 v, uint2& h, uint2& l) {
    uint32_t h0, l0, h1, l1;
    split2(v.x, v.y, h0, l0);
    split2(v.z, v.w, h1, l1);
    h.x = h0; h.y = h1; l.x = l0; l.y = l1;
}
// address within a 16KB (128 rows x 64 k) SW128 quarter tile
__device__ __forceinline__ uint32_t t64_addr(uint32_t tbase, int row, int kc) {
    return tbase + (uint32_t)(((row >> 3) << 10) + ((row & 7) << 7)
                 + ((((kc & 63) << 1)) ^ ((row & 7) << 4)));
}

// ---------------- weight pack + bf16 split ----------------
__global__ void prepw_kernel(const float* __restrict__ wq, const float* __restrict__ bq,
                             const float* __restrict__ wk, const float* __restrict__ bk,
                             const float* __restrict__ wv, const float* __restrict__ bv,
                             __nv_bfloat16* __restrict__ wph, __nv_bfloat16* __restrict__ wpl,
                             float* __restrict__ bp) {
    int idx = blockIdx.x * 256 + threadIdx.x;
    int g = idx / 163840;
    int r = idx - g * 163840;
    int m = r >> 8, k = r & 255;
    const float* src; float bias;
    if (m < 256)       { src = wq + (size_t)(g*256 + m)       * 256; bias = bq[g*256 + m]; }
    else if (m < 512)  { src = wk + (size_t)(g*256 + (m-256)) * 256; bias = bk[g*256 + m-256]; }
    else               { src = wv + (size_t)(g*128 + (m-512)) * 256; bias = bv[g*128 + m-512]; }
    float w = src[k];
    __nv_bfloat16 h = __float2bfloat16(w);
    wph[idx] = h;
    wpl[idx] = __float2bfloat16(w - __bfloat162float(h));
    if (k == 0) bp[g*640 + m] = bias;
}

// ---- stage [128 x 64] bf16 A quarter tile into SW128 layout, async ----
__device__ __forceinline__ void stage_a64(uint32_t smb, const __nv_bfloat16* __restrict__ src,
                                          int tid) {
    #pragma unroll
    for (int it = 0; it < 4; it++) {
        int idx = it * 256 + tid;          // 0..1023
        int row = idx >> 3;
        int k8 = (idx & 7) << 3;
        uint32_t byte = (uint32_t)(((row >> 3) << 10) + ((row & 7) << 7)
                       + ((k8 << 1) ^ ((row & 7) << 4)));
        CP_ASYNC16(smb + byte, src + (size_t)row * 256 + k8);
    }
}

// ---------------- fused qkv projection GEMM (B-resident, pipelined A) -------------
// CTA: 640 channels x 128 contiguous pixels. B = x hi/lo resident;
// A = W streamed as 20 k-quarters through 2 ping-pong buffers (cp.async).
__global__ __launch_bounds__(256, 1)
void gemm_kernel(const float* __restrict__ x,
                 const __nv_bfloat16* __restrict__ wph, const __nv_bfloat16* __restrict__ wpl,
                 const float* __restrict__ bp,
                 uint32_t* __restrict__ qb, uint32_t* __restrict__ kb2, uint32_t* __restrict__ vb) {
    extern __shared__ char sm[];
    uint32_t sbase = smem_u32(sm);
    const uint32_t AHb[2] = {1024, 33792};
    const uint32_t ALb[2] = {17408, 50176};
    const uint32_t BH = 66560, BL = 136192;
    int tid = threadIdx.x;
    int lane = tid & 31, wid = tid >> 5;
    int pbase = blockIdx.x * 128;
    int z = blockIdx.y;                 // b*2+g
    int b = z >> 1, g = z & 1;
    const __nv_bfloat16* wbase_h = wph + (size_t)g*640*256;
    const __nv_bfloat16* wbase_l = wpl + (size_t)g*640*256;

    // prefetch A quarter 0
    stage_a64(sbase + AHb[0], wbase_h, tid);
    stage_a64(sbase + ALb[0], wbase_l, tid);
    CP_COMMIT();

    // stage B: x [k=256][128 pix] f32 -> hi/lo bf16, rows stride 272B
    {
        const float* xb = x + ((size_t)b*512 + g*256) * HWSZ + pbase;
        #pragma unroll 4
        for (int it = 0; it < 32; it++) {
            int idx = it * 256 + tid;
            int row = idx >> 5;
            int p4  = (idx & 31) << 2;
            float4 v = *(const float4*)(xb + (size_t)row * HWSZ + p4);
            uint2 h, l;
            cvt4(v, h, l);
            uint32_t off = (uint32_t)(row * 272 + p4 * 2);
            *(uint2*)(sm + BH + off) = h;
            *(uint2*)(sm + BL + off) = l;
        }
    }

    int mb = (wid & 1) * 64;
    int nb = (wid >> 1) * 32;
    int laneA_row = ((lane >> 3) & 1) * 8 + (lane & 7);
    int laneA_k8  = (lane >> 4) * 8;
    int bt_r = (((lane >> 3) & 1) << 3) + (lane & 7);
    int bt_c = (lane >> 4) << 3;

    float d[4][4][4];

    #pragma unroll 1
    for (int q = 0; q < 20; q++) {
        int mt = q >> 2;
        if ((q & 3) == 0) {
            #pragma unroll
            for (int mi = 0; mi < 4; mi++)
                #pragma unroll
                for (int nj = 0; nj < 4; nj++)
                    #pragma unroll
                    for (int c = 0; c < 4; c++) d[mi][nj][c] = 0.f;
        }
        __syncthreads();                // buf[(q+1)&1] free (read finished at q-1)
        if (q < 19) {
            int qq = q + 1;
            size_t aoff = ((size_t)(qq >> 2) * 128) * 256 + (qq & 3) * 64;
            stage_a64(sbase + AHb[qq & 1], wbase_h + aoff, tid);
            stage_a64(sbase + ALb[qq & 1], wbase_l + aoff, tid);
            CP_COMMIT();
            CP_WAIT1();                 // quarter q complete, prefetch pending
        } else {
            CP_WAIT0();
        }
        __syncthreads();

        uint32_t AH = sbase + AHb[q & 1];
        uint32_t AL = sbase + ALb[q & 1];
        int kbase = (q & 3) * 64;       // global k offset for B

        #pragma unroll
        for (int ks = 0; ks < 4; ks++) {
            int kl = ks * 16;
            int kk = kbase + kl;
            uint32_t aH[4][4], aL[4][4];
            #pragma unroll
            for (int mi = 0; mi < 4; mi++) {
                LDSM_X4(aH[mi][0], aH[mi][1], aH[mi][2], aH[mi][3],
                        t64_addr(AH, mb + mi*16 + laneA_row, kl + laneA_k8));
                LDSM_X4(aL[mi][0], aL[mi][1], aL[mi][2], aL[mi][3],
                        t64_addr(AL, mb + mi*16 + laneA_row, kl + laneA_k8));
            }
            uint32_t bHf[2][4], bLf[2][4];
            #pragma unroll
            for (int p = 0; p < 2; p++) {
                uint32_t bd = sbase + (uint32_t)((kk + bt_r)*272 + (nb + p*16 + bt_c)*2);
                LDSM_X4_T(bHf[p][0], bHf[p][1], bHf[p][2], bHf[p][3], bd + BH);
                LDSM_X4_T(bLf[p][0], bLf[p][1], bLf[p][2], bLf[p][3], bd + BL);
            }
            #pragma unroll
            for (int mi = 0; mi < 4; mi++)
                #pragma unroll
                for (int nj = 0; nj < 4; nj++) {
                    int p = nj >> 1, qx = (nj & 1) * 2;
                    mma16816(d[mi][nj], aH[mi], bHf[p][qx], bHf[p][qx+1]);
                    mma16816(d[mi][nj], aH[mi], bLf[p][qx], bLf[p][qx+1]);
                    mma16816(d[mi][nj], aL[mi], bHf[p][qx], bHf[p][qx+1]);
                }
        }

        if ((q & 3) == 3) {
            // epilogue for m-tile mt (registers + global only; prefetch runs behind)
            uint32_t* dst; size_t ch0;
            if (mt < 2)      { dst = qb;  ch0 = (size_t)b*512 + g*256 + mt*128; }
            else if (mt < 4) { dst = kb2; ch0 = (size_t)b*512 + g*256 + (mt-2)*128; }
            else             { dst = vb;  ch0 = (size_t)b*256 + g*128; }
            #pragma unroll
            for (int mi = 0; mi < 4; mi++) {
                int r0 = mb + mi*16 + (lane >> 2);
                float bias0 = bp[g*640 + mt*128 + r0];
                float bias1 = bp[g*640 + mt*128 + r0 + 8];
                uint32_t* row0 = dst + (ch0 + r0)     * HWSZ + pbase;
                uint32_t* row1 = dst + (ch0 + r0 + 8) * HWSZ + pbase;
                #pragma unroll
                for (int nj = 0; nj < 4; nj++) {
                    int col = nb + nj*8 + (lane & 3)*2;
                    uint2 o0 = { pack_bf(d[mi][nj][0] + bias0), pack_bf(d[mi][nj][1] + bias0) };
                    uint2 o1 = { pack_bf(d[mi][nj][2] + bias1), pack_bf(d[mi][nj][3] + bias1) };
                    *(uint2*)(row0 + col) = o0;
                    *(uint2*)(row1 + col) = o1;
                }
            }
        }
    }
}

// ---------------- 128x128 transpose per slice (4-byte elements) ----------------
__global__ void transpose_kernel(const float* __restrict__ in, float* __restrict__ out) {
    __shared__ float t[32][33];
    int tile = blockIdx.x;
    int bx = (tile & 3) * 32, by = (tile >> 2) * 32;
    const float* ip = in  + (size_t)blockIdx.y * HWSZ;
    float*       op = out + (size_t)blockIdx.y * HWSZ;
    int x = threadIdx.x, y = threadIdx.y;
    #pragma unroll
    for (int r = 0; r < 32; r += 8)
        t[y+r][x] = ip[(size_t)(by + y + r)*128 + bx + x];
    __syncthreads();
    #pragma unroll
    for (int r = 0; r < 32; r += 8)
        op[(size_t)(bx + y + r)*128 + by + x] = t[x][y+r];
}

// ---------------- axial attention: 64 queries/CTA, 2 CTAs/SM, fused BN sums --------
__global__ __launch_bounds__(256, 2)
void attn_mma_kernel(const uint32_t* __restrict__ qp, const uint32_t* __restrict__ kp,
                     const uint32_t* __restrict__ vp, float* __restrict__ out,
                     float* __restrict__ bns) {
    extern __shared__ char smc[];
    uint32_t sb = smem_u32(smc);
    const uint32_t SQh = 0, SQl = 18432, SKh = 36864, SKl = 71680;
    float* redM = (float*)(smc + 106496);
    float* redS = (float*)(smc + 107520);
    const float SCALE = 0.08838834764831845f;

    int r = blockIdx.x;
    int n = blockIdx.y >> 1, half = blockIdx.y & 1;
    int b = blockIdx.z;
    size_t qoff = ((size_t)(b*4 + n) * 128) * HWSZ + (size_t)r * 128;
    size_t voff = ((size_t)(b*4 + n) *  64) * HWSZ + (size_t)r * 128;
    int ibq = half * 64;
    int tid = threadIdx.x;
    int lane = tid & 31, wid = tid >> 5;
    int g = lane >> 2, t = lane & 3;

    {
        const uint32_t* qs = qp + qoff + ibq;
        #pragma unroll
        for (int u = 0; u < 8; u++) {
            int idx = u*256 + tid;
            int row = idx >> 4, p4 = (idx & 15) << 2;
            uint32_t off = (uint32_t)(row*144 + p4*2);
            uint4 dq = *(const uint4*)(qs + (size_t)row*HWSZ + p4);
            uint2 qh = { (dq.x & 0xffffu) | (dq.y << 16), (dq.z & 0xffffu) | (dq.w << 16) };
            uint2 ql = { (dq.x >> 16) | (dq.y & 0xffff0000u), (dq.z >> 16) | (dq.w & 0xffff0000u) };
            *(uint2*)(smc + SQh + off) = qh;
            *(uint2*)(smc + SQl + off) = ql;
        }
        const uint32_t* ks2 = kp + qoff;
        #pragma unroll
        for (int u = 0; u < 16; u++) {
            int idx = u*256 + tid;
            int row = idx >> 5, p4 = (idx & 31) << 2;
            uint32_t off = (uint32_t)(row*272 + p4*2);
            uint4 dk = *(const uint4*)(ks2 + (size_t)row*HWSZ + p4);
            uint2 kh = { (dk.x & 0xffffu) | (dk.y << 16), (dk.z & 0xffffu) | (dk.w << 16) };
            uint2 kl = { (dk.x >> 16) | (dk.y & 0xffff0000u), (dk.z >> 16) | (dk.w & 0xffff0000u) };
            *(uint2*)(smc + SKh + off) = kh;
            *(uint2*)(smc + SKl + off) = kl;
        }
    }
    __syncthreads();

    int wm = wid >> 2, wn = wid & 3;
    int m0 = wm * 32, n0 = wn * 32;
    float acc[2][4][4];
    #pragma unroll
    for (int mi = 0; mi < 2; mi++)
        #pragma unroll
        for (int nj = 0; nj < 4; nj++)
            #pragma unroll
            for (int c = 0; c < 4; c++) acc[mi][nj][c] = 0.f;

    int a_r = ((lane >> 4) << 3) + (lane & 7);
    int a_c = ((lane >> 3) & 1) << 3;
    int b_r = (((lane >> 3) & 1) << 3) + (lane & 7);
    int b_c = (lane >> 4) << 3;
    uint32_t aoff0 = (uint32_t)(a_r*144 + (m0 + a_c)*2);
    uint32_t boff0 = (uint32_t)(b_r*272 + (n0 + b_c)*2);

    #pragma unroll
    for (int ks = 0; ks < 8; ks++) {
        uint32_t kq = (uint32_t)(ks * 16 * 144);
        uint32_t kk2 = (uint32_t)(ks * 16 * 272);
        uint32_t aqh[2][4], aql[2][4];
        #pragma unroll
        for (int mi = 0; mi < 2; mi++) {
            uint32_t ad = sb + kq + aoff0 + mi*32;
            LDSM_X4_T(aqh[mi][0], aqh[mi][1], aqh[mi][2], aqh[mi][3], ad + SQh);
            LDSM_X4_T(aql[mi][0], aql[mi][1], aql[mi][2], aql[mi][3], ad + SQl);
        }
        uint32_t bkh[2][4], bkl[2][4];
        #pragma unroll
        for (int p = 0; p < 2; p++) {
            uint32_t bd = sb + kk2 + boff0 + p*32;
            LDSM_X4_T(bkh[p][0], bkh[p][1], bkh[p][2], bkh[p][3], bd + SKh);
            LDSM_X4_T(bkl[p][0], bkl[p][1], bkl[p][2], bkl[p][3], bd + SKl);
        }
        #pragma unroll
        for (int mi = 0; mi < 2; mi++)
            #pragma unroll
            for (int nj = 0; nj < 4; nj++) {
                int p = nj >> 1, q2 = (nj & 1) * 2;
                mma16816(acc[mi][nj], aqh[mi], bkh[p][q2], bkh[p][q2+1]);
                mma16816(acc[mi][nj], aqh[mi], bkl[p][q2], bkl[p][q2+1]);
                mma16816(acc[mi][nj], aql[mi], bkh[p][q2], bkh[p][q2+1]);
            }
    }
    #pragma unroll
    for (int mi = 0; mi < 2; mi++)
        #pragma unroll
        for (int nj = 0; nj < 4; nj++)
            #pragma unroll
            for (int c = 0; c < 4; c++) acc[mi][nj][c] *= SCALE;

    #pragma unroll
    for (int mi = 0; mi < 2; mi++) {
        int rA = m0 + mi*16 + g, rB = rA + 8;
        float mA = -1e30f, mB = -1e30f;
        #pragma unroll
        for (int nj = 0; nj < 4; nj++) {
            mA = fmaxf(mA, fmaxf(acc[mi][nj][0], acc[mi][nj][1]));
            mB = fmaxf(mB, fmaxf(acc[mi][nj][2], acc[mi][nj][3]));
        }
        mA = fmaxf(mA, __shfl_xor_sync(0xffffffffu, mA, 1));
        mA = fmaxf(mA, __shfl_xor_sync(0xffffffffu, mA, 2));
        mB = fmaxf(mB, __shfl_xor_sync(0xffffffffu, mB, 1));
        mB = fmaxf(mB, __shfl_xor_sync(0xffffffffu, mB, 2));
        if (t == 0) { redM[rA*4 + wn] = mA; redM[rB*4 + wn] = mB; }
    }
    __syncthreads();
    #pragma unroll
    for (int mi = 0; mi < 2; mi++) {
        int rA = m0 + mi*16 + g, rB = rA + 8;
        float mxA = fmaxf(fmaxf(redM[rA*4], redM[rA*4+1]), fmaxf(redM[rA*4+2], redM[rA*4+3]));
        float mxB = fmaxf(fmaxf(redM[rB*4], redM[rB*4+1]), fmaxf(redM[rB*4+2], redM[rB*4+3]));
        float sA = 0.f, sB = 0.f;
        #pragma unroll
        for (int nj = 0; nj < 4; nj++) {
            float e0 = __expf(acc[mi][nj][0] - mxA);
            float e1 = __expf(acc[mi][nj][1] - mxA);
            float e2 = __expf(acc[mi][nj][2] - mxB);
            float e3 = __expf(acc[mi][nj][3] - mxB);
            acc[mi][nj][0] = e0; acc[mi][nj][1] = e1;
            acc[mi][nj][2] = e2; acc[mi][nj][3] = e3;
            sA += e0 + e1; sB += e2 + e3;
        }
        sA += __shfl_xor_sync(0xffffffffu, sA, 1);
        sA += __shfl_xor_sync(0xffffffffu, sA, 2);
        sB += __shfl_xor_sync(0xffffffffu, sB, 1);
        sB += __shfl_xor_sync(0xffffffffu, sB, 2);
        if (t == 0) { redS[rA*4 + wn] = sA; redS[rB*4 + wn] = sB; }
    }
    __syncthreads();

    #pragma unroll
    for (int mi = 0; mi < 2; mi++) {
        int rA = m0 + mi*16 + g, rB = rA + 8;
        float iA = 1.0f / (redS[rA*4] + redS[rA*4+1] + redS[rA*4+2] + redS[rA*4+3]);
        float iB = 1.0f / (redS[rB*4] + redS[rB*4+1] + redS[rB*4+2] + redS[rB*4+3]);
        #pragma unroll
        for (int nj = 0; nj < 4; nj++) {
            int j0 = n0 + nj*8 + t*2;
            uint32_t h, l;
            split2(acc[mi][nj][0]*iA, acc[mi][nj][1]*iA, h, l);
            *(uint32_t*)(smc + SQh + rA*272 + j0*2) = h;
            *(uint32_t*)(smc + SQl + rA*272 + j0*2) = l;
            split2(acc[mi][nj][2]*iB, acc[mi][nj][3]*iB, h, l);
            *(uint32_t*)(smc + SQh + rB*272 + j0*2) = h;
            *(uint32_t*)(smc + SQl + rB*272 + j0*2) = l;
        }
    }
    __syncthreads();

    {
        const uint32_t* vs = vp + voff;
        #pragma unroll
        for (int u = 0; u < 8; u++) {
            int idx = u*256 + tid;
            int row = idx >> 5, p4 = (idx & 31) << 2;
            uint32_t off = (uint32_t)(row*272 + p4*2);
            uint4 dv = *(const uint4*)(vs + (size_t)row*HWSZ + p4);
            uint2 vh = { (dv.x & 0xffffu) | (dv.y << 16), (dv.z & 0xffffu) | (dv.w << 16) };
            uint2 vl = { (dv.x >> 16) | (dv.y & 0xffff0000u), (dv.z >> 16) | (dv.w & 0xffff0000u) };
            *(uint2*)(smc + SKh + off) = vh;
            *(uint2*)(smc + SKl + off) = vl;
        }
    }
    __syncthreads();

    int c0 = (wid & 3) * 16, i0 = (wid >> 2) * 32;
    float oacc[4][4];
    #pragma unroll
    for (int nj = 0; nj < 4; nj++)
        #pragma unroll
        for (int c = 0; c < 4; c++) oacc[nj][c] = 0.f;

    int ar2 = (((lane >> 3) & 1) << 3) + (lane & 7);
    int ac2 = (lane >> 4) << 3;
    int br2 = ((lane >> 4) << 3) + (lane & 7);
    int bc2 = ((lane >> 3) & 1) << 3;

    #pragma unroll
    for (int ks = 0; ks < 8; ks++) {
        int kb = ks * 16;
        uint32_t avh[4], avl[4];
        {
            uint32_t ad = sb + (uint32_t)((c0 + ar2)*272 + (kb + ac2)*2);
            LDSM_X4(avh[0], avh[1], avh[2], avh[3], ad + SKh);
            LDSM_X4(avl[0], avl[1], avl[2], avl[3], ad + SKl);
        }
        uint32_t bah[2][4], bal[2][4];
        #pragma unroll
        for (int ib2 = 0; ib2 < 2; ib2++) {
            uint32_t bd = sb + (uint32_t)((i0 + ib2*16 + br2)*272 + (kb + bc2)*2);
            LDSM_X4(bah[ib2][0], bah[ib2][1], bah[ib2][2], bah[ib2][3], bd + SQh);
            LDSM_X4(bal[ib2][0], bal[ib2][1], bal[ib2][2], bal[ib2][3], bd + SQl);
        }
        #pragma unroll
        for (int nj = 0; nj < 4; nj++) {
            int ib2 = nj >> 1, q2 = (nj & 1) * 2;
            mma16816(oacc[nj], avh, bah[ib2][q2], bah[ib2][q2+1]);
            mma16816(oacc[nj], avh, bal[ib2][q2], bal[ib2][q2+1]);
            mma16816(oacc[nj], avl, bah[ib2][q2], bah[ib2][q2+1]);
        }
    }

    {
        int cA = c0 + g, cB = cA + 8;
        float* oA = out + voff + (size_t)cA * HWSZ + ibq;
        float* oB = out + voff + (size_t)cB * HWSZ + ibq;
        #pragma unroll
        for (int nj = 0; nj < 4; nj++) {
            int i = i0 + nj*8 + t*2;
            float2 vA = { oacc[nj][0], oacc[nj][1] };
            float2 vB = { oacc[nj][2], oacc[nj][3] };
            *(float2*)(oA + i) = vA;
            *(float2*)(oB + i) = vB;
        }
    }

    if (n < 2) {
        float s0 = 0.f, q0 = 0.f, s1 = 0.f, q1 = 0.f;
        #pragma unroll
        for (int nj = 0; nj < 4; nj++) {
            s0 += oacc[nj][0] + oacc[nj][1];
            q0 += oacc[nj][0]*oacc[nj][0] + oacc[nj][1]*oacc[nj][1];
            s1 += oacc[nj][2] + oacc[nj][3];
            q1 += oacc[nj][2]*oacc[nj][2] + oacc[nj][3]*oacc[nj][3];
        }
        s0 += __shfl_xor_sync(0xffffffffu, s0, 1);
        s0 += __shfl_xor_sync(0xffffffffu, s0, 2);
        q0 += __shfl_xor_sync(0xffffffffu, q0, 1);
        q0 += __shfl_xor_sync(0xffffffffu, q0, 2);
        s1 += __shfl_xor_sync(0xffffffffu, s1, 1);
        s1 += __shfl_xor_sync(0xffffffffu, s1, 2);
        q1 += __shfl_xor_sync(0xffffffffu, q1, 1);
        q1 += __shfl_xor_sync(0xffffffffu, q1, 2);
        if (t == 0) {
            int chA = n*64 + c0 + g, chB = chA + 8;
            atomicAdd(&bns[chA], s0);       atomicAdd(&bns[256 + chA], q0);
            atomicAdd(&bns[chB], s1);       atomicAdd(&bns[256 + chB], q1);
        }
    }
}

// ---------------- BN finalize ----------------
__global__ void bn_finalize_kernel(const float* __restrict__ bnsW, const float* __restrict__ bnsH,
                                   const float* __restrict__ bnh_w, const float* __restrict__ bnh_b,
                                   const float* __restrict__ bnw_w, const float* __restrict__ bnw_b,
                                   float* __restrict__ scH, float* __restrict__ scW) {
    int tid = threadIdx.x;
    const float N = 65536.0f;
    if (tid < 128) {
        float mean = bnsW[tid] / N;
        float var  = bnsW[256 + tid] / N - mean*mean;
        float scale = bnw_w[tid] * rsqrtf(var + 1e-5f);
        scW[tid] = scale;
        scW[128 + tid] = bnw_b[tid] - mean*scale;
    } else {
        int c = tid - 128;
        float mean = bnsH[c] / N;
        float var  = bnsH[256 + c] / N - mean*mean;
        float scale = bnh_w[c] * rsqrtf(var + 1e-5f);
        scH[c] = scale;
        scH[128 + c] = bnh_b[c] - mean*scale;
    }
}

// ---------------- fused epilogue ----------------
__global__ void final_fused_kernel(const float* __restrict__ x, const float* __restrict__ oh,
                                   const float* __restrict__ ow, const float* __restrict__ scH,
                                   const float* __restrict__ scW, const float* __restrict__ gamma,
                                   float* __restrict__ out) {
    int idx = blockIdx.x * 256 + threadIdx.x;
    int b  = idx >> 20;
    int c  = (idx >> 12) & 255;
    int i4 = (idx & 4095) << 2;
    float gm = gamma[0];

    float4 h4 = *(const float4*)(oh + ((size_t)b*256 + c)*HWSZ + i4);
    float4 w4 = *(const float4*)(ow + ((size_t)b*256 + c)*HWSZ + i4);
    float4 x0 = *(const float4*)(x + ((size_t)b*512 + c)      *HWSZ + i4);
    float4 x1 = *(const float4*)(x + ((size_t)b*512 + c + 256)*HWSZ + i4);

    float4 o0, o1;
    o0.x = gm*fmaxf(h4.x, 0.f) + x0.x;  o0.y = gm*fmaxf(h4.y, 0.f) + x0.y;
    o0.z = gm*fmaxf(h4.z, 0.f) + x0.z;  o0.w = gm*fmaxf(h4.w, 0.f) + x0.w;
    o1.x = gm*fmaxf(w4.x, 0.f) + x1.x;  o1.y = gm*fmaxf(w4.y, 0.f) + x1.y;
    o1.z = gm*fmaxf(w4.z, 0.f) + x1.z;  o1.w = gm*fmaxf(w4.w, 0.f) + x1.w;
    *(float4*)(out + ((size_t)b*512 + c)      *HWSZ + i4) = o0;
    *(float4*)(out + ((size_t)b*512 + c + 256)*HWSZ + i4) = o1;

    if (c < 128) {
        float sH = scH[c], shH = scH[128+c];
        float sW = scW[c], shW = scW[128+c];
        float4 p0, p1;
        p0.x = h4.x*sH + shH; p0.y = h4.y*sH + shH; p0.z = h4.z*sH + shH; p0.w = h4.w*sH + shH;
        p1.x = w4.x*sW + shW; p1.y = w4.y*sW + shW; p1.z = w4.z*sW + shW; p1.w = w4.w*sW + shW;
        *(float4*)(out + 33554432ull + ((size_t)b*128 + c)*HWSZ + i4) = p0;
        *(float4*)(out + 41943040ull + ((size_t)b*128 + c)*HWSZ + i4) = p1;
    }
}

// ---------------- launch ----------------
extern "C" void kernel_launch(void* const* d_in, const int* in_sizes, int n_in,
                              void* d_out, int out_size) {
    const float* x     = (const float*)d_in[0];
    const float* wq    = (const float*)d_in[1];
    const float* bq    = (const float*)d_in[2];
    const float* wk    = (const float*)d_in[3];
    const float* bk    = (const float*)d_in[4];
    const float* wv    = (const float*)d_in[5];
    const float* bv    = (const float*)d_in[6];
    const float* bnh_w = (const float*)d_in[7];
    const float* bnh_b = (const float*)d_in[8];
    const float* bnw_w = (const float*)d_in[9];
    const float* bnw_b = (const float*)d_in[10];
    const float* gamma = (const float*)d_in[11];
    float* out = (float*)d_out;

    uint32_t *qp, *kp, *vp, *qpT, *kpT, *vpT;
    float *oW, *oHT, *oH, *scH, *scW, *bp, *bnsW, *bnsH;
    __nv_bfloat16 *wph, *wpl;
    cudaGetSymbolAddress((void**)&qp,   g_qp);
    cudaGetSymbolAddress((void**)&kp,   g_kp);
    cudaGetSymbolAddress((void**)&vp,   g_vp);
    cudaGetSymbolAddress((void**)&qpT,  g_qpT);
    cudaGetSymbolAddress((void**)&kpT,  g_kpT);
    cudaGetSymbolAddress((void**)&vpT,  g_vpT);
    cudaGetSymbolAddress((void**)&oW,   g_outW);
    cudaGetSymbolAddress((void**)&oHT,  g_outHT);
    cudaGetSymbolAddress((void**)&oH,   g_outH);
    cudaGetSymbolAddress((void**)&scH,  g_scH);
    cudaGetSymbolAddress((void**)&scW,  g_scW);
    cudaGetSymbolAddress((void**)&bnsW, g_bnsW);
    cudaGetSymbolAddress((void**)&bnsH, g_bnsH);
    cudaGetSymbolAddress((void**)&wph,  g_wph);
    cudaGetSymbolAddress((void**)&wpl,  g_wpl);
    cudaGetSymbolAddress((void**)&bp,   g_bp);

    cudaFuncSetAttribute(gemm_kernel, cudaFuncAttributeMaxDynamicSharedMemorySize, GEMM_SMEM);
    cudaFuncSetAttribute(attn_mma_kernel, cudaFuncAttributeMaxDynamicSharedMemorySize, ATT3_SMEM);

    cudaMemsetAsync(bnsW, 0, 512 * sizeof(float));
    cudaMemsetAsync(bnsH, 0, 512 * sizeof(float));

    prepw_kernel<<<1280, 256>>>(wq, bq, wk, bk, wv, bv, wph, wpl, bp);
    gemm_kernel<<<dim3(128, 8), 256, GEMM_SMEM>>>(x, wph, wpl, bp, qp, kp, vp);

    // W-direction attention runs while transposes prepare H-direction inputs
    attn_mma_kernel<<<dim3(128, 8, 4), 256, ATT3_SMEM>>>(qp,  kp,  vp,  oW,  bnsW);
    transpose_kernel<<<dim3(16, 2048), dim3(32,8)>>>((const float*)qp, (float*)qpT);
    transpose_kernel<<<dim3(16, 2048), dim3(32,8)>>>((const float*)kp, (float*)kpT);
    transpose_kernel<<<dim3(16, 1024), dim3(32,8)>>>((const float*)vp, (float*)vpT);
    attn_mma_kernel<<<dim3(128, 8, 4), 256, ATT3_SMEM>>>(qpT, kpT, vpT, oHT, bnsH);
    transpose_kernel<<<dim3(16, 1024), dim3(32,8)>>>(oHT, oH);

    bn_finalize_kernel<<<1, 256>>>(bnsW, bnsH, bnh_w, bnh_b, bnw_w, bnw_b, scH, scW);
    final_fused_kernel<<<16384, 256>>>(x, oH, oW, scH, scW, gamma, out);
}

// round 9
// speedup vs baseline: 2.0824x; 1.0124x over previous
#include <cuda_runtime.h>
#include <cuda_bf16.h>
#include <math.h>
#include <stdint.h>

#define HWSZ 16384
#define GEMM_SMEM 205824
#define ATT3_SMEM 108544

// ---------------- scratch ----------------
__device__ uint32_t g_qp [4ull*512*16384];   // packed bf16: hi | lo<<16
__device__ uint32_t g_kp [4ull*512*16384];
__device__ uint32_t g_vp [4ull*256*16384];
__device__ uint32_t g_qpT[4ull*512*16384];
__device__ uint32_t g_kpT[4ull*512*16384];
__device__ uint32_t g_vpT[4ull*256*16384];
__device__ float g_outW [4ull*256*16384];
__device__ float g_outHT[4ull*256*16384];
__device__ float g_scH[256];
__device__ float g_scW[256];
__device__ float g_bnsW[512];   // [0..255]=sum, [256..511]=sumsq
__device__ float g_bnsH[512];
__device__ __nv_bfloat16 g_wph[2*640*256];   // [g][m][k]
__device__ __nv_bfloat16 g_wpl[2*640*256];
__device__ float g_bp[2*640];

// ---------------- helpers ----------------
__device__ __forceinline__ uint32_t smem_u32(const void* p) {
    uint32_t a;
    asm("{ .reg .u64 t; cvta.to.shared.u64 t, %1; cvt.u32.u64 %0, t; }" : "=r"(a) : "l"(p));
    return a;
}
#define LDSM_X4(r0, r1, r2, r3, addr) \
    asm volatile("ldmatrix.sync.aligned.m8n8.x4.shared.b16 {%0,%1,%2,%3}, [%4];" \
        : "=r"(r0), "=r"(r1), "=r"(r2), "=r"(r3) : "r"(addr))
#define LDSM_X4_T(r0, r1, r2, r3, addr) \
    asm volatile("ldmatrix.sync.aligned.m8n8.x4.trans.shared.b16 {%0,%1,%2,%3}, [%4];" \
        : "=r"(r0), "=r"(r1), "=r"(r2), "=r"(r3) : "r"(addr))
#define CP_ASYNC16(dst, src) \
    asm volatile("cp.async.cg.shared.global [%0], [%1], 16;" :: "r"(dst), "l"(src))
#define CP_COMMIT() asm volatile("cp.async.commit_group;" ::: "memory")
#define CP_WAIT1()  asm volatile("cp.async.wait_group 1;" ::: "memory")
#define CP_WAIT0()  asm volatile("cp.async.wait_group 0;" ::: "memory")

__device__ __forceinline__ void mma16816(float* d, const uint32_t* a,
                                         uint32_t b0, uint32_t b1) {
    asm volatile(
        "mma.sync.aligned.m16n8k16.row.col.f32.bf16.bf16.f32 "
        "{%0,%1,%2,%3}, {%4,%5,%6,%7}, {%8,%9}, {%0,%1,%2,%3};"
        : "+f"(d[0]), "+f"(d[1]), "+f"(d[2]), "+f"(d[3])
        : "r"(a[0]), "r"(a[1]), "r"(a[2]), "r"(a[3]), "r"(b0), "r"(b1));
}
__device__ __forceinline__ uint32_t pack_bf(float f) {
    __nv_bfloat16 h = __float2bfloat16(f);
    __nv_bfloat16 l = __float2bfloat16(f - __bfloat162float(h));
    return (uint32_t)__bfloat16_as_ushort(h) | ((uint32_t)__bfloat16_as_ushort(l) << 16);
}
__device__ __forceinline__ void split2(float a, float b, uint32_t& h, uint32_t& l) {
    __nv_bfloat16 ha = __float2bfloat16(a);
    __nv_bfloat16 hb = __float2bfloat16(b);
    __nv_bfloat16 la = __float2bfloat16(a - __bfloat162float(ha));
    __nv_bfloat16 lb = __float2bfloat16(b - __bfloat162float(hb));
    h = (uint32_t)__bfloat16_as_ushort(ha) | ((uint32_t)__bfloat16_as_ushort(hb) << 16);
    l = (uint32_t)__bfloat16_as_ushort(la) | ((uint32_t)__bfloat16_as_ushort(lb) << 16);
}
__device__ __forceinline__ void cvt4(float4 v, uint2& h, uint2& l) {
    uint32_t h0, l0, h1, l1;
    split2(v.x, v.y, h0, l0);
    split2(v.z, v.w, h1, l1);
    h.x = h0; h.y = h1; l.x = l0; l.y = l1;
}
// address within a 16KB (128 rows x 64 k) SW128 quarter tile
__device__ __forceinline__ uint32_t t64_addr(uint32_t tbase, int row, int kc) {
    return tbase + (uint32_t)(((row >> 3) << 10) + ((row & 7) << 7)
                 + ((((kc & 63) << 1)) ^ ((row & 7) << 4)));
}

// ---------------- weight pack + bf16 split (split into 3 kernels) ----------------
__global__ void prepw_one(const float* __restrict__ w, const float* __restrict__ bias,
                          __nv_bfloat16* __restrict__ wph, __nv_bfloat16* __restrict__ wpl,
                          float* __restrict__ bp, int m_off, int M) {
    int idx = blockIdx.x * 256 + threadIdx.x;    // 2*M*256 total
    int per_g = M * 256;
    int g = idx / per_g;
    int r = idx - g * per_g;
    int m = r >> 8, k = r & 255;
    float wv = w[(size_t)(g*M + m) * 256 + k];
    __nv_bfloat16 h = __float2bfloat16(wv);
    size_t didx = (size_t)(g*640 + m_off + m) * 256 + k;
    wph[didx] = h;
    wpl[didx] = __float2bfloat16(wv - __bfloat162float(h));
    if (k == 0) bp[g*640 + m_off + m] = bias[g*M + m];
}

// ---- stage [128 x 64] bf16 A quarter tile into SW128 layout, async ----
__device__ __forceinline__ void stage_a64(uint32_t smb, const __nv_bfloat16* __restrict__ src,
                                          int tid) {
    #pragma unroll
    for (int it = 0; it < 4; it++) {
        int idx = it * 256 + tid;          // 0..1023
        int row = idx >> 3;
        int k8 = (idx & 7) << 3;
        uint32_t byte = (uint32_t)(((row >> 3) << 10) + ((row & 7) << 7)
                       + ((k8 << 1) ^ ((row & 7) << 4)));
        CP_ASYNC16(smb + byte, src + (size_t)row * 256 + k8);
    }
}

// ---------------- fused qkv projection GEMM (B-resident, pipelined A) -------------
__global__ __launch_bounds__(256, 1)
void gemm_kernel(const float* __restrict__ x,
                 const __nv_bfloat16* __restrict__ wph, const __nv_bfloat16* __restrict__ wpl,
                 const float* __restrict__ bp,
                 uint32_t* __restrict__ qb, uint32_t* __restrict__ kb2, uint32_t* __restrict__ vb) {
    extern __shared__ char sm[];
    uint32_t sbase = smem_u32(sm);
    const uint32_t AHb[2] = {1024, 33792};
    const uint32_t ALb[2] = {17408, 50176};
    const uint32_t BH = 66560, BL = 136192;
    int tid = threadIdx.x;
    int lane = tid & 31, wid = tid >> 5;
    int pbase = blockIdx.x * 128;
    int z = blockIdx.y;                 // b*2+g
    int b = z >> 1, g = z & 1;
    const __nv_bfloat16* wbase_h = wph + (size_t)g*640*256;
    const __nv_bfloat16* wbase_l = wpl + (size_t)g*640*256;

    stage_a64(sbase + AHb[0], wbase_h, tid);
    stage_a64(sbase + ALb[0], wbase_l, tid);
    CP_COMMIT();

    {
        const float* xb = x + ((size_t)b*512 + g*256) * HWSZ + pbase;
        #pragma unroll 4
        for (int it = 0; it < 32; it++) {
            int idx = it * 256 + tid;
            int row = idx >> 5;
            int p4  = (idx & 31) << 2;
            float4 v = *(const float4*)(xb + (size_t)row * HWSZ + p4);
            uint2 h, l;
            cvt4(v, h, l);
            uint32_t off = (uint32_t)(row * 272 + p4 * 2);
            *(uint2*)(sm + BH + off) = h;
            *(uint2*)(sm + BL + off) = l;
        }
    }

    int mb = (wid & 1) * 64;
    int nb = (wid >> 1) * 32;
    int laneA_row = ((lane >> 3) & 1) * 8 + (lane & 7);
    int laneA_k8  = (lane >> 4) * 8;
    int bt_r = (((lane >> 3) & 1) << 3) + (lane & 7);
    int bt_c = (lane >> 4) << 3;

    float d[4][4][4];

    #pragma unroll 1
    for (int q = 0; q < 20; q++) {
        int mt = q >> 2;
        if ((q & 3) == 0) {
            #pragma unroll
            for (int mi = 0; mi < 4; mi++)
                #pragma unroll
                for (int nj = 0; nj < 4; nj++)
                    #pragma unroll
                    for (int c = 0; c < 4; c++) d[mi][nj][c] = 0.f;
        }
        __syncthreads();
        if (q < 19) {
            int qq = q + 1;
            size_t aoff = ((size_t)(qq >> 2) * 128) * 256 + (qq & 3) * 64;
            stage_a64(sbase + AHb[qq & 1], wbase_h + aoff, tid);
            stage_a64(sbase + ALb[qq & 1], wbase_l + aoff, tid);
            CP_COMMIT();
            CP_WAIT1();
        } else {
            CP_WAIT0();
        }
        __syncthreads();

        uint32_t AH = sbase + AHb[q & 1];
        uint32_t AL = sbase + ALb[q & 1];
        int kbase = (q & 3) * 64;

        #pragma unroll
        for (int ks = 0; ks < 4; ks++) {
            int kl = ks * 16;
            int kk = kbase + kl;
            uint32_t aH[4][4], aL[4][4];
            #pragma unroll
            for (int mi = 0; mi < 4; mi++) {
                LDSM_X4(aH[mi][0], aH[mi][1], aH[mi][2], aH[mi][3],
                        t64_addr(AH, mb + mi*16 + laneA_row, kl + laneA_k8));
                LDSM_X4(aL[mi][0], aL[mi][1], aL[mi][2], aL[mi][3],
                        t64_addr(AL, mb + mi*16 + laneA_row, kl + laneA_k8));
            }
            uint32_t bHf[2][4], bLf[2][4];
            #pragma unroll
            for (int p = 0; p < 2; p++) {
                uint32_t bd = sbase + (uint32_t)((kk + bt_r)*272 + (nb + p*16 + bt_c)*2);
                LDSM_X4_T(bHf[p][0], bHf[p][1], bHf[p][2], bHf[p][3], bd + BH);
                LDSM_X4_T(bLf[p][0], bLf[p][1], bLf[p][2], bLf[p][3], bd + BL);
            }
            #pragma unroll
            for (int mi = 0; mi < 4; mi++)
                #pragma unroll
                for (int nj = 0; nj < 4; nj++) {
                    int p = nj >> 1, qx = (nj & 1) * 2;
                    mma16816(d[mi][nj], aH[mi], bHf[p][qx], bHf[p][qx+1]);
                    mma16816(d[mi][nj], aH[mi], bLf[p][qx], bLf[p][qx+1]);
                    mma16816(d[mi][nj], aL[mi], bHf[p][qx], bHf[p][qx+1]);
                }
        }

        if ((q & 3) == 3) {
            uint32_t* dst; size_t ch0;
            if (mt < 2)      { dst = qb;  ch0 = (size_t)b*512 + g*256 + mt*128; }
            else if (mt < 4) { dst = kb2; ch0 = (size_t)b*512 + g*256 + (mt-2)*128; }
            else             { dst = vb;  ch0 = (size_t)b*256 + g*128; }
            #pragma unroll
            for (int mi = 0; mi < 4; mi++) {
                int r0 = mb + mi*16 + (lane >> 2);
                float bias0 = bp[g*640 + mt*128 + r0];
                float bias1 = bp[g*640 + mt*128 + r0 + 8];
                uint32_t* row0 = dst + (ch0 + r0)     * HWSZ + pbase;
                uint32_t* row1 = dst + (ch0 + r0 + 8) * HWSZ + pbase;
                #pragma unroll
                for (int nj = 0; nj < 4; nj++) {
                    int col = nb + nj*8 + (lane & 3)*2;
                    uint2 o0 = { pack_bf(d[mi][nj][0] + bias0), pack_bf(d[mi][nj][1] + bias0) };
                    uint2 o1 = { pack_bf(d[mi][nj][2] + bias1), pack_bf(d[mi][nj][3] + bias1) };
                    *(uint2*)(row0 + col) = o0;
                    *(uint2*)(row1 + col) = o1;
                }
            }
        }
    }
}

// ---------------- 128x128 transpose per slice (4-byte elements) ----------------
__global__ void transpose_kernel(const float* __restrict__ in, float* __restrict__ out) {
    __shared__ float t[32][33];
    int tile = blockIdx.x;
    int bx = (tile & 3) * 32, by = (tile >> 2) * 32;
    const float* ip = in  + (size_t)blockIdx.y * HWSZ;
    float*       op = out + (size_t)blockIdx.y * HWSZ;
    int x = threadIdx.x, y = threadIdx.y;
    #pragma unroll
    for (int r = 0; r < 32; r += 8)
        t[y+r][x] = ip[(size_t)(by + y + r)*128 + bx + x];
    __syncthreads();
    #pragma unroll
    for (int r = 0; r < 32; r += 8)
        op[(size_t)(bx + y + r)*128 + by + x] = t[x][y+r];
}

// ---------------- axial attention: 64 queries/CTA, 2 CTAs/SM, fused BN sums --------
__global__ __launch_bounds__(256, 2)
void attn_mma_kernel(const uint32_t* __restrict__ qp, const uint32_t* __restrict__ kp,
                     const uint32_t* __restrict__ vp, float* __restrict__ out,
                     float* __restrict__ bns) {
    extern __shared__ char smc[];
    uint32_t sb = smem_u32(smc);
    const uint32_t SQh = 0, SQl = 18432, SKh = 36864, SKl = 71680;
    float* redM = (float*)(smc + 106496);
    float* redS = (float*)(smc + 107520);
    const float SC2 = 0.08838834764831845f * 1.4426950408889634f;  // scale*log2e

    int r = blockIdx.x;
    int n = blockIdx.y >> 1, half = blockIdx.y & 1;
    int b = blockIdx.z;
    size_t qoff = ((size_t)(b*4 + n) * 128) * HWSZ + (size_t)r * 128;
    size_t voff = ((size_t)(b*4 + n) *  64) * HWSZ + (size_t)r * 128;
    int ibq = half * 64;
    int tid = threadIdx.x;
    int lane = tid & 31, wid = tid >> 5;
    int g = lane >> 2, t = lane & 3;

    {
        const uint32_t* qs = qp + qoff + ibq;
        #pragma unroll
        for (int u = 0; u < 8; u++) {
            int idx = u*256 + tid;
            int row = idx >> 4, p4 = (idx & 15) << 2;
            uint32_t off = (uint32_t)(row*144 + p4*2);
            uint4 dq = *(const uint4*)(qs + (size_t)row*HWSZ + p4);
            uint2 qh = { (dq.x & 0xffffu) | (dq.y << 16), (dq.z & 0xffffu) | (dq.w << 16) };
            uint2 ql = { (dq.x >> 16) | (dq.y & 0xffff0000u), (dq.z >> 16) | (dq.w & 0xffff0000u) };
            *(uint2*)(smc + SQh + off) = qh;
            *(uint2*)(smc + SQl + off) = ql;
        }
        const uint32_t* ks2 = kp + qoff;
        #pragma unroll
        for (int u = 0; u < 16; u++) {
            int idx = u*256 + tid;
            int row = idx >> 5, p4 = (idx & 31) << 2;
            uint32_t off = (uint32_t)(row*272 + p4*2);
            uint4 dk = *(const uint4*)(ks2 + (size_t)row*HWSZ + p4);
            uint2 kh = { (dk.x & 0xffffu) | (dk.y << 16), (dk.z & 0xffffu) | (dk.w << 16) };
            uint2 kl = { (dk.x >> 16) | (dk.y & 0xffff0000u), (dk.z >> 16) | (dk.w & 0xffff0000u) };
            *(uint2*)(smc + SKh + off) = kh;
            *(uint2*)(smc + SKl + off) = kl;
        }
    }
    __syncthreads();

    int wm = wid >> 2, wn = wid & 3;
    int m0 = wm * 32, n0 = wn * 32;
    float acc[2][4][4];
    #pragma unroll
    for (int mi = 0; mi < 2; mi++)
        #pragma unroll
        for (int nj = 0; nj < 4; nj++)
            #pragma unroll
            for (int c = 0; c < 4; c++) acc[mi][nj][c] = 0.f;

    int a_r = ((lane >> 4) << 3) + (lane & 7);
    int a_c = ((lane >> 3) & 1) << 3;
    int b_r = (((lane >> 3) & 1) << 3) + (lane & 7);
    int b_c = (lane >> 4) << 3;
    uint32_t aoff0 = (uint32_t)(a_r*144 + (m0 + a_c)*2);
    uint32_t boff0 = (uint32_t)(b_r*272 + (n0 + b_c)*2);

    #pragma unroll
    for (int ks = 0; ks < 8; ks++) {
        uint32_t kq = (uint32_t)(ks * 16 * 144);
        uint32_t kk2 = (uint32_t)(ks * 16 * 272);
        uint32_t aqh[2][4], aql[2][4];
        #pragma unroll
        for (int mi = 0; mi < 2; mi++) {
            uint32_t ad = sb + kq + aoff0 + mi*32;
            LDSM_X4_T(aqh[mi][0], aqh[mi][1], aqh[mi][2], aqh[mi][3], ad + SQh);
            LDSM_X4_T(aql[mi][0], aql[mi][1], aql[mi][2], aql[mi][3], ad + SQl);
        }
        uint32_t bkh[2][4], bkl[2][4];
        #pragma unroll
        for (int p = 0; p < 2; p++) {
            uint32_t bd = sb + kk2 + boff0 + p*32;
            LDSM_X4_T(bkh[p][0], bkh[p][1], bkh[p][2], bkh[p][3], bd + SKh);
            LDSM_X4_T(bkl[p][0], bkl[p][1], bkl[p][2], bkl[p][3], bd + SKl);
        }
        #pragma unroll
        for (int mi = 0; mi < 2; mi++)
            #pragma unroll
            for (int nj = 0; nj < 4; nj++) {
                int p = nj >> 1, q2 = (nj & 1) * 2;
                mma16816(acc[mi][nj], aqh[mi], bkh[p][q2], bkh[p][q2+1]);
                mma16816(acc[mi][nj], aqh[mi], bkl[p][q2], bkl[p][q2+1]);
                mma16816(acc[mi][nj], aql[mi], bkh[p][q2], bkh[p][q2+1]);
            }
    }

    // softmax over raw scores; scale folded into exponent
    #pragma unroll
    for (int mi = 0; mi < 2; mi++) {
        int rA = m0 + mi*16 + g, rB = rA + 8;
        float mA = -1e30f, mB = -1e30f;
        #pragma unroll
        for (int nj = 0; nj < 4; nj++) {
            mA = fmaxf(mA, fmaxf(acc[mi][nj][0], acc[mi][nj][1]));
            mB = fmaxf(mB, fmaxf(acc[mi][nj][2], acc[mi][nj][3]));
        }
        mA = fmaxf(mA, __shfl_xor_sync(0xffffffffu, mA, 1));
        mA = fmaxf(mA, __shfl_xor_sync(0xffffffffu, mA, 2));
        mB = fmaxf(mB, __shfl_xor_sync(0xffffffffu, mB, 1));
        mB = fmaxf(mB, __shfl_xor_sync(0xffffffffu, mB, 2));
        if (t == 0) { redM[rA*4 + wn] = mA; redM[rB*4 + wn] = mB; }
    }
    __syncthreads();
    #pragma unroll
    for (int mi = 0; mi < 2; mi++) {
        int rA = m0 + mi*16 + g, rB = rA + 8;
        float mxA = fmaxf(fmaxf(redM[rA*4], redM[rA*4+1]), fmaxf(redM[rA*4+2], redM[rA*4+3])) * SC2;
        float mxB = fmaxf(fmaxf(redM[rB*4], redM[rB*4+1]), fmaxf(redM[rB*4+2], redM[rB*4+3])) * SC2;
        float sA = 0.f, sB = 0.f;
        #pragma unroll
        for (int nj = 0; nj < 4; nj++) {
            float e0 = exp2f(fmaf(acc[mi][nj][0], SC2, -mxA));
            float e1 = exp2f(fmaf(acc[mi][nj][1], SC2, -mxA));
            float e2 = exp2f(fmaf(acc[mi][nj][2], SC2, -mxB));
            float e3 = exp2f(fmaf(acc[mi][nj][3], SC2, -mxB));
            acc[mi][nj][0] = e0; acc[mi][nj][1] = e1;
            acc[mi][nj][2] = e2; acc[mi][nj][3] = e3;
            sA += e0 + e1; sB += e2 + e3;
        }
        sA += __shfl_xor_sync(0xffffffffu, sA, 1);
        sA += __shfl_xor_sync(0xffffffffu, sA, 2);
        sB += __shfl_xor_sync(0xffffffffu, sB, 1);
        sB += __shfl_xor_sync(0xffffffffu, sB, 2);
        if (t == 0) { redS[rA*4 + wn] = sA; redS[rB*4 + wn] = sB; }
    }
    __syncthreads();

    #pragma unroll
    for (int mi = 0; mi < 2; mi++) {
        int rA = m0 + mi*16 + g, rB = rA + 8;
        float iA = 1.0f / (redS[rA*4] + redS[rA*4+1] + redS[rA*4+2] + redS[rA*4+3]);
        float iB = 1.0f / (redS[rB*4] + redS[rB*4+1] + redS[rB*4+2] + redS[rB*4+3]);
        #pragma unroll
        for (int nj = 0; nj < 4; nj++) {
            int j0 = n0 + nj*8 + t*2;
            uint32_t h, l;
            split2(acc[mi][nj][0]*iA, acc[mi][nj][1]*iA, h, l);
            *(uint32_t*)(smc + SQh + rA*272 + j0*2) = h;
            *(uint32_t*)(smc + SQl + rA*272 + j0*2) = l;
            split2(acc[mi][nj][2]*iB, acc[mi][nj][3]*iB, h, l);
            *(uint32_t*)(smc + SQh + rB*272 + j0*2) = h;
            *(uint32_t*)(smc + SQl + rB*272 + j0*2) = l;
        }
    }
    __syncthreads();

    {
        const uint32_t* vs = vp + voff;
        #pragma unroll
        for (int u = 0; u < 8; u++) {
            int idx = u*256 + tid;
            int row = idx >> 5, p4 = (idx & 31) << 2;
            uint32_t off = (uint32_t)(row*272 + p4*2);
            uint4 dv = *(const uint4*)(vs + (size_t)row*HWSZ + p4);
            uint2 vh = { (dv.x & 0xffffu) | (dv.y << 16), (dv.z & 0xffffu) | (dv.w << 16) };
            uint2 vl = { (dv.x >> 16) | (dv.y & 0xffff0000u), (dv.z >> 16) | (dv.w & 0xffff0000u) };
            *(uint2*)(smc + SKh + off) = vh;
            *(uint2*)(smc + SKl + off) = vl;
        }
    }
    __syncthreads();

    int c0 = (wid & 3) * 16, i0 = (wid >> 2) * 32;
    float oacc[4][4];
    #pragma unroll
    for (int nj = 0; nj < 4; nj++)
        #pragma unroll
        for (int c = 0; c < 4; c++) oacc[nj][c] = 0.f;

    int ar2 = (((lane >> 3) & 1) << 3) + (lane & 7);
    int ac2 = (lane >> 4) << 3;
    int br2 = ((lane >> 4) << 3) + (lane & 7);
    int bc2 = ((lane >> 3) & 1) << 3;

    #pragma unroll
    for (int ks = 0; ks < 8; ks++) {
        int kb = ks * 16;
        uint32_t avh[4], avl[4];
        {
            uint32_t ad = sb + (uint32_t)((c0 + ar2)*272 + (kb + ac2)*2);
            LDSM_X4(avh[0], avh[1], avh[2], avh[3], ad + SKh);
            LDSM_X4(avl[0], avl[1], avl[2], avl[3], ad + SKl);
        }
        uint32_t bah[2][4], bal[2][4];
        #pragma unroll
        for (int ib2 = 0; ib2 < 2; ib2++) {
            uint32_t bd = sb + (uint32_t)((i0 + ib2*16 + br2)*272 + (kb + bc2)*2);
            LDSM_X4(bah[ib2][0], bah[ib2][1], bah[ib2][2], bah[ib2][3], bd + SQh);
            LDSM_X4(bal[ib2][0], bal[ib2][1], bal[ib2][2], bal[ib2][3], bd + SQl);
        }
        #pragma unroll
        for (int nj = 0; nj < 4; nj++) {
            int ib2 = nj >> 1, q2 = (nj & 1) * 2;
            mma16816(oacc[nj], avh, bah[ib2][q2], bah[ib2][q2+1]);
            mma16816(oacc[nj], avh, bal[ib2][q2], bal[ib2][q2+1]);
            mma16816(oacc[nj], avl, bah[ib2][q2], bah[ib2][q2+1]);
        }
    }

    {
        int cA = c0 + g, cB = cA + 8;
        float* oA = out + voff + (size_t)cA * HWSZ + ibq;
        float* oB = out + voff + (size_t)cB * HWSZ + ibq;
        #pragma unroll
        for (int nj = 0; nj < 4; nj++) {
            int i = i0 + nj*8 + t*2;
            float2 vA = { oacc[nj][0], oacc[nj][1] };
            float2 vB = { oacc[nj][2], oacc[nj][3] };
            *(float2*)(oA + i) = vA;
            *(float2*)(oB + i) = vB;
        }
    }

    if (n < 2) {
        float s0 = 0.f, q0 = 0.f, s1 = 0.f, q1 = 0.f;
        #pragma unroll
        for (int nj = 0; nj < 4; nj++) {
            s0 += oacc[nj][0] + oacc[nj][1];
            q0 += oacc[nj][0]*oacc[nj][0] + oacc[nj][1]*oacc[nj][1];
            s1 += oacc[nj][2] + oacc[nj][3];
            q1 += oacc[nj][2]*oacc[nj][2] + oacc[nj][3]*oacc[nj][3];
        }
        s0 += __shfl_xor_sync(0xffffffffu, s0, 1);
        s0 += __shfl_xor_sync(0xffffffffu, s0, 2);
        q0 += __shfl_xor_sync(0xffffffffu, q0, 1);
        q0 += __shfl_xor_sync(0xffffffffu, q0, 2);
        s1 += __shfl_xor_sync(0xffffffffu, s1, 1);
        s1 += __shfl_xor_sync(0xffffffffu, s1, 2);
        q1 += __shfl_xor_sync(0xffffffffu, q1, 1);
        q1 += __shfl_xor_sync(0xffffffffu, q1, 2);
        if (t == 0) {
            int chA = n*64 + c0 + g, chB = chA + 8;
            atomicAdd(&bns[chA], s0);       atomicAdd(&bns[256 + chA], q0);
            atomicAdd(&bns[chB], s1);       atomicAdd(&bns[256 + chB], q1);
        }
    }
}

// ---------------- BN finalize ----------------
__global__ void bn_finalize_kernel(const float* __restrict__ bnsW, const float* __restrict__ bnsH,
                                   const float* __restrict__ bnh_w, const float* __restrict__ bnh_b,
                                   const float* __restrict__ bnw_w, const float* __restrict__ bnw_b,
                                   float* __restrict__ scH, float* __restrict__ scW) {
    int tid = threadIdx.x;
    const float N = 65536.0f;
    if (tid < 128) {
        float mean = bnsW[tid] / N;
        float var  = bnsW[256 + tid] / N - mean*mean;
        float scale = bnw_w[tid] * rsqrtf(var + 1e-5f);
        scW[tid] = scale;
        scW[128 + tid] = bnw_b[tid] - mean*scale;
    } else {
        int c = tid - 128;
        float mean = bnsH[c] / N;
        float var  = bnsH[256 + c] / N - mean*mean;
        float scale = bnh_w[c] * rsqrtf(var + 1e-5f);
        scH[c] = scale;
        scH[128 + c] = bnh_b[c] - mean*scale;
    }
}

// ---------------- fused epilogue (reads oHT transposed in-kernel) ----------------
__global__ void final_fused_kernel(const float* __restrict__ x, const float* __restrict__ oht,
                                   const float* __restrict__ ow, const float* __restrict__ scH,
                                   const float* __restrict__ scW, const float* __restrict__ gamma,
                                   float* __restrict__ out) {
    __shared__ float t[32][33];
    int tile = blockIdx.x;               // 0..15
    int h0 = (tile >> 2) * 32, w0 = (tile & 3) * 32;
    int c = blockIdx.y, b = blockIdx.z;
    int tx = threadIdx.x, ty = threadIdx.y;
    float gm = gamma[0];

    // load oHT tile: stored [w][h]; we read rows of w, columns of h (coalesced)
    const float* ohs = oht + (size_t)(b*256 + c) * HWSZ;
    #pragma unroll
    for (int r = 0; r < 32; r += 8)
        t[ty + r][tx] = ohs[(size_t)(w0 + ty + r)*128 + h0 + tx];
    __syncthreads();

    const float* ows = ow + (size_t)(b*256 + c) * HWSZ;
    const float* x0p = x + (size_t)(b*512 + c)       * HWSZ;
    const float* x1p = x + (size_t)(b*512 + c + 256) * HWSZ;
    float* o0p = out + (size_t)(b*512 + c)       * HWSZ;
    float* o1p = out + (size_t)(b*512 + c + 256) * HWSZ;
    bool dop = (c < 128);
    float sH = 0.f, shH = 0.f, sW = 0.f, shW = 0.f;
    if (dop) { sH = scH[c]; shH = scH[128+c]; sW = scW[c]; shW = scW[128+c]; }
    float* p0p = out + 33554432ull + (size_t)(b*128 + c) * HWSZ;
    float* p1p = out + 41943040ull + (size_t)(b*128 + c) * HWSZ;

    #pragma unroll
    for (int r = 0; r < 32; r += 8) {
        int hr = ty + r;
        size_t pix = (size_t)(h0 + hr)*128 + w0 + tx;
        float hv = t[tx][hr];            // = oh[h0+hr][w0+tx]
        float wv = ows[pix];
        o0p[pix] = gm*fmaxf(hv, 0.f) + x0p[pix];
        o1p[pix] = gm*fmaxf(wv, 0.f) + x1p[pix];
        if (dop) {
            p0p[pix] = hv*sH + shH;
            p1p[pix] = wv*sW + shW;
        }
    }
}

// ---------------- launch ----------------
extern "C" void kernel_launch(void* const* d_in, const int* in_sizes, int n_in,
                              void* d_out, int out_size) {
    const float* x     = (const float*)d_in[0];
    const float* wq    = (const float*)d_in[1];
    const float* bq    = (const float*)d_in[2];
    const float* wk    = (const float*)d_in[3];
    const float* bk    = (const float*)d_in[4];
    const float* wv    = (const float*)d_in[5];
    const float* bv    = (const float*)d_in[6];
    const float* bnh_w = (const float*)d_in[7];
    const float* bnh_b = (const float*)d_in[8];
    const float* bnw_w = (const float*)d_in[9];
    const float* bnw_b = (const float*)d_in[10];
    const float* gamma = (const float*)d_in[11];
    float* out = (float*)d_out;

    uint32_t *qp, *kp, *vp, *qpT, *kpT, *vpT;
    float *oW, *oHT, *scH, *scW, *bp, *bnsW, *bnsH;
    __nv_bfloat16 *wph, *wpl;
    cudaGetSymbolAddress((void**)&qp,   g_qp);
    cudaGetSymbolAddress((void**)&kp,   g_kp);
    cudaGetSymbolAddress((void**)&vp,   g_vp);
    cudaGetSymbolAddress((void**)&qpT,  g_qpT);
    cudaGetSymbolAddress((void**)&kpT,  g_kpT);
    cudaGetSymbolAddress((void**)&vpT,  g_vpT);
    cudaGetSymbolAddress((void**)&oW,   g_outW);
    cudaGetSymbolAddress((void**)&oHT,  g_outHT);
    cudaGetSymbolAddress((void**)&scH,  g_scH);
    cudaGetSymbolAddress((void**)&scW,  g_scW);
    cudaGetSymbolAddress((void**)&bnsW, g_bnsW);
    cudaGetSymbolAddress((void**)&bnsH, g_bnsH);
    cudaGetSymbolAddress((void**)&wph,  g_wph);
    cudaGetSymbolAddress((void**)&wpl,  g_wpl);
    cudaGetSymbolAddress((void**)&bp,   g_bp);

    cudaFuncSetAttribute(gemm_kernel, cudaFuncAttributeMaxDynamicSharedMemorySize, GEMM_SMEM);
    cudaFuncSetAttribute(attn_mma_kernel, cudaFuncAttributeMaxDynamicSharedMemorySize, ATT3_SMEM);

    cudaMemsetAsync(bnsW, 0, 512 * sizeof(float));
    cudaMemsetAsync(bnsH, 0, 512 * sizeof(float));

    // prepw split into 3 so launch #6 (= ncu -s 5 -c 1) is gemm_kernel
    prepw_one<<<512, 256>>>(wq, bq, wph, wpl, bp, 0,   256);
    prepw_one<<<512, 256>>>(wk, bk, wph, wpl, bp, 256, 256);
    prepw_one<<<256, 256>>>(wv, bv, wph, wpl, bp, 512, 128);
    gemm_kernel<<<dim3(128, 8), 256, GEMM_SMEM>>>(x, wph, wpl, bp, qp, kp, vp);

    attn_mma_kernel<<<dim3(128, 8, 4), 256, ATT3_SMEM>>>(qp,  kp,  vp,  oW,  bnsW);
    transpose_kernel<<<dim3(16, 2048), dim3(32,8)>>>((const float*)qp, (float*)qpT);
    transpose_kernel<<<dim3(16, 2048), dim3(32,8)>>>((const float*)kp, (float*)kpT);
    transpose_kernel<<<dim3(16, 1024), dim3(32,8)>>>((const float*)vp, (float*)vpT);
    attn_mma_kernel<<<dim3(128, 8, 4), 256, ATT3_SMEM>>>(qpT, kpT, vpT, oHT, bnsH);

    bn_finalize_kernel<<<1, 256>>>(bnsW, bnsH, bnh_w, bnh_b, bnw_w, bnw_b, scH, scW);
    final_fused_kernel<<<dim3(16, 256, 4), dim3(32, 8)>>>(x, oHT, oW, scH, scW, gamma, out);
}

// round 11
// speedup vs baseline: 2.1193x; 1.0177x over previous
#include <cuda_runtime.h>
#include <cuda_bf16.h>
#include <math.h>
#include <stdint.h>

#define HWSZ 16384
#define GEMM_SMEM 107520
#define ATT3_SMEM 108544

// ---------------- scratch ----------------
__device__ uint32_t g_qp [4ull*512*16384];   // packed bf16: hi | lo<<16
__device__ uint32_t g_kp [4ull*512*16384];
__device__ uint32_t g_vp [4ull*256*16384];
__device__ uint32_t g_qpT[4ull*512*16384];
__device__ uint32_t g_kpT[4ull*512*16384];
__device__ uint32_t g_vpT[4ull*256*16384];
__device__ float g_outW [4ull*256*16384];
__device__ float g_outHT[4ull*256*16384];
__device__ float g_scH[256];
__device__ float g_scW[256];
__device__ float g_bnsW[512];   // [0..255]=sum, [256..511]=sumsq
__device__ float g_bnsH[512];
__device__ __nv_bfloat16 g_wph[2*640*256];   // [g][m][k]
__device__ __nv_bfloat16 g_wpl[2*640*256];
__device__ float g_bp[2*640];

// ---------------- helpers ----------------
__device__ __forceinline__ uint32_t smem_u32(const void* p) {
    uint32_t a;
    asm("{ .reg .u64 t; cvta.to.shared.u64 t, %1; cvt.u32.u64 %0, t; }" : "=r"(a) : "l"(p));
    return a;
}
#define LDSM_X4(r0, r1, r2, r3, addr) \
    asm volatile("ldmatrix.sync.aligned.m8n8.x4.shared.b16 {%0,%1,%2,%3}, [%4];" \
        : "=r"(r0), "=r"(r1), "=r"(r2), "=r"(r3) : "r"(addr))
#define LDSM_X4_T(r0, r1, r2, r3, addr) \
    asm volatile("ldmatrix.sync.aligned.m8n8.x4.trans.shared.b16 {%0,%1,%2,%3}, [%4];" \
        : "=r"(r0), "=r"(r1), "=r"(r2), "=r"(r3) : "r"(addr))
#define CP_ASYNC16(dst, src) \
    asm volatile("cp.async.cg.shared.global [%0], [%1], 16;" :: "r"(dst), "l"(src))
#define CP_COMMIT() asm volatile("cp.async.commit_group;" ::: "memory")
#define CP_WAIT1()  asm volatile("cp.async.wait_group 1;" ::: "memory")
#define CP_WAIT0()  asm volatile("cp.async.wait_group 0;" ::: "memory")

__device__ __forceinline__ void mma16816(float* d, const uint32_t* a,
                                         uint32_t b0, uint32_t b1) {
    asm volatile(
        "mma.sync.aligned.m16n8k16.row.col.f32.bf16.bf16.f32 "
        "{%0,%1,%2,%3}, {%4,%5,%6,%7}, {%8,%9}, {%0,%1,%2,%3};"
        : "+f"(d[0]), "+f"(d[1]), "+f"(d[2]), "+f"(d[3])
        : "r"(a[0]), "r"(a[1]), "r"(a[2]), "r"(a[3]), "r"(b0), "r"(b1));
}
__device__ __forceinline__ uint32_t pack_bf(float f) {
    __nv_bfloat16 h = __float2bfloat16(f);
    __nv_bfloat16 l = __float2bfloat16(f - __bfloat162float(h));
    return (uint32_t)__bfloat16_as_ushort(h) | ((uint32_t)__bfloat16_as_ushort(l) << 16);
}
__device__ __forceinline__ void split2(float a, float b, uint32_t& h, uint32_t& l) {
    __nv_bfloat16 ha = __float2bfloat16(a);
    __nv_bfloat16 hb = __float2bfloat16(b);
    __nv_bfloat16 la = __float2bfloat16(a - __bfloat162float(ha));
    __nv_bfloat16 lb = __float2bfloat16(b - __bfloat162float(hb));
    h = (uint32_t)__bfloat16_as_ushort(ha) | ((uint32_t)__bfloat16_as_ushort(hb) << 16);
    l = (uint32_t)__bfloat16_as_ushort(la) | ((uint32_t)__bfloat16_as_ushort(lb) << 16);
}
__device__ __forceinline__ void cvt4(float4 v, uint2& h, uint2& l) {
    uint32_t h0, l0, h1, l1;
    split2(v.x, v.y, h0, l0);
    split2(v.z, v.w, h1, l1);
    h.x = h0; h.y = h1; l.x = l0; l.y = l1;
}
// A chunk layout: 128 rows x 32 k bf16; row stride 64B, XOR swizzle on 16B segs
__device__ __forceinline__ uint32_t a32_addr(uint32_t tbase, int row, int kc) {
    return tbase + (uint32_t)((row << 6) + (((kc & 31) << 1) ^ (((row >> 1) & 3) << 4)));
}

// ---------------- weight pack + bf16 split (3 kernels for launch alignment) --------
__global__ void prepw_one(const float* __restrict__ w, const float* __restrict__ bias,
                          __nv_bfloat16* __restrict__ wph, __nv_bfloat16* __restrict__ wpl,
                          float* __restrict__ bp, int m_off, int M) {
    int idx = blockIdx.x * 256 + threadIdx.x;
    int per_g = M * 256;
    int g = idx / per_g;
    int r = idx - g * per_g;
    int m = r >> 8, k = r & 255;
    float wv = w[(size_t)(g*M + m) * 256 + k];
    __nv_bfloat16 h = __float2bfloat16(wv);
    size_t didx = (size_t)(g*640 + m_off + m) * 256 + k;
    wph[didx] = h;
    wpl[didx] = __float2bfloat16(wv - __bfloat162float(h));
    if (k == 0) bp[g*640 + m_off + m] = bias[g*M + m];
}

// ---- stage [128 x 32] bf16 A chunk into swizzled layout, async (128 threads) ----
__device__ __forceinline__ void stage_a32(uint32_t smb, const __nv_bfloat16* __restrict__ src,
                                          int tid) {
    #pragma unroll
    for (int it = 0; it < 4; it++) {
        int idx = it * 128 + tid;          // 0..511
        int row = idx >> 2;
        int k8 = (idx & 3) << 3;
        uint32_t byte = (uint32_t)((row << 6) + ((k8 << 1) ^ (((row >> 1) & 3) << 4)));
        CP_ASYNC16(smb + byte, src + (size_t)row * 256 + k8);
    }
}

// ---------------- fused qkv projection GEMM: 128 thr, 64 px, 2 CTAs/SM -------------
__global__ __launch_bounds__(128, 2)
void gemm_kernel(const float* __restrict__ x,
                 const __nv_bfloat16* __restrict__ wph, const __nv_bfloat16* __restrict__ wpl,
                 const float* __restrict__ bp,
                 uint32_t* __restrict__ qb, uint32_t* __restrict__ kb2, uint32_t* __restrict__ vb) {
    extern __shared__ char sm[];
    uint32_t sbase = smem_u32(sm);
    // A ping-pong: buf{0,1} x {hi,lo}, each 8KB -> [1024, 33792)
    const uint32_t AHb[2] = {1024, 17408};
    const uint32_t ALb[2] = {9216, 25600};
    const uint32_t BH = 33792, BL = 70656;   // each 256 rows x 144B = 36864B, ends 107520
    int tid = threadIdx.x;
    int lane = tid & 31, wid = tid >> 5;
    int pbase = blockIdx.x * 64;
    int z = blockIdx.y;                 // b*2+g
    int b = z >> 1, g = z & 1;
    const __nv_bfloat16* wbase_h = wph + (size_t)g*640*256;
    const __nv_bfloat16* wbase_l = wpl + (size_t)g*640*256;

    // prefetch A chunk 0 (m-tile 0, k 0..31)
    stage_a32(sbase + AHb[0], wbase_h, tid);
    stage_a32(sbase + ALb[0], wbase_l, tid);
    CP_COMMIT();

    // stage B: x [k=256][64 px] f32 -> hi/lo bf16, rows stride 144B
    {
        const float* xb = x + ((size_t)b*512 + g*256) * HWSZ + pbase;
        #pragma unroll 4
        for (int it = 0; it < 32; it++) {
            int idx = it * 128 + tid;       // 0..4095 float4
            int row = idx >> 4;
            int p4  = (idx & 15) << 2;
            float4 v = *(const float4*)(xb + (size_t)row * HWSZ + p4);
            uint2 h, l;
            cvt4(v, h, l);
            uint32_t off = (uint32_t)(row * 144 + p4 * 2);
            *(uint2*)(sm + BH + off) = h;
            *(uint2*)(sm + BL + off) = l;
        }
    }

    int mb = (wid & 1) * 64;            // warp M offset within 128-ch m-tile
    int nb = (wid >> 1) * 32;           // warp N offset within 64 px
    int laneA_row = ((lane >> 3) & 1) * 8 + (lane & 7);
    int laneA_k8  = (lane >> 4) * 8;
    int bt_r = (((lane >> 3) & 1) << 3) + (lane & 7);
    int bt_c = (lane >> 4) << 3;

    float d[4][4][4];

    #pragma unroll 1
    for (int q = 0; q < 40; q++) {      // (mt, chunk): mt = q>>3, 32-k chunk = q&7
        int mt = q >> 3;
        if ((q & 7) == 0) {
            #pragma unroll
            for (int mi = 0; mi < 4; mi++)
                #pragma unroll
                for (int nj = 0; nj < 4; nj++)
                    #pragma unroll
                    for (int c = 0; c < 4; c++) d[mi][nj][c] = 0.f;
        }
        __syncthreads();                // buf[(q+1)&1] reads finished at q-1
        if (q < 39) {
            int qq = q + 1;
            size_t aoff = ((size_t)(qq >> 3) * 128) * 256 + (qq & 7) * 32;
            stage_a32(sbase + AHb[qq & 1], wbase_h + aoff, tid);
            stage_a32(sbase + ALb[qq & 1], wbase_l + aoff, tid);
            CP_COMMIT();
            CP_WAIT1();                 // chunk q landed; prefetch in flight
        } else {
            CP_WAIT0();
        }
        __syncthreads();

        uint32_t AH = sbase + AHb[q & 1];
        uint32_t AL = sbase + ALb[q & 1];
        int kbase = (q & 7) * 32;       // B global k offset

        #pragma unroll
        for (int ks = 0; ks < 2; ks++) {
            int kl = ks * 16;
            int kk = kbase + kl;
            uint32_t aH[4][4], aL[4][4];
            #pragma unroll
            for (int mi = 0; mi < 4; mi++) {
                LDSM_X4(aH[mi][0], aH[mi][1], aH[mi][2], aH[mi][3],
                        a32_addr(AH, mb + mi*16 + laneA_row, kl + laneA_k8));
                LDSM_X4(aL[mi][0], aL[mi][1], aL[mi][2], aL[mi][3],
                        a32_addr(AL, mb + mi*16 + laneA_row, kl + laneA_k8));
            }
            uint32_t bHf[2][4], bLf[2][4];
            #pragma unroll
            for (int p = 0; p < 2; p++) {
                uint32_t bd = sbase + (uint32_t)((kk + bt_r)*144 + (nb + p*16 + bt_c)*2);
                LDSM_X4_T(bHf[p][0], bHf[p][1], bHf[p][2], bHf[p][3], bd + BH);
                LDSM_X4_T(bLf[p][0], bLf[p][1], bLf[p][2], bLf[p][3], bd + BL);
            }
            #pragma unroll
            for (int mi = 0; mi < 4; mi++)
                #pragma unroll
                for (int nj = 0; nj < 4; nj++) {
                    int p = nj >> 1, qx = (nj & 1) * 2;
                    mma16816(d[mi][nj], aH[mi], bHf[p][qx], bHf[p][qx+1]);
                    mma16816(d[mi][nj], aH[mi], bLf[p][qx], bLf[p][qx+1]);
                    mma16816(d[mi][nj], aL[mi], bHf[p][qx], bHf[p][qx+1]);
                }
        }

        if ((q & 7) == 7) {
            uint32_t* dst; size_t ch0;
            if (mt < 2)      { dst = qb;  ch0 = (size_t)b*512 + g*256 + mt*128; }
            else if (mt < 4) { dst = kb2; ch0 = (size_t)b*512 + g*256 + (mt-2)*128; }
            else             { dst = vb;  ch0 = (size_t)b*256 + g*128; }
            #pragma unroll
            for (int mi = 0; mi < 4; mi++) {
                int r0 = mb + mi*16 + (lane >> 2);
                float bias0 = bp[g*640 + mt*128 + r0];
                float bias1 = bp[g*640 + mt*128 + r0 + 8];
                uint32_t* row0 = dst + (ch0 + r0)     * HWSZ + pbase;
                uint32_t* row1 = dst + (ch0 + r0 + 8) * HWSZ + pbase;
                #pragma unroll
                for (int nj = 0; nj < 4; nj++) {
                    int col = nb + nj*8 + (lane & 3)*2;
                    uint2 o0 = { pack_bf(d[mi][nj][0] + bias0), pack_bf(d[mi][nj][1] + bias0) };
                    uint2 o1 = { pack_bf(d[mi][nj][2] + bias1), pack_bf(d[mi][nj][3] + bias1) };
                    *(uint2*)(row0 + col) = o0;
                    *(uint2*)(row1 + col) = o1;
                }
            }
        }
    }
}

// ---------------- 128x128 transpose per slice (4-byte elements) ----------------
__global__ void transpose_kernel(const float* __restrict__ in, float* __restrict__ out) {
    __shared__ float t[32][33];
    int tile = blockIdx.x;
    int bx = (tile & 3) * 32, by = (tile >> 2) * 32;
    const float* ip = in  + (size_t)blockIdx.y * HWSZ;
    float*       op = out + (size_t)blockIdx.y * HWSZ;
    int x = threadIdx.x, y = threadIdx.y;
    #pragma unroll
    for (int r = 0; r < 32; r += 8)
        t[y+r][x] = ip[(size_t)(by + y + r)*128 + bx + x];
    __syncthreads();
    #pragma unroll
    for (int r = 0; r < 32; r += 8)
        op[(size_t)(bx + y + r)*128 + by + x] = t[x][y+r];
}

// ---------------- axial attention: 64 queries/CTA, 2 CTAs/SM, fused BN sums --------
__global__ __launch_bounds__(256, 2)
void attn_mma_kernel(const uint32_t* __restrict__ qp, const uint32_t* __restrict__ kp,
                     const uint32_t* __restrict__ vp, float* __restrict__ out,
                     float* __restrict__ bns) {
    extern __shared__ char smc[];
    uint32_t sb = smem_u32(smc);
    const uint32_t SQh = 0, SQl = 18432, SKh = 36864, SKl = 71680;
    float* redM = (float*)(smc + 106496);
    float* redS = (float*)(smc + 107520);
    const float SC2 = 0.08838834764831845f * 1.4426950408889634f;  // scale*log2e

    int r = blockIdx.x;
    int n = blockIdx.y >> 1, half = blockIdx.y & 1;
    int b = blockIdx.z;
    size_t qoff = ((size_t)(b*4 + n) * 128) * HWSZ + (size_t)r * 128;
    size_t voff = ((size_t)(b*4 + n) *  64) * HWSZ + (size_t)r * 128;
    int ibq = half * 64;
    int tid = threadIdx.x;
    int lane = tid & 31, wid = tid >> 5;
    int g = lane >> 2, t = lane & 3;

    {
        const uint32_t* qs = qp + qoff + ibq;
        #pragma unroll
        for (int u = 0; u < 8; u++) {
            int idx = u*256 + tid;
            int row = idx >> 4, p4 = (idx & 15) << 2;
            uint32_t off = (uint32_t)(row*144 + p4*2);
            uint4 dq = *(const uint4*)(qs + (size_t)row*HWSZ + p4);
            uint2 qh = { (dq.x & 0xffffu) | (dq.y << 16), (dq.z & 0xffffu) | (dq.w << 16) };
            uint2 ql = { (dq.x >> 16) | (dq.y & 0xffff0000u), (dq.z >> 16) | (dq.w & 0xffff0000u) };
            *(uint2*)(smc + SQh + off) = qh;
            *(uint2*)(smc + SQl + off) = ql;
        }
        const uint32_t* ks2 = kp + qoff;
        #pragma unroll
        for (int u = 0; u < 16; u++) {
            int idx = u*256 + tid;
            int row = idx >> 5, p4 = (idx & 31) << 2;
            uint32_t off = (uint32_t)(row*272 + p4*2);
            uint4 dk = *(const uint4*)(ks2 + (size_t)row*HWSZ + p4);
            uint2 kh = { (dk.x & 0xffffu) | (dk.y << 16), (dk.z & 0xffffu) | (dk.w << 16) };
            uint2 kl = { (dk.x >> 16) | (dk.y & 0xffff0000u), (dk.z >> 16) | (dk.w & 0xffff0000u) };
            *(uint2*)(smc + SKh + off) = kh;
            *(uint2*)(smc + SKl + off) = kl;
        }
    }
    __syncthreads();

    int wm = wid >> 2, wn = wid & 3;
    int m0 = wm * 32, n0 = wn * 32;
    float acc[2][4][4];
    #pragma unroll
    for (int mi = 0; mi < 2; mi++)
        #pragma unroll
        for (int nj = 0; nj < 4; nj++)
            #pragma unroll
            for (int c = 0; c < 4; c++) acc[mi][nj][c] = 0.f;

    int a_r = ((lane >> 4) << 3) + (lane & 7);
    int a_c = ((lane >> 3) & 1) << 3;
    int b_r = (((lane >> 3) & 1) << 3) + (lane & 7);
    int b_c = (lane >> 4) << 3;
    uint32_t aoff0 = (uint32_t)(a_r*144 + (m0 + a_c)*2);
    uint32_t boff0 = (uint32_t)(b_r*272 + (n0 + b_c)*2);

    #pragma unroll
    for (int ks = 0; ks < 8; ks++) {
        uint32_t kq = (uint32_t)(ks * 16 * 144);
        uint32_t kk2 = (uint32_t)(ks * 16 * 272);
        uint32_t aqh[2][4], aql[2][4];
        #pragma unroll
        for (int mi = 0; mi < 2; mi++) {
            uint32_t ad = sb + kq + aoff0 + mi*32;
            LDSM_X4_T(aqh[mi][0], aqh[mi][1], aqh[mi][2], aqh[mi][3], ad + SQh);
            LDSM_X4_T(aql[mi][0], aql[mi][1], aql[mi][2], aql[mi][3], ad + SQl);
        }
        uint32_t bkh[2][4], bkl[2][4];
        #pragma unroll
        for (int p = 0; p < 2; p++) {
            uint32_t bd = sb + kk2 + boff0 + p*32;
            LDSM_X4_T(bkh[p][0], bkh[p][1], bkh[p][2], bkh[p][3], bd + SKh);
            LDSM_X4_T(bkl[p][0], bkl[p][1], bkl[p][2], bkl[p][3], bd + SKl);
        }
        #pragma unroll
        for (int mi = 0; mi < 2; mi++)
            #pragma unroll
            for (int nj = 0; nj < 4; nj++) {
                int p = nj >> 1, q2 = (nj & 1) * 2;
                mma16816(acc[mi][nj], aqh[mi], bkh[p][q2], bkh[p][q2+1]);
                mma16816(acc[mi][nj], aqh[mi], bkl[p][q2], bkl[p][q2+1]);
                mma16816(acc[mi][nj], aql[mi], bkh[p][q2], bkh[p][q2+1]);
            }
    }

    #pragma unroll
    for (int mi = 0; mi < 2; mi++) {
        int rA = m0 + mi*16 + g, rB = rA + 8;
        float mA = -1e30f, mB = -1e30f;
        #pragma unroll
        for (int nj = 0; nj < 4; nj++) {
            mA = fmaxf(mA, fmaxf(acc[mi][nj][0], acc[mi][nj][1]));
            mB = fmaxf(mB, fmaxf(acc[mi][nj][2], acc[mi][nj][3]));
        }
        mA = fmaxf(mA, __shfl_xor_sync(0xffffffffu, mA, 1));
        mA = fmaxf(mA, __shfl_xor_sync(0xffffffffu, mA, 2));
        mB = fmaxf(mB, __shfl_xor_sync(0xffffffffu, mB, 1));
        mB = fmaxf(mB, __shfl_xor_sync(0xffffffffu, mB, 2));
        if (t == 0) { redM[rA*4 + wn] = mA; redM[rB*4 + wn] = mB; }
    }
    __syncthreads();
    #pragma unroll
    for (int mi = 0; mi < 2; mi++) {
        int rA = m0 + mi*16 + g, rB = rA + 8;
        float mxA = fmaxf(fmaxf(redM[rA*4], redM[rA*4+1]), fmaxf(redM[rA*4+2], redM[rA*4+3])) * SC2;
        float mxB = fmaxf(fmaxf(redM[rB*4], redM[rB*4+1]), fmaxf(redM[rB*4+2], redM[rB*4+3])) * SC2;
        float sA = 0.f, sB = 0.f;
        #pragma unroll
        for (int nj = 0; nj < 4; nj++) {
            float e0 = exp2f(fmaf(acc[mi][nj][0], SC2, -mxA));
            float e1 = exp2f(fmaf(acc[mi][nj][1], SC2, -mxA));
            float e2 = exp2f(fmaf(acc[mi][nj][2], SC2, -mxB));
            float e3 = exp2f(fmaf(acc[mi][nj][3], SC2, -mxB));
            acc[mi][nj][0] = e0; acc[mi][nj][1] = e1;
            acc[mi][nj][2] = e2; acc[mi][nj][3] = e3;
            sA += e0 + e1; sB += e2 + e3;
        }
        sA += __shfl_xor_sync(0xffffffffu, sA, 1);
        sA += __shfl_xor_sync(0xffffffffu, sA, 2);
        sB += __shfl_xor_sync(0xffffffffu, sB, 1);
        sB += __shfl_xor_sync(0xffffffffu, sB, 2);
        if (t == 0) { redS[rA*4 + wn] = sA; redS[rB*4 + wn] = sB; }
    }
    __syncthreads();

    #pragma unroll
    for (int mi = 0; mi < 2; mi++) {
        int rA = m0 + mi*16 + g, rB = rA + 8;
        float iA = 1.0f / (redS[rA*4] + redS[rA*4+1] + redS[rA*4+2] + redS[rA*4+3]);
        float iB = 1.0f / (redS[rB*4] + redS[rB*4+1] + redS[rB*4+2] + redS[rB*4+3]);
        #pragma unroll
        for (int nj = 0; nj < 4; nj++) {
            int j0 = n0 + nj*8 + t*2;
            uint32_t h, l;
            split2(acc[mi][nj][0]*iA, acc[mi][nj][1]*iA, h, l);
            *(uint32_t*)(smc + SQh + rA*272 + j0*2) = h;
            *(uint32_t*)(smc + SQl + rA*272 + j0*2) = l;
            split2(acc[mi][nj][2]*iB, acc[mi][nj][3]*iB, h, l);
            *(uint32_t*)(smc + SQh + rB*272 + j0*2) = h;
            *(uint32_t*)(smc + SQl + rB*272 + j0*2) = l;
        }
    }
    __syncthreads();

    {
        const uint32_t* vs = vp + voff;
        #pragma unroll
        for (int u = 0; u < 8; u++) {
            int idx = u*256 + tid;
            int row = idx >> 5, p4 = (idx & 31) << 2;
            uint32_t off = (uint32_t)(row*272 + p4*2);
            uint4 dv = *(const uint4*)(vs + (size_t)row*HWSZ + p4);
            uint2 vh = { (dv.x & 0xffffu) | (dv.y << 16), (dv.z & 0xffffu) | (dv.w << 16) };
            uint2 vl = { (dv.x >> 16) | (dv.y & 0xffff0000u), (dv.z >> 16) | (dv.w & 0xffff0000u) };
            *(uint2*)(smc + SKh + off) = vh;
            *(uint2*)(smc + SKl + off) = vl;
        }
    }
    __syncthreads();

    int c0 = (wid & 3) * 16, i0 = (wid >> 2) * 32;
    float oacc[4][4];
    #pragma unroll
    for (int nj = 0; nj < 4; nj++)
        #pragma unroll
        for (int c = 0; c < 4; c++) oacc[nj][c] = 0.f;

    int ar2 = (((lane >> 3) & 1) << 3) + (lane & 7);
    int ac2 = (lane >> 4) << 3;
    int br2 = ((lane >> 4) << 3) + (lane & 7);
    int bc2 = ((lane >> 3) & 1) << 3;

    #pragma unroll
    for (int ks = 0; ks < 8; ks++) {
        int kb = ks * 16;
        uint32_t avh[4], avl[4];
        {
            uint32_t ad = sb + (uint32_t)((c0 + ar2)*272 + (kb + ac2)*2);
            LDSM_X4(avh[0], avh[1], avh[2], avh[3], ad + SKh);
            LDSM_X4(avl[0], avl[1], avl[2], avl[3], ad + SKl);
        }
        uint32_t bah[2][4], bal[2][4];
        #pragma unroll
        for (int ib2 = 0; ib2 < 2; ib2++) {
            uint32_t bd = sb + (uint32_t)((i0 + ib2*16 + br2)*272 + (kb + bc2)*2);
            LDSM_X4(bah[ib2][0], bah[ib2][1], bah[ib2][2], bah[ib2][3], bd + SQh);
            LDSM_X4(bal[ib2][0], bal[ib2][1], bal[ib2][2], bal[ib2][3], bd + SQl);
        }
        #pragma unroll
        for (int nj = 0; nj < 4; nj++) {
            int ib2 = nj >> 1, q2 = (nj & 1) * 2;
            mma16816(oacc[nj], avh, bah[ib2][q2], bah[ib2][q2+1]);
            mma16816(oacc[nj], avh, bal[ib2][q2], bal[ib2][q2+1]);
            mma16816(oacc[nj], avl, bah[ib2][q2], bah[ib2][q2+1]);
        }
    }

    {
        int cA = c0 + g, cB = cA + 8;
        float* oA = out + voff + (size_t)cA * HWSZ + ibq;
        float* oB = out + voff + (size_t)cB * HWSZ + ibq;
        #pragma unroll
        for (int nj = 0; nj < 4; nj++) {
            int i = i0 + nj*8 + t*2;
            float2 vA = { oacc[nj][0], oacc[nj][1] };
            float2 vB = { oacc[nj][2], oacc[nj][3] };
            *(float2*)(oA + i) = vA;
            *(float2*)(oB + i) = vB;
        }
    }

    if (n < 2) {
        float s0 = 0.f, q0 = 0.f, s1 = 0.f, q1 = 0.f;
        #pragma unroll
        for (int nj = 0; nj < 4; nj++) {
            s0 += oacc[nj][0] + oacc[nj][1];
            q0 += oacc[nj][0]*oacc[nj][0] + oacc[nj][1]*oacc[nj][1];
            s1 += oacc[nj][2] + oacc[nj][3];
            q1 += oacc[nj][2]*oacc[nj][2] + oacc[nj][3]*oacc[nj][3];
        }
        s0 += __shfl_xor_sync(0xffffffffu, s0, 1);
        s0 += __shfl_xor_sync(0xffffffffu, s0, 2);
        q0 += __shfl_xor_sync(0xffffffffu, q0, 1);
        q0 += __shfl_xor_sync(0xffffffffu, q0, 2);
        s1 += __shfl_xor_sync(0xffffffffu, s1, 1);
        s1 += __shfl_xor_sync(0xffffffffu, s1, 2);
        q1 += __shfl_xor_sync(0xffffffffu, q1, 1);
        q1 += __shfl_xor_sync(0xffffffffu, q1, 2);
        if (t == 0) {
            int chA = n*64 + c0 + g, chB = chA + 8;
            atomicAdd(&bns[chA], s0);       atomicAdd(&bns[256 + chA], q0);
            atomicAdd(&bns[chB], s1);       atomicAdd(&bns[256 + chB], q1);
        }
    }
}

// ---------------- BN finalize ----------------
__global__ void bn_finalize_kernel(const float* __restrict__ bnsW, const float* __restrict__ bnsH,
                                   const float* __restrict__ bnh_w, const float* __restrict__ bnh_b,
                                   const float* __restrict__ bnw_w, const float* __restrict__ bnw_b,
                                   float* __restrict__ scH, float* __restrict__ scW) {
    int tid = threadIdx.x;
    const float N = 65536.0f;
    if (tid < 128) {
        float mean = bnsW[tid] / N;
        float var  = bnsW[256 + tid] / N - mean*mean;
        float scale = bnw_w[tid] * rsqrtf(var + 1e-5f);
        scW[tid] = scale;
        scW[128 + tid] = bnw_b[tid] - mean*scale;
    } else {
        int c = tid - 128;
        float mean = bnsH[c] / N;
        float var  = bnsH[256 + c] / N - mean*mean;
        float scale = bnh_w[c] * rsqrtf(var + 1e-5f);
        scH[c] = scale;
        scH[128 + c] = bnh_b[c] - mean*scale;
    }
}

// ---------------- fused epilogue (reads oHT transposed in-kernel) ----------------
__global__ void final_fused_kernel(const float* __restrict__ x, const float* __restrict__ oht,
                                   const float* __restrict__ ow, const float* __restrict__ scH,
                                   const float* __restrict__ scW, const float* __restrict__ gamma,
                                   float* __restrict__ out) {
    __shared__ float t[32][33];
    int tile = blockIdx.x;
    int h0 = (tile >> 2) * 32, w0 = (tile & 3) * 32;
    int c = blockIdx.y, b = blockIdx.z;
    int tx = threadIdx.x, ty = threadIdx.y;
    float gm = gamma[0];

    const float* ohs = oht + (size_t)(b*256 + c) * HWSZ;
    #pragma unroll
    for (int r = 0; r < 32; r += 8)
        t[ty + r][tx] = ohs[(size_t)(w0 + ty + r)*128 + h0 + tx];
    __syncthreads();

    const float* ows = ow + (size_t)(b*256 + c) * HWSZ;
    const float* x0p = x + (size_t)(b*512 + c)       * HWSZ;
    const float* x1p = x + (size_t)(b*512 + c + 256) * HWSZ;
    float* o0p = out + (size_t)(b*512 + c)       * HWSZ;
    float* o1p = out + (size_t)(b*512 + c + 256) * HWSZ;
    bool dop = (c < 128);
    float sH = 0.f, shH = 0.f, sW = 0.f, shW = 0.f;
    if (dop) { sH = scH[c]; shH = scH[128+c]; sW = scW[c]; shW = scW[128+c]; }
    float* p0p = out + 33554432ull + (size_t)(b*128 + c) * HWSZ;
    float* p1p = out + 41943040ull + (size_t)(b*128 + c) * HWSZ;

    #pragma unroll
    for (int r = 0; r < 32; r += 8) {
        int hr = ty + r;
        size_t pix = (size_t)(h0 + hr)*128 + w0 + tx;
        float hv = t[tx][hr];
        float wv = ows[pix];
        o0p[pix] = gm*fmaxf(hv, 0.f) + x0p[pix];
        o1p[pix] = gm*fmaxf(wv, 0.f) + x1p[pix];
        if (dop) {
            p0p[pix] = hv*sH + shH;
            p1p[pix] = wv*sW + shW;
        }
    }
}

// ---------------- launch ----------------
extern "C" void kernel_launch(void* const* d_in, const int* in_sizes, int n_in,
                              void* d_out, int out_size) {
    const float* x     = (const float*)d_in[0];
    const float* wq    = (const float*)d_in[1];
    const float* bq    = (const float*)d_in[2];
    const float* wk    = (const float*)d_in[3];
    const float* bk    = (const float*)d_in[4];
    const float* wv    = (const float*)d_in[5];
    const float* bv    = (const float*)d_in[6];
    const float* bnh_w = (const float*)d_in[7];
    const float* bnh_b = (const float*)d_in[8];
    const float* bnw_w = (const float*)d_in[9];
    const float* bnw_b = (const float*)d_in[10];
    const float* gamma = (const float*)d_in[11];
    float* out = (float*)d_out;

    uint32_t *qp, *kp, *vp, *qpT, *kpT, *vpT;
    float *oW, *oHT, *scH, *scW, *bp, *bnsW, *bnsH;
    __nv_bfloat16 *wph, *wpl;
    cudaGetSymbolAddress((void**)&qp,   g_qp);
    cudaGetSymbolAddress((void**)&kp,   g_kp);
    cudaGetSymbolAddress((void**)&vp,   g_vp);
    cudaGetSymbolAddress((void**)&qpT,  g_qpT);
    cudaGetSymbolAddress((void**)&kpT,  g_kpT);
    cudaGetSymbolAddress((void**)&vpT,  g_vpT);
    cudaGetSymbolAddress((void**)&oW,   g_outW);
    cudaGetSymbolAddress((void**)&oHT,  g_outHT);
    cudaGetSymbolAddress((void**)&scH,  g_scH);
    cudaGetSymbolAddress((void**)&scW,  g_scW);
    cudaGetSymbolAddress((void**)&bnsW, g_bnsW);
    cudaGetSymbolAddress((void**)&bnsH, g_bnsH);
    cudaGetSymbolAddress((void**)&wph,  g_wph);
    cudaGetSymbolAddress((void**)&wpl,  g_wpl);
    cudaGetSymbolAddress((void**)&bp,   g_bp);

    cudaFuncSetAttribute(gemm_kernel, cudaFuncAttributeMaxDynamicSharedMemorySize, GEMM_SMEM);
    cudaFuncSetAttribute(attn_mma_kernel, cudaFuncAttributeMaxDynamicSharedMemorySize, ATT3_SMEM);

    cudaMemsetAsync(bnsW, 0, 512 * sizeof(float));
    cudaMemsetAsync(bnsH, 0, 512 * sizeof(float));

    prepw_one<<<512, 256>>>(wq, bq, wph, wpl, bp, 0,   256);
    prepw_one<<<512, 256>>>(wk, bk, wph, wpl, bp, 256, 256);
    prepw_one<<<256, 256>>>(wv, bv, wph, wpl, bp, 512, 128);
    // #6 (profiled): GEMM — 128 threads, 64 px per CTA, 2 CTAs/SM
    gemm_kernel<<<dim3(256, 8), 128, GEMM_SMEM>>>(x, wph, wpl, bp, qp, kp, vp);

    attn_mma_kernel<<<dim3(128, 8, 4), 256, ATT3_SMEM>>>(qp,  kp,  vp,  oW,  bnsW);
    transpose_kernel<<<dim3(16, 2048), dim3(32,8)>>>((const float*)qp, (float*)qpT);
    transpose_kernel<<<dim3(16, 2048), dim3(32,8)>>>((const float*)kp, (float*)kpT);
    transpose_kernel<<<dim3(16, 1024), dim3(32,8)>>>((const float*)vp, (float*)vpT);
    attn_mma_kernel<<<dim3(128, 8, 4), 256, ATT3_SMEM>>>(qpT, kpT, vpT, oHT, bnsH);

    bn_finalize_kernel<<<1, 256>>>(bnsW, bnsH, bnh_w, bnh_b, bnw_w, bnw_b, scH, scW);
    final_fused_kernel<<<dim3(16, 256, 4), dim3(32, 8)>>>(x, oHT, oW, scH, scW, gamma, out);
}

// round 12
// speedup vs baseline: 2.1528x; 1.0158x over previous
#include <cuda_runtime.h>
#include <cuda_bf16.h>
#include <math.h>
#include <stdint.h>

#define HWSZ 16384
#define GEMM_SMEM 107520
#define ATT3_SMEM 108544

// ---------------- scratch ----------------
__device__ uint32_t g_qp [4ull*512*16384];   // packed bf16: hi | lo<<16
__device__ uint32_t g_kp [4ull*512*16384];
__device__ uint32_t g_vp [4ull*256*16384];
__device__ uint32_t g_qpT[4ull*512*16384];
__device__ uint32_t g_kpT[4ull*512*16384];
__device__ uint32_t g_vpT[4ull*256*16384];
__device__ float g_outW [4ull*256*16384];
__device__ float g_outHT[4ull*256*16384];
__device__ float g_scH[256];
__device__ float g_scW[256];
__device__ float g_bnsW[512];   // [0..255]=sum, [256..511]=sumsq
__device__ float g_bnsH[512];
__device__ __nv_bfloat16 g_wph[2*640*256];   // [g][m][k]
__device__ __nv_bfloat16 g_wpl[2*640*256];
__device__ float g_bp[2*640];

// ---------------- helpers ----------------
__device__ __forceinline__ uint32_t smem_u32(const void* p) {
    uint32_t a;
    asm("{ .reg .u64 t; cvta.to.shared.u64 t, %1; cvt.u32.u64 %0, t; }" : "=r"(a) : "l"(p));
    return a;
}
#define LDSM_X4(r0, r1, r2, r3, addr) \
    asm volatile("ldmatrix.sync.aligned.m8n8.x4.shared.b16 {%0,%1,%2,%3}, [%4];" \
        : "=r"(r0), "=r"(r1), "=r"(r2), "=r"(r3) : "r"(addr))
#define LDSM_X4_T(r0, r1, r2, r3, addr) \
    asm volatile("ldmatrix.sync.aligned.m8n8.x4.trans.shared.b16 {%0,%1,%2,%3}, [%4];" \
        : "=r"(r0), "=r"(r1), "=r"(r2), "=r"(r3) : "r"(addr))
#define CP_ASYNC16(dst, src) \
    asm volatile("cp.async.cg.shared.global [%0], [%1], 16;" :: "r"(dst), "l"(src))
#define CP_COMMIT() asm volatile("cp.async.commit_group;" ::: "memory")
#define CP_WAIT1()  asm volatile("cp.async.wait_group 1;" ::: "memory")
#define CP_WAIT0()  asm volatile("cp.async.wait_group 0;" ::: "memory")

__device__ __forceinline__ void mma16816(float* d, const uint32_t* a,
                                         uint32_t b0, uint32_t b1) {
    asm volatile(
        "mma.sync.aligned.m16n8k16.row.col.f32.bf16.bf16.f32 "
        "{%0,%1,%2,%3}, {%4,%5,%6,%7}, {%8,%9}, {%0,%1,%2,%3};"
        : "+f"(d[0]), "+f"(d[1]), "+f"(d[2]), "+f"(d[3])
        : "r"(a[0]), "r"(a[1]), "r"(a[2]), "r"(a[3]), "r"(b0), "r"(b1));
}
__device__ __forceinline__ uint32_t pack_bf(float f) {
    __nv_bfloat16 h = __float2bfloat16(f);
    __nv_bfloat16 l = __float2bfloat16(f - __bfloat162float(h));
    return (uint32_t)__bfloat16_as_ushort(h) | ((uint32_t)__bfloat16_as_ushort(l) << 16);
}
__device__ __forceinline__ void split2(float a, float b, uint32_t& h, uint32_t& l) {
    __nv_bfloat16 ha = __float2bfloat16(a);
    __nv_bfloat16 hb = __float2bfloat16(b);
    __nv_bfloat16 la = __float2bfloat16(a - __bfloat162float(ha));
    __nv_bfloat16 lb = __float2bfloat16(b - __bfloat162float(hb));
    h = (uint32_t)__bfloat16_as_ushort(ha) | ((uint32_t)__bfloat16_as_ushort(hb) << 16);
    l = (uint32_t)__bfloat16_as_ushort(la) | ((uint32_t)__bfloat16_as_ushort(lb) << 16);
}
__device__ __forceinline__ void cvt4(float4 v, uint2& h, uint2& l) {
    uint32_t h0, l0, h1, l1;
    split2(v.x, v.y, h0, l0);
    split2(v.z, v.w, h1, l1);
    h.x = h0; h.y = h1; l.x = l0; l.y = l1;
}
// A chunk layout: 128 rows x 32 k bf16; row stride 64B, XOR swizzle on 16B segs
__device__ __forceinline__ uint32_t a32_addr(uint32_t tbase, int row, int kc) {
    return tbase + (uint32_t)((row << 6) + (((kc & 31) << 1) ^ (((row >> 1) & 3) << 4)));
}

// ---------------- weight pack + bf16 split (3 kernels for launch alignment) --------
__global__ void prepw_one(const float* __restrict__ w, const float* __restrict__ bias,
                          __nv_bfloat16* __restrict__ wph, __nv_bfloat16* __restrict__ wpl,
                          float* __restrict__ bp, int m_off, int M) {
    int idx = blockIdx.x * 256 + threadIdx.x;
    int per_g = M * 256;
    int g = idx / per_g;
    int r = idx - g * per_g;
    int m = r >> 8, k = r & 255;
    float wv = w[(size_t)(g*M + m) * 256 + k];
    __nv_bfloat16 h = __float2bfloat16(wv);
    size_t didx = (size_t)(g*640 + m_off + m) * 256 + k;
    wph[didx] = h;
    wpl[didx] = __float2bfloat16(wv - __bfloat162float(h));
    if (k == 0) bp[g*640 + m_off + m] = bias[g*M + m];
}

// ---- stage [128 x 32] bf16 A chunk into swizzled layout, async (256 threads) ----
__device__ __forceinline__ void stage_a32(uint32_t smb, const __nv_bfloat16* __restrict__ src,
                                          int tid) {
    #pragma unroll
    for (int it = 0; it < 2; it++) {
        int idx = it * 256 + tid;          // 0..511
        int row = idx >> 2;
        int k8 = (idx & 3) << 3;
        uint32_t byte = (uint32_t)((row << 6) + ((k8 << 1) ^ (((row >> 1) & 3) << 4)));
        CP_ASYNC16(smb + byte, src + (size_t)row * 256 + k8);
    }
}

// ---------------- fused qkv projection GEMM: 256 thr, 64 px, 2 CTAs/SM -------------
__global__ __launch_bounds__(256, 2)
void gemm_kernel(const float* __restrict__ x,
                 const __nv_bfloat16* __restrict__ wph, const __nv_bfloat16* __restrict__ wpl,
                 const float* __restrict__ bp,
                 uint32_t* __restrict__ qb, uint32_t* __restrict__ kb2, uint32_t* __restrict__ vb) {
    extern __shared__ char sm[];
    uint32_t sbase = smem_u32(sm);
    const uint32_t AHb[2] = {1024, 17408};
    const uint32_t ALb[2] = {9216, 25600};
    const uint32_t BH = 33792, BL = 70656;   // each 256 rows x 144B = 36864B, ends 107520
    int tid = threadIdx.x;
    int lane = tid & 31, wid = tid >> 5;
    int pbase = blockIdx.x * 64;
    int z = blockIdx.y;                 // b*2+g
    int b = z >> 1, g = z & 1;
    const __nv_bfloat16* wbase_h = wph + (size_t)g*640*256;
    const __nv_bfloat16* wbase_l = wpl + (size_t)g*640*256;

    // prefetch A chunk 0 (m-tile 0, k 0..31)
    stage_a32(sbase + AHb[0], wbase_h, tid);
    stage_a32(sbase + ALb[0], wbase_l, tid);
    CP_COMMIT();

    // stage B: x [k=256][64 px] f32 -> hi/lo bf16, rows stride 144B
    {
        const float* xb = x + ((size_t)b*512 + g*256) * HWSZ + pbase;
        #pragma unroll 4
        for (int it = 0; it < 16; it++) {
            int idx = it * 256 + tid;       // 0..4095 float4
            int row = idx >> 4;
            int p4  = (idx & 15) << 2;
            float4 v = *(const float4*)(xb + (size_t)row * HWSZ + p4);
            uint2 h, l;
            cvt4(v, h, l);
            uint32_t off = (uint32_t)(row * 144 + p4 * 2);
            *(uint2*)(sm + BH + off) = h;
            *(uint2*)(sm + BL + off) = l;
        }
    }

    int mb = (wid & 3) * 32;            // warp M offset (4 slots of 32 ch)
    int nb = (wid >> 2) * 32;           // warp N offset (2 slots of 32 px)
    int laneA_row = ((lane >> 3) & 1) * 8 + (lane & 7);
    int laneA_k8  = (lane >> 4) * 8;
    int bt_r = (((lane >> 3) & 1) << 3) + (lane & 7);
    int bt_c = (lane >> 4) << 3;

    float d[2][4][4];

    #pragma unroll 1
    for (int q = 0; q < 40; q++) {      // mt = q>>3, 32-k chunk = q&7
        int mt = q >> 3;
        if ((q & 7) == 0) {
            #pragma unroll
            for (int mi = 0; mi < 2; mi++)
                #pragma unroll
                for (int nj = 0; nj < 4; nj++)
                    #pragma unroll
                    for (int c = 0; c < 4; c++) d[mi][nj][c] = 0.f;
        }
        __syncthreads();                // buf[(q+1)&1] reads finished at q-1
        if (q < 39) {
            int qq = q + 1;
            size_t aoff = ((size_t)(qq >> 3) * 128) * 256 + (qq & 7) * 32;
            stage_a32(sbase + AHb[qq & 1], wbase_h + aoff, tid);
            stage_a32(sbase + ALb[qq & 1], wbase_l + aoff, tid);
            CP_COMMIT();
            CP_WAIT1();                 // chunk q landed; prefetch in flight
        } else {
            CP_WAIT0();
        }
        __syncthreads();

        uint32_t AH = sbase + AHb[q & 1];
        uint32_t AL = sbase + ALb[q & 1];
        int kbase = (q & 7) * 32;       // B global k offset

        #pragma unroll
        for (int ks = 0; ks < 2; ks++) {
            int kl = ks * 16;
            int kk = kbase + kl;
            uint32_t aH[2][4], aL[2][4];
            #pragma unroll
            for (int mi = 0; mi < 2; mi++) {
                LDSM_X4(aH[mi][0], aH[mi][1], aH[mi][2], aH[mi][3],
                        a32_addr(AH, mb + mi*16 + laneA_row, kl + laneA_k8));
                LDSM_X4(aL[mi][0], aL[mi][1], aL[mi][2], aL[mi][3],
                        a32_addr(AL, mb + mi*16 + laneA_row, kl + laneA_k8));
            }
            uint32_t bHf[2][4], bLf[2][4];
            #pragma unroll
            for (int p = 0; p < 2; p++) {
                uint32_t bd = sbase + (uint32_t)((kk + bt_r)*144 + (nb + p*16 + bt_c)*2);
                LDSM_X4_T(bHf[p][0], bHf[p][1], bHf[p][2], bHf[p][3], bd + BH);
                LDSM_X4_T(bLf[p][0], bLf[p][1], bLf[p][2], bLf[p][3], bd + BL);
            }
            #pragma unroll
            for (int mi = 0; mi < 2; mi++)
                #pragma unroll
                for (int nj = 0; nj < 4; nj++) {
                    int p = nj >> 1, qx = (nj & 1) * 2;
                    mma16816(d[mi][nj], aH[mi], bHf[p][qx], bHf[p][qx+1]);
                    mma16816(d[mi][nj], aH[mi], bLf[p][qx], bLf[p][qx+1]);
                    mma16816(d[mi][nj], aL[mi], bHf[p][qx], bHf[p][qx+1]);
                }
        }

        if ((q & 7) == 7) {
            uint32_t* dst; size_t ch0;
            if (mt < 2)      { dst = qb;  ch0 = (size_t)b*512 + g*256 + mt*128; }
            else if (mt < 4) { dst = kb2; ch0 = (size_t)b*512 + g*256 + (mt-2)*128; }
            else             { dst = vb;  ch0 = (size_t)b*256 + g*128; }
            #pragma unroll
            for (int mi = 0; mi < 2; mi++) {
                int r0 = mb + mi*16 + (lane >> 2);
                float bias0 = bp[g*640 + mt*128 + r0];
                float bias1 = bp[g*640 + mt*128 + r0 + 8];
                uint32_t* row0 = dst + (ch0 + r0)     * HWSZ + pbase;
                uint32_t* row1 = dst + (ch0 + r0 + 8) * HWSZ + pbase;
                #pragma unroll
                for (int nj = 0; nj < 4; nj++) {
                    int col = nb + nj*8 + (lane & 3)*2;
                    uint2 o0 = { pack_bf(d[mi][nj][0] + bias0), pack_bf(d[mi][nj][1] + bias0) };
                    uint2 o1 = { pack_bf(d[mi][nj][2] + bias1), pack_bf(d[mi][nj][3] + bias1) };
                    *(uint2*)(row0 + col) = o0;
                    *(uint2*)(row1 + col) = o1;
                }
            }
        }
    }
}

// ---------------- 128x128 transpose per slice (4-byte elements) ----------------
__global__ void transpose_kernel(const float* __restrict__ in, float* __restrict__ out) {
    __shared__ float t[32][33];
    int tile = blockIdx.x;
    int bx = (tile & 3) * 32, by = (tile >> 2) * 32;
    const float* ip = in  + (size_t)blockIdx.y * HWSZ;
    float*       op = out + (size_t)blockIdx.y * HWSZ;
    int x = threadIdx.x, y = threadIdx.y;
    #pragma unroll
    for (int r = 0; r < 32; r += 8)
        t[y+r][x] = ip[(size_t)(by + y + r)*128 + bx + x];
    __syncthreads();
    #pragma unroll
    for (int r = 0; r < 32; r += 8)
        op[(size_t)(bx + y + r)*128 + by + x] = t[x][y+r];
}

// ---------------- axial attention: 64 queries/CTA, 2 CTAs/SM, fused BN sums --------
__global__ __launch_bounds__(256, 2)
void attn_mma_kernel(const uint32_t* __restrict__ qp, const uint32_t* __restrict__ kp,
                     const uint32_t* __restrict__ vp, float* __restrict__ out,
                     float* __restrict__ bns) {
    extern __shared__ char smc[];
    uint32_t sb = smem_u32(smc);
    const uint32_t SQh = 0, SQl = 18432, SKh = 36864, SKl = 71680;
    float* redM = (float*)(smc + 106496);
    float* redS = (float*)(smc + 107520);
    const float SC2 = 0.08838834764831845f * 1.4426950408889634f;  // scale*log2e

    int r = blockIdx.x;
    int n = blockIdx.y >> 1, half = blockIdx.y & 1;
    int b = blockIdx.z;
    size_t qoff = ((size_t)(b*4 + n) * 128) * HWSZ + (size_t)r * 128;
    size_t voff = ((size_t)(b*4 + n) *  64) * HWSZ + (size_t)r * 128;
    int ibq = half * 64;
    int tid = threadIdx.x;
    int lane = tid & 31, wid = tid >> 5;
    int g = lane >> 2, t = lane & 3;

    {
        const uint32_t* qs = qp + qoff + ibq;
        #pragma unroll
        for (int u = 0; u < 8; u++) {
            int idx = u*256 + tid;
            int row = idx >> 4, p4 = (idx & 15) << 2;
            uint32_t off = (uint32_t)(row*144 + p4*2);
            uint4 dq = *(const uint4*)(qs + (size_t)row*HWSZ + p4);
            uint2 qh = { (dq.x & 0xffffu) | (dq.y << 16), (dq.z & 0xffffu) | (dq.w << 16) };
            uint2 ql = { (dq.x >> 16) | (dq.y & 0xffff0000u), (dq.z >> 16) | (dq.w & 0xffff0000u) };
            *(uint2*)(smc + SQh + off) = qh;
            *(uint2*)(smc + SQl + off) = ql;
        }
        const uint32_t* ks2 = kp + qoff;
        #pragma unroll
        for (int u = 0; u < 16; u++) {
            int idx = u*256 + tid;
            int row = idx >> 5, p4 = (idx & 31) << 2;
            uint32_t off = (uint32_t)(row*272 + p4*2);
            uint4 dk = *(const uint4*)(ks2 + (size_t)row*HWSZ + p4);
            uint2 kh = { (dk.x & 0xffffu) | (dk.y << 16), (dk.z & 0xffffu) | (dk.w << 16) };
            uint2 kl = { (dk.x >> 16) | (dk.y & 0xffff0000u), (dk.z >> 16) | (dk.w & 0xffff0000u) };
            *(uint2*)(smc + SKh + off) = kh;
            *(uint2*)(smc + SKl + off) = kl;
        }
    }
    __syncthreads();

    int wm = wid >> 2, wn = wid & 3;
    int m0 = wm * 32, n0 = wn * 32;
    float acc[2][4][4];
    #pragma unroll
    for (int mi = 0; mi < 2; mi++)
        #pragma unroll
        for (int nj = 0; nj < 4; nj++)
            #pragma unroll
            for (int c = 0; c < 4; c++) acc[mi][nj][c] = 0.f;

    int a_r = ((lane >> 4) << 3) + (lane & 7);
    int a_c = ((lane >> 3) & 1) << 3;
    int b_r = (((lane >> 3) & 1) << 3) + (lane & 7);
    int b_c = (lane >> 4) << 3;
    uint32_t aoff0 = (uint32_t)(a_r*144 + (m0 + a_c)*2);
    uint32_t boff0 = (uint32_t)(b_r*272 + (n0 + b_c)*2);

    #pragma unroll
    for (int ks = 0; ks < 8; ks++) {
        uint32_t kq = (uint32_t)(ks * 16 * 144);
        uint32_t kk2 = (uint32_t)(ks * 16 * 272);
        uint32_t aqh[2][4], aql[2][4];
        #pragma unroll
        for (int mi = 0; mi < 2; mi++) {
            uint32_t ad = sb + kq + aoff0 + mi*32;
            LDSM_X4_T(aqh[mi][0], aqh[mi][1], aqh[mi][2], aqh[mi][3], ad + SQh);
            LDSM_X4_T(aql[mi][0], aql[mi][1], aql[mi][2], aql[mi][3], ad + SQl);
        }
        uint32_t bkh[2][4], bkl[2][4];
        #pragma unroll
        for (int p = 0; p < 2; p++) {
            uint32_t bd = sb + kk2 + boff0 + p*32;
            LDSM_X4_T(bkh[p][0], bkh[p][1], bkh[p][2], bkh[p][3], bd + SKh);
            LDSM_X4_T(bkl[p][0], bkl[p][1], bkl[p][2], bkl[p][3], bd + SKl);
        }
        #pragma unroll
        for (int mi = 0; mi < 2; mi++)
            #pragma unroll
            for (int nj = 0; nj < 4; nj++) {
                int p = nj >> 1, q2 = (nj & 1) * 2;
                mma16816(acc[mi][nj], aqh[mi], bkh[p][q2], bkh[p][q2+1]);
                mma16816(acc[mi][nj], aqh[mi], bkl[p][q2], bkl[p][q2+1]);
                mma16816(acc[mi][nj], aql[mi], bkh[p][q2], bkh[p][q2+1]);
            }
    }

    #pragma unroll
    for (int mi = 0; mi < 2; mi++) {
        int rA = m0 + mi*16 + g, rB = rA + 8;
        float mA = -1e30f, mB = -1e30f;
        #pragma unroll
        for (int nj = 0; nj < 4; nj++) {
            mA = fmaxf(mA, fmaxf(acc[mi][nj][0], acc[mi][nj][1]));
            mB = fmaxf(mB, fmaxf(acc[mi][nj][2], acc[mi][nj][3]));
        }
        mA = fmaxf(mA, __shfl_xor_sync(0xffffffffu, mA, 1));
        mA = fmaxf(mA, __shfl_xor_sync(0xffffffffu, mA, 2));
        mB = fmaxf(mB, __shfl_xor_sync(0xffffffffu, mB, 1));
        mB = fmaxf(mB, __shfl_xor_sync(0xffffffffu, mB, 2));
        if (t == 0) { redM[rA*4 + wn] = mA; redM[rB*4 + wn] = mB; }
    }
    __syncthreads();
    #pragma unroll
    for (int mi = 0; mi < 2; mi++) {
        int rA = m0 + mi*16 + g, rB = rA + 8;
        float mxA = fmaxf(fmaxf(redM[rA*4], redM[rA*4+1]), fmaxf(redM[rA*4+2], redM[rA*4+3])) * SC2;
        float mxB = fmaxf(fmaxf(redM[rB*4], redM[rB*4+1]), fmaxf(redM[rB*4+2], redM[rB*4+3])) * SC2;
        float sA = 0.f, sB = 0.f;
        #pragma unroll
        for (int nj = 0; nj < 4; nj++) {
            float e0 = exp2f(fmaf(acc[mi][nj][0], SC2, -mxA));
            float e1 = exp2f(fmaf(acc[mi][nj][1], SC2, -mxA));
            float e2 = exp2f(fmaf(acc[mi][nj][2], SC2, -mxB));
            float e3 = exp2f(fmaf(acc[mi][nj][3], SC2, -mxB));
            acc[mi][nj][0] = e0; acc[mi][nj][1] = e1;
            acc[mi][nj][2] = e2; acc[mi][nj][3] = e3;
            sA += e0 + e1; sB += e2 + e3;
        }
        sA += __shfl_xor_sync(0xffffffffu, sA, 1);
        sA += __shfl_xor_sync(0xffffffffu, sA, 2);
        sB += __shfl_xor_sync(0xffffffffu, sB, 1);
        sB += __shfl_xor_sync(0xffffffffu, sB, 2);
        if (t == 0) { redS[rA*4 + wn] = sA; redS[rB*4 + wn] = sB; }
    }
    __syncthreads();

    #pragma unroll
    for (int mi = 0; mi < 2; mi++) {
        int rA = m0 + mi*16 + g, rB = rA + 8;
        float iA = 1.0f / (redS[rA*4] + redS[rA*4+1] + redS[rA*4+2] + redS[rA*4+3]);
        float iB = 1.0f / (redS[rB*4] + redS[rB*4+1] + redS[rB*4+2] + redS[rB*4+3]);
        #pragma unroll
        for (int nj = 0; nj < 4; nj++) {
            int j0 = n0 + nj*8 + t*2;
            uint32_t h, l;
            split2(acc[mi][nj][0]*iA, acc[mi][nj][1]*iA, h, l);
            *(uint32_t*)(smc + SQh + rA*272 + j0*2) = h;
            *(uint32_t*)(smc + SQl + rA*272 + j0*2) = l;
            split2(acc[mi][nj][2]*iB, acc[mi][nj][3]*iB, h, l);
            *(uint32_t*)(smc + SQh + rB*272 + j0*2) = h;
            *(uint32_t*)(smc + SQl + rB*272 + j0*2) = l;
        }
    }
    __syncthreads();

    {
        const uint32_t* vs = vp + voff;
        #pragma unroll
        for (int u = 0; u < 8; u++) {
            int idx = u*256 + tid;
            int row = idx >> 5, p4 = (idx & 31) << 2;
            uint32_t off = (uint32_t)(row*272 + p4*2);
            uint4 dv = *(const uint4*)(vs + (size_t)row*HWSZ + p4);
            uint2 vh = { (dv.x & 0xffffu) | (dv.y << 16), (dv.z & 0xffffu) | (dv.w << 16) };
            uint2 vl = { (dv.x >> 16) | (dv.y & 0xffff0000u), (dv.z >> 16) | (dv.w & 0xffff0000u) };
            *(uint2*)(smc + SKh + off) = vh;
            *(uint2*)(smc + SKl + off) = vl;
        }
    }
    __syncthreads();

    int c0 = (wid & 3) * 16, i0 = (wid >> 2) * 32;
    float oacc[4][4];
    #pragma unroll
    for (int nj = 0; nj < 4; nj++)
        #pragma unroll
        for (int c = 0; c < 4; c++) oacc[nj][c] = 0.f;

    int ar2 = (((lane >> 3) & 1) << 3) + (lane & 7);
    int ac2 = (lane >> 4) << 3;
    int br2 = ((lane >> 4) << 3) + (lane & 7);
    int bc2 = ((lane >> 3) & 1) << 3;

    #pragma unroll
    for (int ks = 0; ks < 8; ks++) {
        int kb = ks * 16;
        uint32_t avh[4], avl[4];
        {
            uint32_t ad = sb + (uint32_t)((c0 + ar2)*272 + (kb + ac2)*2);
            LDSM_X4(avh[0], avh[1], avh[2], avh[3], ad + SKh);
            LDSM_X4(avl[0], avl[1], avl[2], avl[3], ad + SKl);
        }
        uint32_t bah[2][4], bal[2][4];
        #pragma unroll
        for (int ib2 = 0; ib2 < 2; ib2++) {
            uint32_t bd = sb + (uint32_t)((i0 + ib2*16 + br2)*272 + (kb + bc2)*2);
            LDSM_X4(bah[ib2][0], bah[ib2][1], bah[ib2][2], bah[ib2][3], bd + SQh);
            LDSM_X4(bal[ib2][0], bal[ib2][1], bal[ib2][2], bal[ib2][3], bd + SQl);
        }
        #pragma unroll
        for (int nj = 0; nj < 4; nj++) {
            int ib2 = nj >> 1, q2 = (nj & 1) * 2;
            mma16816(oacc[nj], avh, bah[ib2][q2], bah[ib2][q2+1]);
            mma16816(oacc[nj], avh, bal[ib2][q2], bal[ib2][q2+1]);
            mma16816(oacc[nj], avl, bah[ib2][q2], bah[ib2][q2+1]);
        }
    }

    {
        int cA = c0 + g, cB = cA + 8;
        float* oA = out + voff + (size_t)cA * HWSZ + ibq;
        float* oB = out + voff + (size_t)cB * HWSZ + ibq;
        #pragma unroll
        for (int nj = 0; nj < 4; nj++) {
            int i = i0 + nj*8 + t*2;
            float2 vA = { oacc[nj][0], oacc[nj][1] };
            float2 vB = { oacc[nj][2], oacc[nj][3] };
            *(float2*)(oA + i) = vA;
            *(float2*)(oB + i) = vB;
        }
    }

    if (n < 2) {
        float s0 = 0.f, q0 = 0.f, s1 = 0.f, q1 = 0.f;
        #pragma unroll
        for (int nj = 0; nj < 4; nj++) {
            s0 += oacc[nj][0] + oacc[nj][1];
            q0 += oacc[nj][0]*oacc[nj][0] + oacc[nj][1]*oacc[nj][1];
            s1 += oacc[nj][2] + oacc[nj][3];
            q1 += oacc[nj][2]*oacc[nj][2] + oacc[nj][3]*oacc[nj][3];
        }
        s0 += __shfl_xor_sync(0xffffffffu, s0, 1);
        s0 += __shfl_xor_sync(0xffffffffu, s0, 2);
        q0 += __shfl_xor_sync(0xffffffffu, q0, 1);
        q0 += __shfl_xor_sync(0xffffffffu, q0, 2);
        s1 += __shfl_xor_sync(0xffffffffu, s1, 1);
        s1 += __shfl_xor_sync(0xffffffffu, s1, 2);
        q1 += __shfl_xor_sync(0xffffffffu, q1, 1);
        q1 += __shfl_xor_sync(0xffffffffu, q1, 2);
        if (t == 0) {
            int chA = n*64 + c0 + g, chB = chA + 8;
            atomicAdd(&bns[chA], s0);       atomicAdd(&bns[256 + chA], q0);
            atomicAdd(&bns[chB], s1);       atomicAdd(&bns[256 + chB], q1);
        }
    }
}

// ---------------- BN finalize ----------------
__global__ void bn_finalize_kernel(const float* __restrict__ bnsW, const float* __restrict__ bnsH,
                                   const float* __restrict__ bnh_w, const float* __restrict__ bnh_b,
                                   const float* __restrict__ bnw_w, const float* __restrict__ bnw_b,
                                   float* __restrict__ scH, float* __restrict__ scW) {
    int tid = threadIdx.x;
    const float N = 65536.0f;
    if (tid < 128) {
        float mean = bnsW[tid] / N;
        float var  = bnsW[256 + tid] / N - mean*mean;
        float scale = bnw_w[tid] * rsqrtf(var + 1e-5f);
        scW[tid] = scale;
        scW[128 + tid] = bnw_b[tid] - mean*scale;
    } else {
        int c = tid - 128;
        float mean = bnsH[c] / N;
        float var  = bnsH[256 + c] / N - mean*mean;
        float scale = bnh_w[c] * rsqrtf(var + 1e-5f);
        scH[c] = scale;
        scH[128 + c] = bnh_b[c] - mean*scale;
    }
}

// ---------------- fused epilogue (reads oHT transposed in-kernel) ----------------
__global__ void final_fused_kernel(const float* __restrict__ x, const float* __restrict__ oht,
                                   const float* __restrict__ ow, const float* __restrict__ scH,
                                   const float* __restrict__ scW, const float* __restrict__ gamma,
                                   float* __restrict__ out) {
    __shared__ float t[32][33];
    int tile = blockIdx.x;
    int h0 = (tile >> 2) * 32, w0 = (tile & 3) * 32;
    int c = blockIdx.y, b = blockIdx.z;
    int tx = threadIdx.x, ty = threadIdx.y;
    float gm = gamma[0];

    const float* ohs = oht + (size_t)(b*256 + c) * HWSZ;
    #pragma unroll
    for (int r = 0; r < 32; r += 8)
        t[ty + r][tx] = ohs[(size_t)(w0 + ty + r)*128 + h0 + tx];
    __syncthreads();

    const float* ows = ow + (size_t)(b*256 + c) * HWSZ;
    const float* x0p = x + (size_t)(b*512 + c)       * HWSZ;
    const float* x1p = x + (size_t)(b*512 + c + 256) * HWSZ;
    float* o0p = out + (size_t)(b*512 + c)       * HWSZ;
    float* o1p = out + (size_t)(b*512 + c + 256) * HWSZ;
    bool dop = (c < 128);
    float sH = 0.f, shH = 0.f, sW = 0.f, shW = 0.f;
    if (dop) { sH = scH[c]; shH = scH[128+c]; sW = scW[c]; shW = scW[128+c]; }
    float* p0p = out + 33554432ull + (size_t)(b*128 + c) * HWSZ;
    float* p1p = out + 41943040ull + (size_t)(b*128 + c) * HWSZ;

    #pragma unroll
    for (int r = 0; r < 32; r += 8) {
        int hr = ty + r;
        size_t pix = (size_t)(h0 + hr)*128 + w0 + tx;
        float hv = t[tx][hr];
        float wv = ows[pix];
        o0p[pix] = gm*fmaxf(hv, 0.f) + x0p[pix];
        o1p[pix] = gm*fmaxf(wv, 0.f) + x1p[pix];
        if (dop) {
            p0p[pix] = hv*sH + shH;
            p1p[pix] = wv*sW + shW;
        }
    }
}

// ---------------- launch ----------------
extern "C" void kernel_launch(void* const* d_in, const int* in_sizes, int n_in,
                              void* d_out, int out_size) {
    const float* x     = (const float*)d_in[0];
    const float* wq    = (const float*)d_in[1];
    const float* bq    = (const float*)d_in[2];
    const float* wk    = (const float*)d_in[3];
    const float* bk    = (const float*)d_in[4];
    const float* wv    = (const float*)d_in[5];
    const float* bv    = (const float*)d_in[6];
    const float* bnh_w = (const float*)d_in[7];
    const float* bnh_b = (const float*)d_in[8];
    const float* bnw_w = (const float*)d_in[9];
    const float* bnw_b = (const float*)d_in[10];
    const float* gamma = (const float*)d_in[11];
    float* out = (float*)d_out;

    uint32_t *qp, *kp, *vp, *qpT, *kpT, *vpT;
    float *oW, *oHT, *scH, *scW, *bp, *bnsW, *bnsH;
    __nv_bfloat16 *wph, *wpl;
    cudaGetSymbolAddress((void**)&qp,   g_qp);
    cudaGetSymbolAddress((void**)&kp,   g_kp);
    cudaGetSymbolAddress((void**)&vp,   g_vp);
    cudaGetSymbolAddress((void**)&qpT,  g_qpT);
    cudaGetSymbolAddress((void**)&kpT,  g_kpT);
    cudaGetSymbolAddress((void**)&vpT,  g_vpT);
    cudaGetSymbolAddress((void**)&oW,   g_outW);
    cudaGetSymbolAddress((void**)&oHT,  g_outHT);
    cudaGetSymbolAddress((void**)&scH,  g_scH);
    cudaGetSymbolAddress((void**)&scW,  g_scW);
    cudaGetSymbolAddress((void**)&bnsW, g_bnsW);
    cudaGetSymbolAddress((void**)&bnsH, g_bnsH);
    cudaGetSymbolAddress((void**)&wph,  g_wph);
    cudaGetSymbolAddress((void**)&wpl,  g_wpl);
    cudaGetSymbolAddress((void**)&bp,   g_bp);

    cudaFuncSetAttribute(gemm_kernel, cudaFuncAttributeMaxDynamicSharedMemorySize, GEMM_SMEM);
    cudaFuncSetAttribute(attn_mma_kernel, cudaFuncAttributeMaxDynamicSharedMemorySize, ATT3_SMEM);

    cudaMemsetAsync(bnsW, 0, 512 * sizeof(float));
    cudaMemsetAsync(bnsH, 0, 512 * sizeof(float));

    prepw_one<<<512, 256>>>(wq, bq, wph, wpl, bp, 0,   256);
    prepw_one<<<512, 256>>>(wk, bk, wph, wpl, bp, 256, 256);
    prepw_one<<<256, 256>>>(wv, bv, wph, wpl, bp, 512, 128);
    // #6 (profiled): GEMM — 256 threads, 64 px per CTA, 2 CTAs/SM (16 warps/SM)
    gemm_kernel<<<dim3(256, 8), 256, GEMM_SMEM>>>(x, wph, wpl, bp, qp, kp, vp);

    attn_mma_kernel<<<dim3(128, 8, 4), 256, ATT3_SMEM>>>(qp,  kp,  vp,  oW,  bnsW);
    transpose_kernel<<<dim3(16, 2048), dim3(32,8)>>>((const float*)qp, (float*)qpT);
    transpose_kernel<<<dim3(16, 2048), dim3(32,8)>>>((const float*)kp, (float*)kpT);
    transpose_kernel<<<dim3(16, 1024), dim3(32,8)>>>((const float*)vp, (float*)vpT);
    attn_mma_kernel<<<dim3(128, 8, 4), 256, ATT3_SMEM>>>(qpT, kpT, vpT, oHT, bnsH);

    bn_finalize_kernel<<<1, 256>>>(bnsW, bnsH, bnh_w, bnh_b, bnw_w, bnw_b, scH, scW);
    final_fused_kernel<<<dim3(16, 256, 4), dim3(32, 8)>>>(x, oHT, oW, scH, scW, gamma, out);
}